// round 2
// baseline (speedup 1.0000x reference)
#include <cuda_runtime.h>
#include <math.h>

#define BB 4
#define CC 64
#define NN 6400   // 80*80

typedef unsigned long long ull;

// Scratch (module-static device memory; no runtime allocation).
// g_Q : [b][n][c]  query rows, row n = h*80+w holds q[:, w, h] (transposed pixel)
// g_K : [b][c][m]  keys, channel-major, natural pixel order
// g_V : [b][m][c]  values, row m holds v[:, m%80, m/80] (transposed pixel)
// g_Kc: [b][m][c]  k natural pixel-major (for channel attention)
__device__ float g_Q [BB * NN * CC];
__device__ float g_K [BB * CC * NN];
__device__ float g_V [BB * NN * CC];
__device__ float g_Kc[BB * NN * CC];
__device__ float g_Lp[BB * 32 * CC * CC];   // channel-logit partials
__device__ float g_ma[BB * CC * CC];        // softmaxed channel attention

// ---------------- packed f32x2 helpers (sm_103a) ----------------
__device__ __forceinline__ void fma2(ull& acc, ull a, ull b) {
    asm("fma.rn.f32x2 %0, %1, %2, %0;" : "+l"(acc) : "l"(a), "l"(b));
}
__device__ __forceinline__ ull mul2(ull a, ull b) {
    ull r; asm("mul.rn.f32x2 %0, %1, %2;" : "=l"(r) : "l"(a), "l"(b)); return r;
}
__device__ __forceinline__ ull dup2f(float x) {
    ull r; asm("mov.b64 %0, {%1, %1};" : "=l"(r) : "f"(x)); return r;
}
__device__ __forceinline__ float2 unpk(ull v) {
    float2 f; asm("mov.b64 {%0, %1}, %2;" : "=f"(f.x), "=f"(f.y) : "l"(v)); return f;
}

// ---------------------------------------------------------------------------
// Kernel 1: 1x1 conv qkv. grid (100 pixel-tiles, 2 halves of 96 outputs, 4 b)
// ---------------------------------------------------------------------------
__global__ __launch_bounds__(256) void qkv_kernel(
    const float* __restrict__ x, const float* __restrict__ w,
    const float* __restrict__ bias)
{
    __shared__ float ws[64][100];  // [c][o_local]
    __shared__ float xs[64][64];   // [c][p]

    const int b     = blockIdx.z;
    const int half  = blockIdx.y;
    const int n0    = blockIdx.x * 64;
    const int tid   = threadIdx.x;
    const int obase = half * 96;

    for (int idx = tid; idx < 96 * 64; idx += 256) {
        int o = idx >> 6;
        int c = idx & 63;
        ws[c][o] = w[(size_t)(obase + o) * 64 + c];
    }
    for (int idx = tid; idx < 64 * 64; idx += 256) {
        int c = idx >> 6;
        int p = idx & 63;
        xs[c][p] = x[((size_t)b * 64 + c) * NN + n0 + p];
    }
    __syncthreads();

    const int p  = tid & 63;
    const int o0 = (tid >> 6) * 24;

    float acc[24];
#pragma unroll
    for (int j = 0; j < 24; j++) acc[j] = 0.f;

#pragma unroll 4
    for (int c = 0; c < 64; c++) {
        float xv = xs[c][p];
#pragma unroll
        for (int j4 = 0; j4 < 24; j4 += 4) {
            float4 wv = *(const float4*)&ws[c][o0 + j4];
            acc[j4 + 0] += xv * wv.x;
            acc[j4 + 1] += xv * wv.y;
            acc[j4 + 2] += xv * wv.z;
            acc[j4 + 3] += xv * wv.w;
        }
    }

    const int n  = n0 + p;
    const int h  = n / 80;
    const int wq = n % 80;
    const int nt = wq * 80 + h;

#pragma unroll
    for (int j4 = 0; j4 < 24; j4 += 4) {
        const int o = obase + o0 + j4;
        float4 v4;
        v4.x = acc[j4 + 0] + bias[o + 0];
        v4.y = acc[j4 + 1] + bias[o + 1];
        v4.z = acc[j4 + 2] + bias[o + 2];
        v4.w = acc[j4 + 3] + bias[o + 3];
        if (o < 64) {
            g_K[((size_t)b * 64 + o + 0) * NN + n] = v4.x;
            g_K[((size_t)b * 64 + o + 1) * NN + n] = v4.y;
            g_K[((size_t)b * 64 + o + 2) * NN + n] = v4.z;
            g_K[((size_t)b * 64 + o + 3) * NN + n] = v4.w;
            *(float4*)&g_Q[((size_t)b * NN + nt) * 64 + o] = v4;
        } else if (o < 128) {
            *(float4*)&g_Kc[((size_t)b * NN + n) * 64 + (o - 64)] = v4;
        } else {
            *(float4*)&g_V[((size_t)b * NN + nt) * 64 + (o - 128)] = v4;
        }
    }
}

// ---------------------------------------------------------------------------
// Kernel 2a: channel-attn logit partials. grid (32 chunks, 4 b), 256 thr
// ---------------------------------------------------------------------------
__global__ __launch_bounds__(256) void chan_logits_kernel()
{
    const int b = blockIdx.y, chunk = blockIdx.x;
    const int tid = threadIdx.x;
    const int tx = tid & 15, ty = tid >> 4;
    const float* __restrict__ Kc = g_Kc + (size_t)b * NN * CC;
    const float* __restrict__ Qm = g_Q  + (size_t)b * NN * CC;

    float acc[4][4];
#pragma unroll
    for (int i = 0; i < 4; i++)
#pragma unroll
        for (int j = 0; j < 4; j++) acc[i][j] = 0.f;

    const int m0 = chunk * 200;
#pragma unroll 2
    for (int m = m0; m < m0 + 200; m++) {
        float4 kv4 = *(const float4*)(Kc + (size_t)m * 64 + ty * 4);
        float4 qv4 = *(const float4*)(Qm + (size_t)m * 64 + tx * 4);
        float kv[4] = {kv4.x, kv4.y, kv4.z, kv4.w};
        float qv[4] = {qv4.x, qv4.y, qv4.z, qv4.w};
#pragma unroll
        for (int i = 0; i < 4; i++)
#pragma unroll
            for (int j = 0; j < 4; j++)
                acc[i][j] += kv[i] * qv[j];
    }

    float* Lp = g_Lp + ((size_t)b * 32 + chunk) * 64 * 64;
#pragma unroll
    for (int i = 0; i < 4; i++) {
        float4 o4 = make_float4(acc[i][0], acc[i][1], acc[i][2], acc[i][3]);
        *(float4*)(Lp + (size_t)(ty * 4 + i) * 64 + tx * 4) = o4;
    }
}

// ---------------------------------------------------------------------------
// Kernel 2b: reduce partials + row softmax. grid 4, 64 threads
// ---------------------------------------------------------------------------
__global__ void chan_softmax_kernel()
{
    const int b = blockIdx.x;
    const int c = threadIdx.x;
    float s[64];
#pragma unroll
    for (int j = 0; j < 64; j++) s[j] = 0.f;

    for (int ch = 0; ch < 32; ch++) {
        const float* p = g_Lp + (((size_t)b * 32 + ch) * 64 + c) * 64;
#pragma unroll
        for (int j4 = 0; j4 < 64; j4 += 4) {
            float4 v = *(const float4*)(p + j4);
            s[j4 + 0] += v.x; s[j4 + 1] += v.y;
            s[j4 + 2] += v.z; s[j4 + 3] += v.w;
        }
    }
    float mx = -INFINITY;
#pragma unroll
    for (int j = 0; j < 64; j++) mx = fmaxf(mx, s[j]);
    float sum = 0.f;
#pragma unroll
    for (int j = 0; j < 64; j++) { s[j] = expf(s[j] - mx); sum += s[j]; }
    const float inv = 1.f / sum;
    float* o = g_ma + ((size_t)b * 64 + c) * 64;
#pragma unroll
    for (int j4 = 0; j4 < 64; j4 += 4) {
        float4 v = make_float4(s[j4] * inv, s[j4 + 1] * inv,
                               s[j4 + 2] * inv, s[j4 + 3] * inv);
        *(float4*)(o + j4) = v;
    }
}

// ---------------------------------------------------------------------------
// Kernel 3: channel apply (writes output base). grid (100, 4), 256 thr
// ---------------------------------------------------------------------------
__global__ __launch_bounds__(256) void chan_apply_kernel(float* __restrict__ out)
{
    __shared__ float vs[64][64];
    __shared__ float mas[64][65];

    const int b  = blockIdx.y;
    const int n0 = blockIdx.x * 64;
    const int tid = threadIdx.x;
    const int tx = tid & 15, ty = tid >> 4;

    for (int idx = tid; idx < 4096; idx += 256) {
        int c  = idx >> 6;
        int cp = idx & 63;
        mas[cp][c] = g_ma[((size_t)b * 64 + c) * 64 + cp];
    }
    {
        int p  = tid >> 2;
        int cb = (tid & 3) * 16;
        int n  = n0 + p;
        int nt = (n % 80) * 80 + n / 80;
        const float* vp = g_V + ((size_t)b * NN + nt) * 64 + cb;
#pragma unroll
        for (int k = 0; k < 4; k++) {
            float4 v4 = *(const float4*)(vp + 4 * k);
            vs[cb + 4 * k + 0][p] = v4.x;
            vs[cb + 4 * k + 1][p] = v4.y;
            vs[cb + 4 * k + 2][p] = v4.z;
            vs[cb + 4 * k + 3][p] = v4.w;
        }
    }
    __syncthreads();

    float acc[4][4];
#pragma unroll
    for (int i = 0; i < 4; i++)
#pragma unroll
        for (int j = 0; j < 4; j++) acc[i][j] = 0.f;

#pragma unroll 4
    for (int cp = 0; cp < 64; cp++) {
        float mv[4];
#pragma unroll
        for (int i = 0; i < 4; i++) mv[i] = mas[cp][ty * 4 + i];
        float4 v4 = *(const float4*)&vs[cp][tx * 4];
        float vv[4] = {v4.x, v4.y, v4.z, v4.w};
#pragma unroll
        for (int i = 0; i < 4; i++)
#pragma unroll
            for (int j = 0; j < 4; j++)
                acc[i][j] += mv[i] * vv[j];
    }
#pragma unroll
    for (int i = 0; i < 4; i++) {
        float4 o4 = make_float4(acc[i][0], acc[i][1], acc[i][2], acc[i][3]);
        *(float4*)(out + ((size_t)b * 64 + ty * 4 + i) * NN + n0 + tx * 4) = o4;
    }
}

// ---------------------------------------------------------------------------
// Kernel 4: spatial flash attention v2 (f32x2 packed FMA), adds into out.
// grid (100, 4), 256 threads, M-tile 64, key tile 128, 4x8 micro-tiles.
// smem: Qs [c][2*row] dup (64x136), KP union {K [c][m] 64x132, P [row][key]
// 64x132}, Vs [k][ch] 128x68.  103424 B dynamic, 2 CTAs/SM.
// ---------------------------------------------------------------------------
#define FL_SMEM_FLOATS (64*136 + 64*132 + 128*68)

__global__ __launch_bounds__(256, 2) void flash2_kernel(float* __restrict__ out)
{
    extern __shared__ float sm[];
    float* Qs = sm;                       // 64 x 136 (row-duplicated)
    float* KP = sm + 64 * 136;            // 64 x 132
    float* Vs = sm + 64 * 136 + 64 * 132; // 128 x 68

    const int b  = blockIdx.y;
    const int n0 = blockIdx.x * 64;
    const int tid = threadIdx.x;
    const int tx = tid & 15;   // keys: tx*8 .. tx*8+7
    const int ty = tid >> 4;   // rows: ty*4 .. ty*4+3

    const float* __restrict__ Qg = g_Q + (size_t)b * NN * CC;
    const float* __restrict__ Kg = g_K + (size_t)b * CC * NN;
    const float* __restrict__ Vg = g_V + (size_t)b * NN * CC;

    // Q tile, duplicated along row axis: Qs[c][2r] = Qs[c][2r+1] = Q[n0+r][c]
    {
        const int rr   = tid >> 2;
        const int cseg = (tid & 3) * 16;
        const float* qp = Qg + ((size_t)(n0 + rr)) * 64 + cseg;
#pragma unroll
        for (int t = 0; t < 4; t++) {
            float4 q4 = *(const float4*)(qp + 4 * t);
            float* d = Qs + (cseg + 4 * t) * 136 + 2 * rr;
            *(float2*)(d)           = make_float2(q4.x, q4.x);
            *(float2*)(d + 136)     = make_float2(q4.y, q4.y);
            *(float2*)(d + 272)     = make_float2(q4.z, q4.z);
            *(float2*)(d + 408)     = make_float2(q4.w, q4.w);
        }
    }

    ull  O2[4][2];
    float mrow[4], lrow[4];
#pragma unroll
    for (int i = 0; i < 4; i++) {
        mrow[i] = -INFINITY; lrow[i] = 0.f;
        O2[i][0] = 0ull; O2[i][1] = 0ull;
    }

    const int kc = tid >> 2, kseg = (tid & 3) * 32;   // K-loader mapping
    const int vk = tid >> 1, vseg = (tid & 1) * 32;   // V-loader mapping

    for (int mt = 0; mt < 50; mt++) {
        const int m0 = mt * 128;
        __syncthreads();   // prior-iter KP/Vs readers done
        {
            const float* kp = Kg + (size_t)kc * NN + m0 + kseg;
            float* kd = KP + kc * 132 + kseg;
#pragma unroll
            for (int t = 0; t < 8; t++)
                *(float4*)(kd + 4 * t) = *(const float4*)(kp + 4 * t);
            const float* vp = Vg + ((size_t)(m0 + vk)) * 64 + vseg;
            float* vd = Vs + vk * 68 + vseg;
#pragma unroll
            for (int t = 0; t < 8; t++)
                *(float4*)(vd + 4 * t) = *(const float4*)(vp + 4 * t);
        }
        __syncthreads();

        // ---- S = Q @ K, packed pairs along key axis ----
        ull S2[4][4];
#pragma unroll
        for (int i = 0; i < 4; i++)
#pragma unroll
            for (int j = 0; j < 4; j++) S2[i][j] = 0ull;

        const float* qbase = Qs + 2 * (ty * 4);
        const float* kbase = KP + tx * 8;
#pragma unroll 4
        for (int c = 0; c < 64; c++) {
            const ull* qp = (const ull*)(qbase + c * 136);
            const ull* kp = (const ull*)(kbase + c * 132);
            ull q0 = qp[0], q1 = qp[1], q2 = qp[2], q3 = qp[3];
            ull k0 = kp[0], k1 = kp[1], k2 = kp[2], k3 = kp[3];
            fma2(S2[0][0], q0, k0); fma2(S2[0][1], q0, k1);
            fma2(S2[0][2], q0, k2); fma2(S2[0][3], q0, k3);
            fma2(S2[1][0], q1, k0); fma2(S2[1][1], q1, k1);
            fma2(S2[1][2], q1, k2); fma2(S2[1][3], q1, k3);
            fma2(S2[2][0], q2, k0); fma2(S2[2][1], q2, k1);
            fma2(S2[2][2], q2, k2); fma2(S2[2][3], q2, k3);
            fma2(S2[3][0], q3, k0); fma2(S2[3][1], q3, k1);
            fma2(S2[3][2], q3, k2); fma2(S2[3][3], q3, k3);
        }

        // ---- online softmax (reduce across tx = 16 lanes in half-warp) ----
        float P[4][8];
#pragma unroll
        for (int i = 0; i < 4; i++) {
            float2 e0 = unpk(S2[i][0]), e1 = unpk(S2[i][1]);
            float2 e2 = unpk(S2[i][2]), e3 = unpk(S2[i][3]);
            P[i][0] = e0.x; P[i][1] = e0.y; P[i][2] = e1.x; P[i][3] = e1.y;
            P[i][4] = e2.x; P[i][5] = e2.y; P[i][6] = e3.x; P[i][7] = e3.y;
            float m = fmaxf(fmaxf(fmaxf(P[i][0], P[i][1]), fmaxf(P[i][2], P[i][3])),
                            fmaxf(fmaxf(P[i][4], P[i][5]), fmaxf(P[i][6], P[i][7])));
#pragma unroll
            for (int s = 8; s >= 1; s >>= 1)
                m = fmaxf(m, __shfl_xor_sync(0xffffffffu, m, s));
            float mnew = fmaxf(mrow[i], m);
            float scl  = __expf(mrow[i] - mnew);
            mrow[i] = mnew;
            float ts = 0.f;
#pragma unroll
            for (int j = 0; j < 8; j++) {
                P[i][j] = __expf(P[i][j] - mnew);
                ts += P[i][j];
            }
#pragma unroll
            for (int s = 8; s >= 1; s >>= 1)
                ts += __shfl_xor_sync(0xffffffffu, ts, s);
            lrow[i] = lrow[i] * scl + ts;
            ull sd = dup2f(scl);
            O2[i][0] = mul2(O2[i][0], sd);
            O2[i][1] = mul2(O2[i][1], sd);
        }

        __syncthreads();   // S-phase KP readers done
#pragma unroll
        for (int i = 0; i < 4; i++) {
            float* pd = KP + (ty * 4 + i) * 132 + tx * 8;
            *(float4*)(pd)     = make_float4(P[i][0], P[i][1], P[i][2], P[i][3]);
            *(float4*)(pd + 4) = make_float4(P[i][4], P[i][5], P[i][6], P[i][7]);
        }
        __syncthreads();

        // ---- O += P @ V, packed pairs along channel axis ----
#pragma unroll 2
        for (int kb = 0; kb < 32; kb++) {
            float4 p0 = *(const float4*)(KP + (ty * 4 + 0) * 132 + kb * 4);
            float4 p1 = *(const float4*)(KP + (ty * 4 + 1) * 132 + kb * 4);
            float4 p2 = *(const float4*)(KP + (ty * 4 + 2) * 132 + kb * 4);
            float4 p3 = *(const float4*)(KP + (ty * 4 + 3) * 132 + kb * 4);
            float pe[4][4] = {{p0.x, p0.y, p0.z, p0.w},
                              {p1.x, p1.y, p1.z, p1.w},
                              {p2.x, p2.y, p2.z, p2.w},
                              {p3.x, p3.y, p3.z, p3.w}};
#pragma unroll
            for (int kk = 0; kk < 4; kk++) {
                const ull* vp = (const ull*)(Vs + (kb * 4 + kk) * 68 + tx * 4);
                ull v0 = vp[0], v1 = vp[1];
#pragma unroll
                for (int i = 0; i < 4; i++) {
                    ull pd = dup2f(pe[i][kk]);
                    fma2(O2[i][0], pd, v0);
                    fma2(O2[i][1], pd, v1);
                }
            }
        }
    }

    // ---- epilogue: normalize, accumulate into out ----
    float oc[4][4];   // [j(ch)][i(row)]
#pragma unroll
    for (int i = 0; i < 4; i++) {
        float inv = 1.f / lrow[i];
        float2 e0 = unpk(O2[i][0]), e1 = unpk(O2[i][1]);
        oc[0][i] = e0.x * inv; oc[1][i] = e0.y * inv;
        oc[2][i] = e1.x * inv; oc[3][i] = e1.y * inv;
    }
#pragma unroll
    for (int j = 0; j < 4; j++) {
        float* op = out + ((size_t)b * 64 + tx * 4 + j) * NN + n0 + ty * 4;
        float4 o4 = *(float4*)op;
        o4.x += oc[j][0]; o4.y += oc[j][1];
        o4.z += oc[j][2]; o4.w += oc[j][3];
        *(float4*)op = o4;
    }
}

// ---------------------------------------------------------------------------
extern "C" void kernel_launch(void* const* d_in, const int* in_sizes, int n_in,
                              void* d_out, int out_size)
{
    const float* x    = (const float*)d_in[0];
    const float* w    = (const float*)d_in[1];
    const float* bias = (const float*)d_in[2];
    float* out = (float*)d_out;

    const int flash_smem = FL_SMEM_FLOATS * 4;  // 103424 B
    cudaFuncSetAttribute(flash2_kernel,
                         cudaFuncAttributeMaxDynamicSharedMemorySize, flash_smem);

    qkv_kernel<<<dim3(100, 2, 4), 256>>>(x, w, bias);
    chan_logits_kernel<<<dim3(32, 4), 256>>>();
    chan_softmax_kernel<<<4, 64>>>();
    chan_apply_kernel<<<dim3(100, 4), 256>>>(out);
    flash2_kernel<<<dim3(100, 4), 256, flash_smem>>>(out);
}

// round 3
// speedup vs baseline: 1.2233x; 1.2233x over previous
#include <cuda_runtime.h>
#include <math.h>

#define BB 4
#define CC 64
#define NN 6400   // 80*80

typedef unsigned long long ull;

// Scratch (module-static device memory; no runtime allocation).
__device__ float g_Q [BB * NN * CC];   // [b][n][c], row n holds q[:, n%80, n/80]
__device__ float g_K [BB * CC * NN];   // [b][c][m], natural pixel order
__device__ float g_V [BB * NN * CC];   // [b][m][c], row m holds v[:, m%80, m/80]
__device__ float g_Kc[BB * NN * CC];   // [b][m][c], k natural order
__device__ float g_Lp[BB * 32 * CC * CC];
__device__ float g_ma[BB * CC * CC];

// ---------------- packed f32x2 helpers (sm_103a) ----------------
__device__ __forceinline__ void fma2(ull& acc, ull a, ull b) {
    asm("fma.rn.f32x2 %0, %1, %2, %0;" : "+l"(acc) : "l"(a), "l"(b));
}
__device__ __forceinline__ ull mul2(ull a, ull b) {
    ull r; asm("mul.rn.f32x2 %0, %1, %2;" : "=l"(r) : "l"(a), "l"(b)); return r;
}
__device__ __forceinline__ ull dup2f(float x) {
    ull r; asm("mov.b64 %0, {%1, %1};" : "=l"(r) : "f"(x)); return r;
}
__device__ __forceinline__ float2 unpk(ull v) {
    float2 f; asm("mov.b64 {%0, %1}, %2;" : "=f"(f.x), "=f"(f.y) : "l"(v)); return f;
}

// ---------------------------------------------------------------------------
// Kernel 1: 1x1 conv qkv. grid (100, 2, 4)
// ---------------------------------------------------------------------------
__global__ __launch_bounds__(256) void qkv_kernel(
    const float* __restrict__ x, const float* __restrict__ w,
    const float* __restrict__ bias)
{
    __shared__ float ws[64][100];
    __shared__ float xs[64][64];

    const int b     = blockIdx.z;
    const int half  = blockIdx.y;
    const int n0    = blockIdx.x * 64;
    const int tid   = threadIdx.x;
    const int obase = half * 96;

    for (int idx = tid; idx < 96 * 64; idx += 256) {
        int o = idx >> 6;
        int c = idx & 63;
        ws[c][o] = w[(size_t)(obase + o) * 64 + c];
    }
    for (int idx = tid; idx < 64 * 64; idx += 256) {
        int c = idx >> 6;
        int p = idx & 63;
        xs[c][p] = x[((size_t)b * 64 + c) * NN + n0 + p];
    }
    __syncthreads();

    const int p  = tid & 63;
    const int o0 = (tid >> 6) * 24;

    float acc[24];
#pragma unroll
    for (int j = 0; j < 24; j++) acc[j] = 0.f;

#pragma unroll 4
    for (int c = 0; c < 64; c++) {
        float xv = xs[c][p];
#pragma unroll
        for (int j4 = 0; j4 < 24; j4 += 4) {
            float4 wv = *(const float4*)&ws[c][o0 + j4];
            acc[j4 + 0] += xv * wv.x;
            acc[j4 + 1] += xv * wv.y;
            acc[j4 + 2] += xv * wv.z;
            acc[j4 + 3] += xv * wv.w;
        }
    }

    const int n  = n0 + p;
    const int h  = n / 80;
    const int wq = n % 80;
    const int nt = wq * 80 + h;

#pragma unroll
    for (int j4 = 0; j4 < 24; j4 += 4) {
        const int o = obase + o0 + j4;
        float4 v4;
        v4.x = acc[j4 + 0] + bias[o + 0];
        v4.y = acc[j4 + 1] + bias[o + 1];
        v4.z = acc[j4 + 2] + bias[o + 2];
        v4.w = acc[j4 + 3] + bias[o + 3];
        if (o < 64) {
            g_K[((size_t)b * 64 + o + 0) * NN + n] = v4.x;
            g_K[((size_t)b * 64 + o + 1) * NN + n] = v4.y;
            g_K[((size_t)b * 64 + o + 2) * NN + n] = v4.z;
            g_K[((size_t)b * 64 + o + 3) * NN + n] = v4.w;
            *(float4*)&g_Q[((size_t)b * NN + nt) * 64 + o] = v4;
        } else if (o < 128) {
            *(float4*)&g_Kc[((size_t)b * NN + n) * 64 + (o - 64)] = v4;
        } else {
            *(float4*)&g_V[((size_t)b * NN + nt) * 64 + (o - 128)] = v4;
        }
    }
}

// ---------------------------------------------------------------------------
// Kernel 2a: channel-attn logit partials. grid (32, 4), 256 thr
// ---------------------------------------------------------------------------
__global__ __launch_bounds__(256) void chan_logits_kernel()
{
    const int b = blockIdx.y, chunk = blockIdx.x;
    const int tid = threadIdx.x;
    const int tx = tid & 15, ty = tid >> 4;
    const float* __restrict__ Kc = g_Kc + (size_t)b * NN * CC;
    const float* __restrict__ Qm = g_Q  + (size_t)b * NN * CC;

    float acc[4][4];
#pragma unroll
    for (int i = 0; i < 4; i++)
#pragma unroll
        for (int j = 0; j < 4; j++) acc[i][j] = 0.f;

    const int m0 = chunk * 200;
#pragma unroll 2
    for (int m = m0; m < m0 + 200; m++) {
        float4 kv4 = *(const float4*)(Kc + (size_t)m * 64 + ty * 4);
        float4 qv4 = *(const float4*)(Qm + (size_t)m * 64 + tx * 4);
        float kv[4] = {kv4.x, kv4.y, kv4.z, kv4.w};
        float qv[4] = {qv4.x, qv4.y, qv4.z, qv4.w};
#pragma unroll
        for (int i = 0; i < 4; i++)
#pragma unroll
            for (int j = 0; j < 4; j++)
                acc[i][j] += kv[i] * qv[j];
    }

    float* Lp = g_Lp + ((size_t)b * 32 + chunk) * 64 * 64;
#pragma unroll
    for (int i = 0; i < 4; i++) {
        float4 o4 = make_float4(acc[i][0], acc[i][1], acc[i][2], acc[i][3]);
        *(float4*)(Lp + (size_t)(ty * 4 + i) * 64 + tx * 4) = o4;
    }
}

// ---------------------------------------------------------------------------
// Kernel 2b: reduce + softmax. grid 4, 64 threads
// ---------------------------------------------------------------------------
__global__ void chan_softmax_kernel()
{
    const int b = blockIdx.x;
    const int c = threadIdx.x;
    float s[64];
#pragma unroll
    for (int j = 0; j < 64; j++) s[j] = 0.f;

    for (int ch = 0; ch < 32; ch++) {
        const float* p = g_Lp + (((size_t)b * 32 + ch) * 64 + c) * 64;
#pragma unroll
        for (int j4 = 0; j4 < 64; j4 += 4) {
            float4 v = *(const float4*)(p + j4);
            s[j4 + 0] += v.x; s[j4 + 1] += v.y;
            s[j4 + 2] += v.z; s[j4 + 3] += v.w;
        }
    }
    float mx = -INFINITY;
#pragma unroll
    for (int j = 0; j < 64; j++) mx = fmaxf(mx, s[j]);
    float sum = 0.f;
#pragma unroll
    for (int j = 0; j < 64; j++) { s[j] = expf(s[j] - mx); sum += s[j]; }
    const float inv = 1.f / sum;
    float* o = g_ma + ((size_t)b * 64 + c) * 64;
#pragma unroll
    for (int j4 = 0; j4 < 64; j4 += 4) {
        float4 v = make_float4(s[j4] * inv, s[j4 + 1] * inv,
                               s[j4 + 2] * inv, s[j4 + 3] * inv);
        *(float4*)(o + j4) = v;
    }
}

// ---------------------------------------------------------------------------
// Kernel 3: channel apply. grid (100, 4), 256 thr
// ---------------------------------------------------------------------------
__global__ __launch_bounds__(256) void chan_apply_kernel(float* __restrict__ out)
{
    __shared__ float vs[64][64];
    __shared__ float mas[64][65];

    const int b  = blockIdx.y;
    const int n0 = blockIdx.x * 64;
    const int tid = threadIdx.x;
    const int tx = tid & 15, ty = tid >> 4;

    for (int idx = tid; idx < 4096; idx += 256) {
        int c  = idx >> 6;
        int cp = idx & 63;
        mas[cp][c] = g_ma[((size_t)b * 64 + c) * 64 + cp];
    }
    {
        int p  = tid >> 2;
        int cb = (tid & 3) * 16;
        int n  = n0 + p;
        int nt = (n % 80) * 80 + n / 80;
        const float* vp = g_V + ((size_t)b * NN + nt) * 64 + cb;
#pragma unroll
        for (int k = 0; k < 4; k++) {
            float4 v4 = *(const float4*)(vp + 4 * k);
            vs[cb + 4 * k + 0][p] = v4.x;
            vs[cb + 4 * k + 1][p] = v4.y;
            vs[cb + 4 * k + 2][p] = v4.z;
            vs[cb + 4 * k + 3][p] = v4.w;
        }
    }
    __syncthreads();

    float acc[4][4];
#pragma unroll
    for (int i = 0; i < 4; i++)
#pragma unroll
        for (int j = 0; j < 4; j++) acc[i][j] = 0.f;

#pragma unroll 4
    for (int cp = 0; cp < 64; cp++) {
        float mv[4];
#pragma unroll
        for (int i = 0; i < 4; i++) mv[i] = mas[cp][ty * 4 + i];
        float4 v4 = *(const float4*)&vs[cp][tx * 4];
        float vv[4] = {v4.x, v4.y, v4.z, v4.w};
#pragma unroll
        for (int i = 0; i < 4; i++)
#pragma unroll
            for (int j = 0; j < 4; j++)
                acc[i][j] += mv[i] * vv[j];
    }
#pragma unroll
    for (int i = 0; i < 4; i++) {
        float4 o4 = make_float4(acc[i][0], acc[i][1], acc[i][2], acc[i][3]);
        *(float4*)(out + ((size_t)b * 64 + ty * 4 + i) * NN + n0 + tx * 4) = o4;
    }
}

// ---------------------------------------------------------------------------
// Kernel 4: spatial flash attention v3 (f32x2, conflict-free LDS.128).
// grid (100, 4), 256 threads, M-tile 64, key tile 128.
// Thread (tx,ty): rows ty*4..+3; keys {4tx..4tx+3} u {64+4tx..+3};
// output channels 4tx..4tx+3.
// smem: Qs[c][2r] dup 64x136, KP union{K[c][m] 64x132, P[r][m] 64x132},
//       Vs[m][c] 128x68.  103424 B dynamic, 2 CTAs/SM.
// ---------------------------------------------------------------------------
#define FL_SMEM_FLOATS (64*136 + 64*132 + 128*68)

__global__ __launch_bounds__(256, 2) void flash3_kernel(float* __restrict__ out)
{
    extern __shared__ float sm[];
    float* Qs = sm;                       // 64 x 136 (row-duplicated)
    float* KP = sm + 64 * 136;            // 64 x 132
    float* Vs = sm + 64 * 136 + 64 * 132; // 128 x 68

    const int b  = blockIdx.y;
    const int n0 = blockIdx.x * 64;
    const int tid = threadIdx.x;
    const int tx = tid & 15;
    const int ty = tid >> 4;

    const float* __restrict__ Qg = g_Q + (size_t)b * NN * CC;
    const float* __restrict__ Kg = g_K + (size_t)b * CC * NN;
    const float* __restrict__ Vg = g_V + (size_t)b * NN * CC;

    // Q tile, duplicated along row axis: Qs[c][2r] = Qs[c][2r+1] = Q[n0+r][c]
    {
        const int rr   = tid >> 2;
        const int cseg = (tid & 3) * 16;
        const float* qp = Qg + ((size_t)(n0 + rr)) * 64 + cseg;
#pragma unroll
        for (int t = 0; t < 4; t++) {
            float4 q4 = *(const float4*)(qp + 4 * t);
            float* d = Qs + (cseg + 4 * t) * 136 + 2 * rr;
            *(float2*)(d)       = make_float2(q4.x, q4.x);
            *(float2*)(d + 136) = make_float2(q4.y, q4.y);
            *(float2*)(d + 272) = make_float2(q4.z, q4.z);
            *(float2*)(d + 408) = make_float2(q4.w, q4.w);
        }
    }

    ull  O2[4][2];
    float mrow[4], lrow[4];
#pragma unroll
    for (int i = 0; i < 4; i++) {
        mrow[i] = -INFINITY; lrow[i] = 0.f;
        O2[i][0] = 0ull; O2[i][1] = 0ull;
    }

    const int kc = tid >> 2, kseg = (tid & 3) * 32;   // K-loader mapping
    const int vk = tid >> 1, vseg = (tid & 1) * 32;   // V-loader mapping

    const float* qbase = Qs + 2 * (ty * 4);
    const float* kbase = KP + tx * 4;

    for (int mt = 0; mt < 50; mt++) {
        const int m0 = mt * 128;
        __syncthreads();
        {
            const float* kp = Kg + (size_t)kc * NN + m0 + kseg;
            float* kd = KP + kc * 132 + kseg;
#pragma unroll
            for (int t = 0; t < 8; t++)
                *(float4*)(kd + 4 * t) = *(const float4*)(kp + 4 * t);
            const float* vp = Vg + ((size_t)(m0 + vk)) * 64 + vseg;
            float* vd = Vs + vk * 68 + vseg;
#pragma unroll
            for (int t = 0; t < 8; t++)
                *(float4*)(vd + 4 * t) = *(const float4*)(vp + 4 * t);
        }
        __syncthreads();

        // ---- S = Q @ K ----
        // S2[i][0]=keys(4tx,4tx+1), [1]=(4tx+2,+3), [2]=(64+4tx,+1), [3]=(64+4tx+2,+3)
        ull S2[4][4];
#pragma unroll
        for (int i = 0; i < 4; i++)
#pragma unroll
            for (int j = 0; j < 4; j++) S2[i][j] = 0ull;

#pragma unroll 4
        for (int c = 0; c < 64; c++) {
            ulonglong2 qA = *(const ulonglong2*)(qbase + c * 136);      // rows r0,r1 (dup)
            ulonglong2 qB = *(const ulonglong2*)(qbase + c * 136 + 4);  // rows r2,r3
            ulonglong2 kA = *(const ulonglong2*)(kbase + c * 132);      // keys 4tx..+3
            ulonglong2 kB = *(const ulonglong2*)(kbase + c * 132 + 64); // keys 64+4tx..+3
            fma2(S2[0][0], qA.x, kA.x); fma2(S2[0][1], qA.x, kA.y);
            fma2(S2[0][2], qA.x, kB.x); fma2(S2[0][3], qA.x, kB.y);
            fma2(S2[1][0], qA.y, kA.x); fma2(S2[1][1], qA.y, kA.y);
            fma2(S2[1][2], qA.y, kB.x); fma2(S2[1][3], qA.y, kB.y);
            fma2(S2[2][0], qB.x, kA.x); fma2(S2[2][1], qB.x, kA.y);
            fma2(S2[2][2], qB.x, kB.x); fma2(S2[2][3], qB.x, kB.y);
            fma2(S2[3][0], qB.y, kA.x); fma2(S2[3][1], qB.y, kA.y);
            fma2(S2[3][2], qB.y, kB.x); fma2(S2[3][3], qB.y, kB.y);
        }

        // ---- online softmax (reduce across tx within half-warp) ----
        float P[4][8];
#pragma unroll
        for (int i = 0; i < 4; i++) {
            float2 e0 = unpk(S2[i][0]), e1 = unpk(S2[i][1]);
            float2 e2 = unpk(S2[i][2]), e3 = unpk(S2[i][3]);
            P[i][0] = e0.x; P[i][1] = e0.y; P[i][2] = e1.x; P[i][3] = e1.y;
            P[i][4] = e2.x; P[i][5] = e2.y; P[i][6] = e3.x; P[i][7] = e3.y;
            float m = fmaxf(fmaxf(fmaxf(P[i][0], P[i][1]), fmaxf(P[i][2], P[i][3])),
                            fmaxf(fmaxf(P[i][4], P[i][5]), fmaxf(P[i][6], P[i][7])));
#pragma unroll
            for (int s = 8; s >= 1; s >>= 1)
                m = fmaxf(m, __shfl_xor_sync(0xffffffffu, m, s));
            float mnew = fmaxf(mrow[i], m);
            float scl  = __expf(mrow[i] - mnew);
            mrow[i] = mnew;
            float ts = 0.f;
#pragma unroll
            for (int j = 0; j < 8; j++) {
                P[i][j] = __expf(P[i][j] - mnew);
                ts += P[i][j];
            }
#pragma unroll
            for (int s = 8; s >= 1; s >>= 1)
                ts += __shfl_xor_sync(0xffffffffu, ts, s);
            lrow[i] = lrow[i] * scl + ts;
            ull sd = dup2f(scl);
            O2[i][0] = mul2(O2[i][0], sd);
            O2[i][1] = mul2(O2[i][1], sd);
        }

        __syncthreads();
#pragma unroll
        for (int i = 0; i < 4; i++) {
            float* pd = KP + (ty * 4 + i) * 132 + tx * 4;
            *(float4*)(pd)      = make_float4(P[i][0], P[i][1], P[i][2], P[i][3]);
            *(float4*)(pd + 64) = make_float4(P[i][4], P[i][5], P[i][6], P[i][7]);
        }
        __syncthreads();

        // ---- O += P @ V (channels 4tx..4tx+3 per thread) ----
#pragma unroll 2
        for (int kb = 0; kb < 32; kb++) {
            float4 p0 = *(const float4*)(KP + (ty * 4 + 0) * 132 + kb * 4);
            float4 p1 = *(const float4*)(KP + (ty * 4 + 1) * 132 + kb * 4);
            float4 p2 = *(const float4*)(KP + (ty * 4 + 2) * 132 + kb * 4);
            float4 p3 = *(const float4*)(KP + (ty * 4 + 3) * 132 + kb * 4);
            float pe[4][4] = {{p0.x, p0.y, p0.z, p0.w},
                              {p1.x, p1.y, p1.z, p1.w},
                              {p2.x, p2.y, p2.z, p2.w},
                              {p3.x, p3.y, p3.z, p3.w}};
#pragma unroll
            for (int kk = 0; kk < 4; kk++) {
                ulonglong2 v = *(const ulonglong2*)(Vs + (kb * 4 + kk) * 68 + tx * 4);
#pragma unroll
                for (int i = 0; i < 4; i++) {
                    ull pd = dup2f(pe[i][kk]);
                    fma2(O2[i][0], pd, v.x);
                    fma2(O2[i][1], pd, v.y);
                }
            }
        }
    }

    // ---- epilogue: normalize, accumulate into out ----
    float oc[4][4];   // [j(ch)][i(row)]
#pragma unroll
    for (int i = 0; i < 4; i++) {
        float inv = 1.f / lrow[i];
        float2 e0 = unpk(O2[i][0]), e1 = unpk(O2[i][1]);
        oc[0][i] = e0.x * inv; oc[1][i] = e0.y * inv;
        oc[2][i] = e1.x * inv; oc[3][i] = e1.y * inv;
    }
#pragma unroll
    for (int j = 0; j < 4; j++) {
        float* op = out + ((size_t)b * 64 + tx * 4 + j) * NN + n0 + ty * 4;
        float4 o4 = *(float4*)op;
        o4.x += oc[j][0]; o4.y += oc[j][1];
        o4.z += oc[j][2]; o4.w += oc[j][3];
        *(float4*)op = o4;
    }
}

// ---------------------------------------------------------------------------
extern "C" void kernel_launch(void* const* d_in, const int* in_sizes, int n_in,
                              void* d_out, int out_size)
{
    const float* x    = (const float*)d_in[0];
    const float* w    = (const float*)d_in[1];
    const float* bias = (const float*)d_in[2];
    float* out = (float*)d_out;

    const int flash_smem = FL_SMEM_FLOATS * 4;  // 103424 B
    cudaFuncSetAttribute(flash3_kernel,
                         cudaFuncAttributeMaxDynamicSharedMemorySize, flash_smem);

    qkv_kernel<<<dim3(100, 2, 4), 256>>>(x, w, bias);
    chan_logits_kernel<<<dim3(32, 4), 256>>>();
    chan_softmax_kernel<<<4, 64>>>();
    chan_apply_kernel<<<dim3(100, 4), 256>>>(out);
    flash3_kernel<<<dim3(100, 4), 256, flash_smem>>>(out);
}

// round 4
// speedup vs baseline: 1.2236x; 1.0002x over previous
#include <cuda_runtime.h>
#include <math.h>

#define BB 4
#define CC 64
#define NN 6400   // 80*80

typedef unsigned long long ull;

// Scratch (module-static device memory; no runtime allocation).
__device__ float g_Q [BB * NN * CC];   // [b][n][c], row n holds q[:, n%80, n/80]
__device__ float g_K [BB * CC * NN];   // [b][c][m], natural pixel order
__device__ float g_V [BB * NN * CC];   // [b][m][c], row m holds v[:, m%80, m/80]
__device__ float g_Kc[BB * NN * CC];   // [b][m][c], k natural order
__device__ float g_Lp[BB * 32 * CC * CC];
__device__ float g_ma[BB * CC * CC];

// ---------------- packed f32x2 helpers (sm_103a) ----------------
__device__ __forceinline__ void fma2(ull& acc, ull a, ull b) {
    asm("fma.rn.f32x2 %0, %1, %2, %0;" : "+l"(acc) : "l"(a), "l"(b));
}
__device__ __forceinline__ ull mul2(ull a, ull b) {
    ull r; asm("mul.rn.f32x2 %0, %1, %2;" : "=l"(r) : "l"(a), "l"(b)); return r;
}
__device__ __forceinline__ ull dup2f(float x) {
    ull r; asm("mov.b64 %0, {%1, %1};" : "=l"(r) : "f"(x)); return r;
}
__device__ __forceinline__ float2 unpk(ull v) {
    float2 f; asm("mov.b64 {%0, %1}, %2;" : "=f"(f.x), "=f"(f.y) : "l"(v)); return f;
}

// ---------------------------------------------------------------------------
// Kernel 1: 1x1 conv qkv. grid (100, 2, 4)
// ---------------------------------------------------------------------------
__global__ __launch_bounds__(256) void qkv_kernel(
    const float* __restrict__ x, const float* __restrict__ w,
    const float* __restrict__ bias)
{
    __shared__ float ws[64][100];
    __shared__ float xs[64][64];

    const int b     = blockIdx.z;
    const int half  = blockIdx.y;
    const int n0    = blockIdx.x * 64;
    const int tid   = threadIdx.x;
    const int obase = half * 96;

    for (int idx = tid; idx < 96 * 64; idx += 256) {
        int o = idx >> 6;
        int c = idx & 63;
        ws[c][o] = w[(size_t)(obase + o) * 64 + c];
    }
    for (int idx = tid; idx < 64 * 64; idx += 256) {
        int c = idx >> 6;
        int p = idx & 63;
        xs[c][p] = x[((size_t)b * 64 + c) * NN + n0 + p];
    }
    __syncthreads();

    const int p  = tid & 63;
    const int o0 = (tid >> 6) * 24;

    float acc[24];
#pragma unroll
    for (int j = 0; j < 24; j++) acc[j] = 0.f;

#pragma unroll 4
    for (int c = 0; c < 64; c++) {
        float xv = xs[c][p];
#pragma unroll
        for (int j4 = 0; j4 < 24; j4 += 4) {
            float4 wv = *(const float4*)&ws[c][o0 + j4];
            acc[j4 + 0] += xv * wv.x;
            acc[j4 + 1] += xv * wv.y;
            acc[j4 + 2] += xv * wv.z;
            acc[j4 + 3] += xv * wv.w;
        }
    }

    const int n  = n0 + p;
    const int h  = n / 80;
    const int wq = n % 80;
    const int nt = wq * 80 + h;

#pragma unroll
    for (int j4 = 0; j4 < 24; j4 += 4) {
        const int o = obase + o0 + j4;
        float4 v4;
        v4.x = acc[j4 + 0] + bias[o + 0];
        v4.y = acc[j4 + 1] + bias[o + 1];
        v4.z = acc[j4 + 2] + bias[o + 2];
        v4.w = acc[j4 + 3] + bias[o + 3];
        if (o < 64) {
            g_K[((size_t)b * 64 + o + 0) * NN + n] = v4.x;
            g_K[((size_t)b * 64 + o + 1) * NN + n] = v4.y;
            g_K[((size_t)b * 64 + o + 2) * NN + n] = v4.z;
            g_K[((size_t)b * 64 + o + 3) * NN + n] = v4.w;
            *(float4*)&g_Q[((size_t)b * NN + nt) * 64 + o] = v4;
        } else if (o < 128) {
            *(float4*)&g_Kc[((size_t)b * NN + n) * 64 + (o - 64)] = v4;
        } else {
            *(float4*)&g_V[((size_t)b * NN + nt) * 64 + (o - 128)] = v4;
        }
    }
}

// ---------------------------------------------------------------------------
// Kernel 2a: channel-attn logit partials. grid (32, 4), 256 thr
// ---------------------------------------------------------------------------
__global__ __launch_bounds__(256) void chan_logits_kernel()
{
    const int b = blockIdx.y, chunk = blockIdx.x;
    const int tid = threadIdx.x;
    const int tx = tid & 15, ty = tid >> 4;
    const float* __restrict__ Kc = g_Kc + (size_t)b * NN * CC;
    const float* __restrict__ Qm = g_Q  + (size_t)b * NN * CC;

    float acc[4][4];
#pragma unroll
    for (int i = 0; i < 4; i++)
#pragma unroll
        for (int j = 0; j < 4; j++) acc[i][j] = 0.f;

    const int m0 = chunk * 200;
#pragma unroll 2
    for (int m = m0; m < m0 + 200; m++) {
        float4 kv4 = *(const float4*)(Kc + (size_t)m * 64 + ty * 4);
        float4 qv4 = *(const float4*)(Qm + (size_t)m * 64 + tx * 4);
        float kv[4] = {kv4.x, kv4.y, kv4.z, kv4.w};
        float qv[4] = {qv4.x, qv4.y, qv4.z, qv4.w};
#pragma unroll
        for (int i = 0; i < 4; i++)
#pragma unroll
            for (int j = 0; j < 4; j++)
                acc[i][j] += kv[i] * qv[j];
    }

    float* Lp = g_Lp + ((size_t)b * 32 + chunk) * 64 * 64;
#pragma unroll
    for (int i = 0; i < 4; i++) {
        float4 o4 = make_float4(acc[i][0], acc[i][1], acc[i][2], acc[i][3]);
        *(float4*)(Lp + (size_t)(ty * 4 + i) * 64 + tx * 4) = o4;
    }
}

// ---------------------------------------------------------------------------
// Kernel 2b: reduce + softmax. grid 4, 64 threads
// ---------------------------------------------------------------------------
__global__ void chan_softmax_kernel()
{
    const int b = blockIdx.x;
    const int c = threadIdx.x;
    float s[64];
#pragma unroll
    for (int j = 0; j < 64; j++) s[j] = 0.f;

    for (int ch = 0; ch < 32; ch++) {
        const float* p = g_Lp + (((size_t)b * 32 + ch) * 64 + c) * 64;
#pragma unroll
        for (int j4 = 0; j4 < 64; j4 += 4) {
            float4 v = *(const float4*)(p + j4);
            s[j4 + 0] += v.x; s[j4 + 1] += v.y;
            s[j4 + 2] += v.z; s[j4 + 3] += v.w;
        }
    }
    float mx = -INFINITY;
#pragma unroll
    for (int j = 0; j < 64; j++) mx = fmaxf(mx, s[j]);
    float sum = 0.f;
#pragma unroll
    for (int j = 0; j < 64; j++) { s[j] = expf(s[j] - mx); sum += s[j]; }
    const float inv = 1.f / sum;
    float* o = g_ma + ((size_t)b * 64 + c) * 64;
#pragma unroll
    for (int j4 = 0; j4 < 64; j4 += 4) {
        float4 v = make_float4(s[j4] * inv, s[j4 + 1] * inv,
                               s[j4 + 2] * inv, s[j4 + 3] * inv);
        *(float4*)(o + j4) = v;
    }
}

// ---------------------------------------------------------------------------
// Kernel 3: channel apply. grid (100, 4), 256 thr
// ---------------------------------------------------------------------------
__global__ __launch_bounds__(256) void chan_apply_kernel(float* __restrict__ out)
{
    __shared__ float vs[64][64];
    __shared__ float mas[64][65];

    const int b  = blockIdx.y;
    const int n0 = blockIdx.x * 64;
    const int tid = threadIdx.x;
    const int tx = tid & 15, ty = tid >> 4;

    for (int idx = tid; idx < 4096; idx += 256) {
        int c  = idx >> 6;
        int cp = idx & 63;
        mas[cp][c] = g_ma[((size_t)b * 64 + c) * 64 + cp];
    }
    {
        int p  = tid >> 2;
        int cb = (tid & 3) * 16;
        int n  = n0 + p;
        int nt = (n % 80) * 80 + n / 80;
        const float* vp = g_V + ((size_t)b * NN + nt) * 64 + cb;
#pragma unroll
        for (int k = 0; k < 4; k++) {
            float4 v4 = *(const float4*)(vp + 4 * k);
            vs[cb + 4 * k + 0][p] = v4.x;
            vs[cb + 4 * k + 1][p] = v4.y;
            vs[cb + 4 * k + 2][p] = v4.z;
            vs[cb + 4 * k + 3][p] = v4.w;
        }
    }
    __syncthreads();

    float acc[4][4];
#pragma unroll
    for (int i = 0; i < 4; i++)
#pragma unroll
        for (int j = 0; j < 4; j++) acc[i][j] = 0.f;

#pragma unroll 4
    for (int cp = 0; cp < 64; cp++) {
        float mv[4];
#pragma unroll
        for (int i = 0; i < 4; i++) mv[i] = mas[cp][ty * 4 + i];
        float4 v4 = *(const float4*)&vs[cp][tx * 4];
        float vv[4] = {v4.x, v4.y, v4.z, v4.w};
#pragma unroll
        for (int i = 0; i < 4; i++)
#pragma unroll
            for (int j = 0; j < 4; j++)
                acc[i][j] += mv[i] * vv[j];
    }
#pragma unroll
    for (int i = 0; i < 4; i++) {
        float4 o4 = make_float4(acc[i][0], acc[i][1], acc[i][2], acc[i][3]);
        *(float4*)(out + ((size_t)b * 64 + ty * 4 + i) * NN + n0 + tx * 4) = o4;
    }
}

// ---------------------------------------------------------------------------
// Kernel 4: spatial flash attention v3 (f32x2, conflict-free LDS.128).
// grid (100, 4), 256 threads, M-tile 64, key tile 128.
// Thread (tx,ty): rows ty*4..+3; keys {4tx..4tx+3} u {64+4tx..+3};
// output channels 4tx..4tx+3.
// smem: Qs[c][2r] dup 64x136, KP union{K[c][m] 64x132, P[r][m] 64x132},
//       Vs[m][c] 128x68.  103424 B dynamic, 2 CTAs/SM.
// ---------------------------------------------------------------------------
#define FL_SMEM_FLOATS (64*136 + 64*132 + 128*68)

__global__ __launch_bounds__(256, 2) void flash3_kernel(float* __restrict__ out)
{
    extern __shared__ float sm[];
    float* Qs = sm;                       // 64 x 136 (row-duplicated)
    float* KP = sm + 64 * 136;            // 64 x 132
    float* Vs = sm + 64 * 136 + 64 * 132; // 128 x 68

    const int b  = blockIdx.y;
    const int n0 = blockIdx.x * 64;
    const int tid = threadIdx.x;
    const int tx = tid & 15;
    const int ty = tid >> 4;

    const float* __restrict__ Qg = g_Q + (size_t)b * NN * CC;
    const float* __restrict__ Kg = g_K + (size_t)b * CC * NN;
    const float* __restrict__ Vg = g_V + (size_t)b * NN * CC;

    // Q tile, duplicated along row axis: Qs[c][2r] = Qs[c][2r+1] = Q[n0+r][c]
    {
        const int rr   = tid >> 2;
        const int cseg = (tid & 3) * 16;
        const float* qp = Qg + ((size_t)(n0 + rr)) * 64 + cseg;
#pragma unroll
        for (int t = 0; t < 4; t++) {
            float4 q4 = *(const float4*)(qp + 4 * t);
            float* d = Qs + (cseg + 4 * t) * 136 + 2 * rr;
            *(float2*)(d)       = make_float2(q4.x, q4.x);
            *(float2*)(d + 136) = make_float2(q4.y, q4.y);
            *(float2*)(d + 272) = make_float2(q4.z, q4.z);
            *(float2*)(d + 408) = make_float2(q4.w, q4.w);
        }
    }

    ull  O2[4][2];
    float mrow[4], lrow[4];
#pragma unroll
    for (int i = 0; i < 4; i++) {
        mrow[i] = -INFINITY; lrow[i] = 0.f;
        O2[i][0] = 0ull; O2[i][1] = 0ull;
    }

    const int kc = tid >> 2, kseg = (tid & 3) * 32;   // K-loader mapping
    const int vk = tid >> 1, vseg = (tid & 1) * 32;   // V-loader mapping

    const float* qbase = Qs + 2 * (ty * 4);
    const float* kbase = KP + tx * 4;

    for (int mt = 0; mt < 50; mt++) {
        const int m0 = mt * 128;
        __syncthreads();
        {
            const float* kp = Kg + (size_t)kc * NN + m0 + kseg;
            float* kd = KP + kc * 132 + kseg;
#pragma unroll
            for (int t = 0; t < 8; t++)
                *(float4*)(kd + 4 * t) = *(const float4*)(kp + 4 * t);
            const float* vp = Vg + ((size_t)(m0 + vk)) * 64 + vseg;
            float* vd = Vs + vk * 68 + vseg;
#pragma unroll
            for (int t = 0; t < 8; t++)
                *(float4*)(vd + 4 * t) = *(const float4*)(vp + 4 * t);
        }
        __syncthreads();

        // ---- S = Q @ K ----
        // S2[i][0]=keys(4tx,4tx+1), [1]=(4tx+2,+3), [2]=(64+4tx,+1), [3]=(64+4tx+2,+3)
        ull S2[4][4];
#pragma unroll
        for (int i = 0; i < 4; i++)
#pragma unroll
            for (int j = 0; j < 4; j++) S2[i][j] = 0ull;

#pragma unroll 4
        for (int c = 0; c < 64; c++) {
            ulonglong2 qA = *(const ulonglong2*)(qbase + c * 136);      // rows r0,r1 (dup)
            ulonglong2 qB = *(const ulonglong2*)(qbase + c * 136 + 4);  // rows r2,r3
            ulonglong2 kA = *(const ulonglong2*)(kbase + c * 132);      // keys 4tx..+3
            ulonglong2 kB = *(const ulonglong2*)(kbase + c * 132 + 64); // keys 64+4tx..+3
            fma2(S2[0][0], qA.x, kA.x); fma2(S2[0][1], qA.x, kA.y);
            fma2(S2[0][2], qA.x, kB.x); fma2(S2[0][3], qA.x, kB.y);
            fma2(S2[1][0], qA.y, kA.x); fma2(S2[1][1], qA.y, kA.y);
            fma2(S2[1][2], qA.y, kB.x); fma2(S2[1][3], qA.y, kB.y);
            fma2(S2[2][0], qB.x, kA.x); fma2(S2[2][1], qB.x, kA.y);
            fma2(S2[2][2], qB.x, kB.x); fma2(S2[2][3], qB.x, kB.y);
            fma2(S2[3][0], qB.y, kA.x); fma2(S2[3][1], qB.y, kA.y);
            fma2(S2[3][2], qB.y, kB.x); fma2(S2[3][3], qB.y, kB.y);
        }

        // ---- online softmax (reduce across tx within half-warp) ----
        float P[4][8];
#pragma unroll
        for (int i = 0; i < 4; i++) {
            float2 e0 = unpk(S2[i][0]), e1 = unpk(S2[i][1]);
            float2 e2 = unpk(S2[i][2]), e3 = unpk(S2[i][3]);
            P[i][0] = e0.x; P[i][1] = e0.y; P[i][2] = e1.x; P[i][3] = e1.y;
            P[i][4] = e2.x; P[i][5] = e2.y; P[i][6] = e3.x; P[i][7] = e3.y;
            float m = fmaxf(fmaxf(fmaxf(P[i][0], P[i][1]), fmaxf(P[i][2], P[i][3])),
                            fmaxf(fmaxf(P[i][4], P[i][5]), fmaxf(P[i][6], P[i][7])));
#pragma unroll
            for (int s = 8; s >= 1; s >>= 1)
                m = fmaxf(m, __shfl_xor_sync(0xffffffffu, m, s));
            float mnew = fmaxf(mrow[i], m);
            float scl  = __expf(mrow[i] - mnew);
            mrow[i] = mnew;
            float ts = 0.f;
#pragma unroll
            for (int j = 0; j < 8; j++) {
                P[i][j] = __expf(P[i][j] - mnew);
                ts += P[i][j];
            }
#pragma unroll
            for (int s = 8; s >= 1; s >>= 1)
                ts += __shfl_xor_sync(0xffffffffu, ts, s);
            lrow[i] = lrow[i] * scl + ts;
            ull sd = dup2f(scl);
            O2[i][0] = mul2(O2[i][0], sd);
            O2[i][1] = mul2(O2[i][1], sd);
        }

        __syncthreads();
#pragma unroll
        for (int i = 0; i < 4; i++) {
            float* pd = KP + (ty * 4 + i) * 132 + tx * 4;
            *(float4*)(pd)      = make_float4(P[i][0], P[i][1], P[i][2], P[i][3]);
            *(float4*)(pd + 64) = make_float4(P[i][4], P[i][5], P[i][6], P[i][7]);
        }
        __syncthreads();

        // ---- O += P @ V (channels 4tx..4tx+3 per thread) ----
#pragma unroll 2
        for (int kb = 0; kb < 32; kb++) {
            float4 p0 = *(const float4*)(KP + (ty * 4 + 0) * 132 + kb * 4);
            float4 p1 = *(const float4*)(KP + (ty * 4 + 1) * 132 + kb * 4);
            float4 p2 = *(const float4*)(KP + (ty * 4 + 2) * 132 + kb * 4);
            float4 p3 = *(const float4*)(KP + (ty * 4 + 3) * 132 + kb * 4);
            float pe[4][4] = {{p0.x, p0.y, p0.z, p0.w},
                              {p1.x, p1.y, p1.z, p1.w},
                              {p2.x, p2.y, p2.z, p2.w},
                              {p3.x, p3.y, p3.z, p3.w}};
#pragma unroll
            for (int kk = 0; kk < 4; kk++) {
                ulonglong2 v = *(const ulonglong2*)(Vs + (kb * 4 + kk) * 68 + tx * 4);
#pragma unroll
                for (int i = 0; i < 4; i++) {
                    ull pd = dup2f(pe[i][kk]);
                    fma2(O2[i][0], pd, v.x);
                    fma2(O2[i][1], pd, v.y);
                }
            }
        }
    }

    // ---- epilogue: normalize, accumulate into out ----
    float oc[4][4];   // [j(ch)][i(row)]
#pragma unroll
    for (int i = 0; i < 4; i++) {
        float inv = 1.f / lrow[i];
        float2 e0 = unpk(O2[i][0]), e1 = unpk(O2[i][1]);
        oc[0][i] = e0.x * inv; oc[1][i] = e0.y * inv;
        oc[2][i] = e1.x * inv; oc[3][i] = e1.y * inv;
    }
#pragma unroll
    for (int j = 0; j < 4; j++) {
        float* op = out + ((size_t)b * 64 + tx * 4 + j) * NN + n0 + ty * 4;
        float4 o4 = *(float4*)op;
        o4.x += oc[j][0]; o4.y += oc[j][1];
        o4.z += oc[j][2]; o4.w += oc[j][3];
        *(float4*)op = o4;
    }
}

// ---------------------------------------------------------------------------
extern "C" void kernel_launch(void* const* d_in, const int* in_sizes, int n_in,
                              void* d_out, int out_size)
{
    const float* x    = (const float*)d_in[0];
    const float* w    = (const float*)d_in[1];
    const float* bias = (const float*)d_in[2];
    float* out = (float*)d_out;

    const int flash_smem = FL_SMEM_FLOATS * 4;  // 103424 B
    cudaFuncSetAttribute(flash3_kernel,
                         cudaFuncAttributeMaxDynamicSharedMemorySize, flash_smem);

    qkv_kernel<<<dim3(100, 2, 4), 256>>>(x, w, bias);
    chan_logits_kernel<<<dim3(32, 4), 256>>>();
    chan_softmax_kernel<<<4, 64>>>();
    chan_apply_kernel<<<dim3(100, 4), 256>>>(out);
    flash3_kernel<<<dim3(100, 4), 256, flash_smem>>>(out);
}

// round 6
// speedup vs baseline: 4.2194x; 3.4482x over previous
#include <cuda_runtime.h>
#include <cuda_bf16.h>
#include <math.h>
#include <stdint.h>

#define BB 4
#define CC 64
#define NN 6400

// ---------------- scratch ----------------
__device__ float g_Q [BB * NN * CC];   // [b][n][c], row n = q(h=n%80, w=n/80)
__device__ float g_V [BB * NN * CC];   // [b][m][c], row m = v(h=m%80, w=m/80)
__device__ float g_Kc[BB * NN * CC];   // [b][m][c], k natural order
__device__ float g_Lp[BB * 32 * CC * CC];
__device__ float g_ma[BB * CC * CC];
__device__ float g_qn[BB * NN];
__device__ float g_knm[BB];
// bf16 hi/lo MMA tiles, ldmatrix-swizzled: per tile 512 hi + 512 lo uint4
__device__ uint4 g_Qt[BB * 100 * 1024];  // [row64][ch64]
__device__ uint4 g_Kt[BB * 100 * 1024];  // [key64][ch64]
__device__ uint4 g_Vt[BB * 100 * 1024];  // [ch64][key64]
// split-kv partials
__device__ float g_Op[800 * 64 * 64];
__device__ float g_Od[800 * 64];

// ---------------- helpers ----------------
__device__ __forceinline__ unsigned smem_u32(const void* p) {
    unsigned a;
    asm("{ .reg .u64 t; cvta.to.shared.u64 t, %1; cvt.u32.u64 %0, t; }" : "=r"(a) : "l"(p));
    return a;
}
__device__ __forceinline__ void ldsm4(unsigned& r0, unsigned& r1, unsigned& r2, unsigned& r3, unsigned a) {
    asm volatile("ldmatrix.sync.aligned.m8n8.x4.shared.b16 {%0,%1,%2,%3}, [%4];"
                 : "=r"(r0), "=r"(r1), "=r"(r2), "=r"(r3) : "r"(a));
}
__device__ __forceinline__ void ldsm2(unsigned& r0, unsigned& r1, unsigned a) {
    asm volatile("ldmatrix.sync.aligned.m8n8.x2.shared.b16 {%0,%1}, [%2];"
                 : "=r"(r0), "=r"(r1) : "r"(a));
}
__device__ __forceinline__ void mma16816(float& c0, float& c1, float& c2, float& c3,
                                         unsigned a0, unsigned a1, unsigned a2, unsigned a3,
                                         unsigned b0, unsigned b1) {
    asm volatile("mma.sync.aligned.m16n8k16.row.col.f32.bf16.bf16.f32 "
                 "{%0,%1,%2,%3}, {%4,%5,%6,%7}, {%8,%9}, {%0,%1,%2,%3};"
                 : "+f"(c0), "+f"(c1), "+f"(c2), "+f"(c3)
                 : "r"(a0), "r"(a1), "r"(a2), "r"(a3), "r"(b0), "r"(b1));
}
__device__ __forceinline__ unsigned pk2(float lo, float hi) {  // lower half = lo
    unsigned r; asm("cvt.rn.bf16x2.f32 %0, %1, %2;" : "=r"(r) : "f"(hi), "f"(lo)); return r;
}
__device__ __forceinline__ float lo_f(unsigned h) { return __uint_as_float(h << 16); }
__device__ __forceinline__ float hi_f(unsigned h) { return __uint_as_float(h & 0xffff0000u); }
__device__ __forceinline__ float ex2f(float x) {
    float r; asm("ex2.approx.ftz.f32 %0, %1;" : "=f"(r) : "f"(x)); return r;
}
__device__ __forceinline__ void cvt8(const float* v, unsigned* hw, unsigned* lw) {
#pragma unroll
    for (int i = 0; i < 4; i++) {
        unsigned h = pk2(v[2*i], v[2*i+1]);
        hw[i] = h;
        lw[i] = pk2(v[2*i] - lo_f(h), v[2*i+1] - hi_f(h));
    }
}

// ---------------------------------------------------------------------------
// Kernel 1: 1x1 conv qkv. grid (100, 2, 4)
// ---------------------------------------------------------------------------
__global__ __launch_bounds__(256) void qkv_kernel(
    const float* __restrict__ x, const float* __restrict__ w, const float* __restrict__ bias)
{
    __shared__ float ws[64][100];
    __shared__ float xs[64][64];
    const int b = blockIdx.z, half = blockIdx.y, n0 = blockIdx.x * 64;
    const int tid = threadIdx.x, obase = half * 96;

    for (int idx = tid; idx < 96 * 64; idx += 256) {
        int o = idx >> 6, c = idx & 63;
        ws[c][o] = w[(size_t)(obase + o) * 64 + c];
    }
    for (int idx = tid; idx < 64 * 64; idx += 256) {
        int c = idx >> 6, p = idx & 63;
        xs[c][p] = x[((size_t)b * 64 + c) * NN + n0 + p];
    }
    __syncthreads();

    const int p = tid & 63, o0 = (tid >> 6) * 24;
    float acc[24];
#pragma unroll
    for (int j = 0; j < 24; j++) acc[j] = 0.f;
#pragma unroll 4
    for (int c = 0; c < 64; c++) {
        float xv = xs[c][p];
#pragma unroll
        for (int j4 = 0; j4 < 24; j4 += 4) {
            float4 wv = *(const float4*)&ws[c][o0 + j4];
            acc[j4+0] += xv * wv.x; acc[j4+1] += xv * wv.y;
            acc[j4+2] += xv * wv.z; acc[j4+3] += xv * wv.w;
        }
    }
    const int n = n0 + p, h = n / 80, wq = n % 80, nt = wq * 80 + h;
#pragma unroll
    for (int j4 = 0; j4 < 24; j4 += 4) {
        const int o = obase + o0 + j4;
        float4 v4;
        v4.x = acc[j4+0] + bias[o+0]; v4.y = acc[j4+1] + bias[o+1];
        v4.z = acc[j4+2] + bias[o+2]; v4.w = acc[j4+3] + bias[o+3];
        if (o < 64) {
            *(float4*)&g_Q[((size_t)b*NN + nt)*64 + o] = v4;
        } else if (o < 128) {
            *(float4*)&g_Kc[((size_t)b*NN + n)*64 + (o-64)] = v4;
        } else {
            *(float4*)&g_V[((size_t)b*NN + nt)*64 + (o-128)] = v4;
        }
    }
}

// ---------------------------------------------------------------------------
// row norms + max norm
// ---------------------------------------------------------------------------
__global__ void qn_kernel() {
    const int b = blockIdx.y, n = blockIdx.x * 256 + threadIdx.x;
    const float* q = g_Q + ((size_t)b * NN + n) * 64;
    float s = 0.f;
#pragma unroll
    for (int j = 0; j < 64; j += 4) {
        float4 v = *(const float4*)(q + j);
        s += v.x*v.x + v.y*v.y + v.z*v.z + v.w*v.w;
    }
    g_qn[(size_t)b * NN + n] = sqrtf(s);
}
__global__ void kmax_kernel() {
    __shared__ float red[256];
    const int b = blockIdx.x, tid = threadIdx.x;
    float m = 0.f;
    for (int n = tid; n < NN; n += 256) m = fmaxf(m, g_qn[(size_t)b * NN + n]);
    red[tid] = m; __syncthreads();
    for (int s = 128; s; s >>= 1) { if (tid < s) red[tid] = fmaxf(red[tid], red[tid+s]); __syncthreads(); }
    if (!tid) g_knm[b] = red[0];
}

// ---------------------------------------------------------------------------
// repack to bf16 hi/lo swizzled tiles. grid (100, 4), 256 thr
// Q tile [r][ch], K tile [key][ch] (key m -> g_Q[nt(m)]), V tile [ch][key]
// swizzle: 16B unit (row r, col cu) stored at cu ^ (r & 7)
// ---------------------------------------------------------------------------
__global__ __launch_bounds__(256) void repack_kernel() {
    const int kt = blockIdx.x, b = blockIdx.y, tid = threadIdx.x;
    uint4* dQ = g_Qt + (size_t)(b * 100 + kt) * 1024;
    uint4* dK = g_Kt + (size_t)(b * 100 + kt) * 1024;
    uint4* dV = g_Vt + (size_t)(b * 100 + kt) * 1024;

    for (int u = tid; u < 512; u += 256) {
        const int r = u >> 3, cu = u & 7;
        const int du = r * 8 + (cu ^ (r & 7));
        {   // Q
            const float* s = g_Q + ((size_t)b * NN + kt * 64 + r) * 64 + cu * 8;
            float v[8];
            *(float4*)v = *(const float4*)s; *(float4*)(v + 4) = *(const float4*)(s + 4);
            uint4 hw, lw; cvt8(v, (unsigned*)&hw, (unsigned*)&lw);
            dQ[du] = hw; dQ[512 + du] = lw;
        }
        {   // K: key r -> m = kt*64+r, source row nt(m)
            const int m = kt * 64 + r;
            const int nt = (m % 80) * 80 + m / 80;
            const float* s = g_Q + ((size_t)b * NN + nt) * 64 + cu * 8;
            float v[8];
            *(float4*)v = *(const float4*)s; *(float4*)(v + 4) = *(const float4*)(s + 4);
            uint4 hw, lw; cvt8(v, (unsigned*)&hw, (unsigned*)&lw);
            dK[du] = hw; dK[512 + du] = lw;
        }
        {   // V: row = ch r, keys cu*8..cu*8+7
            const float* s = g_V + ((size_t)b * NN + kt * 64 + cu * 8) * 64 + r;
            float v[8];
#pragma unroll
            for (int j = 0; j < 8; j++) v[j] = s[j * 64];
            uint4 hw, lw; cvt8(v, (unsigned*)&hw, (unsigned*)&lw);
            dV[du] = hw; dV[512 + du] = lw;
        }
    }
}

// ---------------------------------------------------------------------------
// channel attention (unchanged)
// ---------------------------------------------------------------------------
__global__ __launch_bounds__(256) void chan_logits_kernel() {
    const int b = blockIdx.y, chunk = blockIdx.x, tid = threadIdx.x;
    const int tx = tid & 15, ty = tid >> 4;
    const float* __restrict__ Kc = g_Kc + (size_t)b * NN * CC;
    const float* __restrict__ Qm = g_Q  + (size_t)b * NN * CC;
    float acc[4][4];
#pragma unroll
    for (int i = 0; i < 4; i++)
#pragma unroll
        for (int j = 0; j < 4; j++) acc[i][j] = 0.f;
    const int m0 = chunk * 200;
#pragma unroll 2
    for (int m = m0; m < m0 + 200; m++) {
        float4 kv4 = *(const float4*)(Kc + (size_t)m*64 + ty*4);
        float4 qv4 = *(const float4*)(Qm + (size_t)m*64 + tx*4);
        float kv[4] = {kv4.x, kv4.y, kv4.z, kv4.w};
        float qv[4] = {qv4.x, qv4.y, qv4.z, qv4.w};
#pragma unroll
        for (int i = 0; i < 4; i++)
#pragma unroll
            for (int j = 0; j < 4; j++) acc[i][j] += kv[i] * qv[j];
    }
    float* Lp = g_Lp + ((size_t)b*32 + chunk) * 64 * 64;
#pragma unroll
    for (int i = 0; i < 4; i++)
        *(float4*)(Lp + (size_t)(ty*4 + i)*64 + tx*4) =
            make_float4(acc[i][0], acc[i][1], acc[i][2], acc[i][3]);
}

__global__ void chan_softmax_kernel() {
    const int b = blockIdx.x, c = threadIdx.x;
    float s[64];
#pragma unroll
    for (int j = 0; j < 64; j++) s[j] = 0.f;
    for (int ch = 0; ch < 32; ch++) {
        const float* p = g_Lp + (((size_t)b*32 + ch)*64 + c)*64;
#pragma unroll
        for (int j4 = 0; j4 < 64; j4 += 4) {
            float4 v = *(const float4*)(p + j4);
            s[j4+0] += v.x; s[j4+1] += v.y; s[j4+2] += v.z; s[j4+3] += v.w;
        }
    }
    float mx = -INFINITY;
#pragma unroll
    for (int j = 0; j < 64; j++) mx = fmaxf(mx, s[j]);
    float sum = 0.f;
#pragma unroll
    for (int j = 0; j < 64; j++) { s[j] = expf(s[j] - mx); sum += s[j]; }
    const float inv = 1.f / sum;
    float* o = g_ma + ((size_t)b*64 + c)*64;
#pragma unroll
    for (int j4 = 0; j4 < 64; j4 += 4)
        *(float4*)(o + j4) = make_float4(s[j4]*inv, s[j4+1]*inv, s[j4+2]*inv, s[j4+3]*inv);
}

__global__ __launch_bounds__(256) void chan_apply_kernel(float* __restrict__ out) {
    __shared__ float vs[64][64];
    __shared__ float mas[64][65];
    const int b = blockIdx.y, n0 = blockIdx.x * 64, tid = threadIdx.x;
    const int tx = tid & 15, ty = tid >> 4;
    for (int idx = tid; idx < 4096; idx += 256) {
        int c = idx >> 6, cp = idx & 63;
        mas[cp][c] = g_ma[((size_t)b*64 + c)*64 + cp];
    }
    {
        int p = tid >> 2, cb = (tid & 3) * 16;
        int n = n0 + p, nt = (n % 80) * 80 + n / 80;
        const float* vp = g_V + ((size_t)b*NN + nt)*64 + cb;
#pragma unroll
        for (int k = 0; k < 4; k++) {
            float4 v4 = *(const float4*)(vp + 4*k);
            vs[cb+4*k+0][p] = v4.x; vs[cb+4*k+1][p] = v4.y;
            vs[cb+4*k+2][p] = v4.z; vs[cb+4*k+3][p] = v4.w;
        }
    }
    __syncthreads();
    float acc[4][4];
#pragma unroll
    for (int i = 0; i < 4; i++)
#pragma unroll
        for (int j = 0; j < 4; j++) acc[i][j] = 0.f;
#pragma unroll 4
    for (int cp = 0; cp < 64; cp++) {
        float mv[4];
#pragma unroll
        for (int i = 0; i < 4; i++) mv[i] = mas[cp][ty*4 + i];
        float4 v4 = *(const float4*)&vs[cp][tx*4];
        float vv[4] = {v4.x, v4.y, v4.z, v4.w};
#pragma unroll
        for (int i = 0; i < 4; i++)
#pragma unroll
            for (int j = 0; j < 4; j++) acc[i][j] += mv[i] * vv[j];
    }
#pragma unroll
    for (int i = 0; i < 4; i++)
        *(float4*)(out + ((size_t)b*64 + ty*4 + i)*NN + n0 + tx*4) =
            make_float4(acc[i][0], acc[i][1], acc[i][2], acc[i][3]);
}

// ---------------------------------------------------------------------------
// warp-MMA flash. grid (100 row-tiles, 2 kv-halves, 4 b), 128 thr (warp=16 rows)
// smem: Qh 0, Ql 8192, Kh 16384, Kl 24576, Vh 32768, Vl 40960 (48KB)
// ---------------------------------------------------------------------------
__global__ __launch_bounds__(128) void flash_wm() {
    __shared__ uint4 sm[3072];
    const unsigned sb = smem_u32(sm);
    const int rt = blockIdx.x, half = blockIdx.y, b = blockIdx.z;
    const int tid = threadIdx.x, warp = tid >> 5, lane = tid & 31;
    const int g = lane >> 2, t = lane & 3;
    const int n0 = rt * 64;
    const float L2E = 1.4426950408889634f;

    {   // Q tiles (hi+lo) linear copy
        const uint4* src = g_Qt + (size_t)(b * 100 + rt) * 1024;
#pragma unroll
        for (int i = 0; i < 8; i++) sm[tid + i * 128] = src[tid + i * 128];
    }
    const float knm = g_knm[b];
    const float mh1 = g_qn[(size_t)b * NN + n0 + warp * 16 + g] * knm * L2E;
    const float mh2 = g_qn[(size_t)b * NN + n0 + warp * 16 + g + 8] * knm * L2E;

    const int subA = lane >> 3, lrA = lane & 7;
    const int rA = warp * 16 + ((subA & 1) << 3) + lrA;
    const int cbA = (subA >> 1) << 4;
    const int lrB = lane & 7, subB = (lane >> 3) & 1;

    float O[8][4];
#pragma unroll
    for (int nb = 0; nb < 8; nb++)
#pragma unroll
        for (int j = 0; j < 4; j++) O[nb][j] = 0.f;
    float d1 = 0.f, d2 = 0.f;

    for (int kt = half * 50; kt < half * 50 + 50; kt++) {
        __syncthreads();
        {
            const uint4* sk = g_Kt + (size_t)(b * 100 + kt) * 1024;
            const uint4* sv = g_Vt + (size_t)(b * 100 + kt) * 1024;
#pragma unroll
            for (int i = 0; i < 8; i++) {
                sm[1024 + tid + i * 128] = sk[tid + i * 128];
                sm[2048 + tid + i * 128] = sv[tid + i * 128];
            }
        }
        __syncthreads();

        // ---- S = Q K^T (3-way bf16 split) ----
        float S[8][4];
#pragma unroll
        for (int nb = 0; nb < 8; nb++)
#pragma unroll
            for (int j = 0; j < 4; j++) S[nb][j] = 0.f;

#pragma unroll
        for (int pass = 0; pass < 3; pass++) {
            const unsigned qoff = (pass == 1) ? 8192u : 0u;
            const unsigned koff = (pass == 2) ? 24576u : 16384u;
#pragma unroll
            for (int kc = 0; kc < 4; kc++) {
                const int byteA = kc * 32 + cbA;
                unsigned a0, a1, a2, a3;
                ldsm4(a0, a1, a2, a3, sb + qoff + rA * 128 + (byteA ^ ((rA & 7) << 4)));
#pragma unroll
                for (int nb = 0; nb < 8; nb++) {
                    const int rB = nb * 8 + lrB;
                    const int byteB = kc * 32 + (subB << 4);
                    unsigned b0, b1;
                    ldsm2(b0, b1, sb + koff + rB * 128 + (byteB ^ ((rB & 7) << 4)));
                    mma16816(S[nb][0], S[nb][1], S[nb][2], S[nb][3], a0, a1, a2, a3, b0, b1);
                }
            }
        }

        // ---- exp + pack P (hi/lo) into A-fragments ----
        unsigned Ph[4][4], Pl[4][4];
#pragma unroll
        for (int nb = 0; nb < 8; nb++) {
            float e0 = ex2f(fmaf(S[nb][0], L2E, -mh1));
            float e1 = ex2f(fmaf(S[nb][1], L2E, -mh1));
            float e2 = ex2f(fmaf(S[nb][2], L2E, -mh2));
            float e3 = ex2f(fmaf(S[nb][3], L2E, -mh2));
            d1 += e0 + e1; d2 += e2 + e3;
            unsigned hA = pk2(e0, e1), hB = pk2(e2, e3);
            unsigned lA = pk2(e0 - lo_f(hA), e1 - hi_f(hA));
            unsigned lB = pk2(e2 - lo_f(hB), e3 - hi_f(hB));
            const int kc = nb >> 1, o = (nb & 1) << 1;
            Ph[kc][o] = hA; Ph[kc][o + 1] = hB;
            Pl[kc][o] = lA; Pl[kc][o + 1] = lB;
        }

        // ---- O += P V (3-way split) ----
#pragma unroll
        for (int pass = 0; pass < 3; pass++) {
            const unsigned voff = (pass == 2) ? 40960u : 32768u;
#pragma unroll
            for (int kc = 0; kc < 4; kc++) {
                const unsigned* A = (pass == 1) ? Pl[kc] : Ph[kc];
#pragma unroll
                for (int nb = 0; nb < 8; nb++) {
                    const int rB = nb * 8 + lrB;
                    const int byteB = kc * 32 + (subB << 4);
                    unsigned b0, b1;
                    ldsm2(b0, b1, sb + voff + rB * 128 + (byteB ^ ((rB & 7) << 4)));
                    mma16816(O[nb][0], O[nb][1], O[nb][2], O[nb][3],
                             A[0], A[1], A[2], A[3], b0, b1);
                }
            }
        }
    }

    // ---- epilogue: reduce denominators, store partials ----
    d1 += __shfl_xor_sync(0xffffffffu, d1, 1);
    d1 += __shfl_xor_sync(0xffffffffu, d1, 2);
    d2 += __shfl_xor_sync(0xffffffffu, d2, 1);
    d2 += __shfl_xor_sync(0xffffffffu, d2, 2);
    const int cta = (b * 2 + half) * 100 + rt;
    if (t == 0) {
        g_Od[cta * 64 + warp * 16 + g] = d1;
        g_Od[cta * 64 + warp * 16 + g + 8] = d2;
    }
    float* U = g_Op + (size_t)cta * 4096;
#pragma unroll
    for (int nb = 0; nb < 8; nb++) {
        const int ch = nb * 8 + t * 2;
        *(float2*)&U[(warp * 16 + g) * 64 + ch]     = make_float2(O[nb][0], O[nb][1]);
        *(float2*)&U[(warp * 16 + g + 8) * 64 + ch] = make_float2(O[nb][2], O[nb][3]);
    }
}

// ---------------------------------------------------------------------------
// combine halves: out += (U1+U2)/(d1+d2). grid (100, 4), 256 thr
// ---------------------------------------------------------------------------
__global__ __launch_bounds__(256) void combine_kernel(float* __restrict__ out) {
    __shared__ float sden[64];
    __shared__ float sO[64 * 65];
    const int rt = blockIdx.x, b = blockIdx.y, tid = threadIdx.x;
    const int c1 = (b * 2 + 0) * 100 + rt, c2 = (b * 2 + 1) * 100 + rt;
    if (tid < 64) sden[tid] = 1.f / (g_Od[c1 * 64 + tid] + g_Od[c2 * 64 + tid]);
    __syncthreads();
    const float* U1 = g_Op + (size_t)c1 * 4096;
    const float* U2 = g_Op + (size_t)c2 * 4096;
#pragma unroll
    for (int i = 0; i < 16; i++) {
        int idx = tid + i * 256, r = idx >> 6, c = idx & 63;
        sO[r * 65 + c] = (U1[idx] + U2[idx]) * sden[r];
    }
    __syncthreads();
    const int n0 = rt * 64;
#pragma unroll
    for (int i = 0; i < 16; i++) {
        int idx = tid + i * 256, c = idx >> 6, r = idx & 63;
        out[((size_t)b * 64 + c) * NN + n0 + r] += sO[r * 65 + c];
    }
}

// ---------------------------------------------------------------------------
extern "C" void kernel_launch(void* const* d_in, const int* in_sizes, int n_in,
                              void* d_out, int out_size)
{
    const float* x    = (const float*)d_in[0];
    const float* w    = (const float*)d_in[1];
    const float* bias = (const float*)d_in[2];
    float* out = (float*)d_out;

    qkv_kernel<<<dim3(100, 2, 4), 256>>>(x, w, bias);
    qn_kernel<<<dim3(25, 4), 256>>>();
    kmax_kernel<<<4, 256>>>();
    repack_kernel<<<dim3(100, 4), 256>>>();
    chan_logits_kernel<<<dim3(32, 4), 256>>>();
    chan_softmax_kernel<<<4, 64>>>();
    chan_apply_kernel<<<dim3(100, 4), 256>>>(out);
    flash_wm<<<dim3(100, 2, 4), 128>>>();
    combine_kernel<<<dim3(100, 4), 256>>>(out);
}

// round 7
// speedup vs baseline: 4.7317x; 1.1214x over previous
#include <cuda_runtime.h>
#include <cuda_bf16.h>
#include <math.h>
#include <stdint.h>

#define BB 4
#define CC 64
#define NN 6400

// ---------------- scratch ----------------
__device__ float g_Q [BB * NN * CC];   // [b][n][c], row n = q(h=n%80, w=n/80)
__device__ float g_V [BB * NN * CC];   // [b][m][c], row m = v(h=m%80, w=m/80)
__device__ float g_Kc[BB * NN * CC];   // [b][m][c], k natural order
__device__ float g_Lp[BB * 32 * CC * CC];
__device__ float g_ma[BB * CC * CC];
__device__ float g_qn[BB * NN];
__device__ float g_knm[BB];
// bf16 hi/lo MMA tiles, ldmatrix-swizzled: per tile 512 hi + 512 lo uint4
__device__ uint4 g_Qt[BB * 100 * 1024];  // [row64][ch64]
__device__ uint4 g_Kt[BB * 100 * 1024];  // [key64][ch64]
__device__ uint4 g_Vt[BB * 100 * 1024];  // [ch64][key64]
// split-kv partials: 800 CTAs x 128 rows x 64 ch
__device__ float g_Op[800 * 128 * 64];
__device__ float g_Od[800 * 128];

// ---------------- helpers ----------------
__device__ __forceinline__ unsigned smem_u32(const void* p) {
    unsigned a;
    asm("{ .reg .u64 t; cvta.to.shared.u64 t, %1; cvt.u32.u64 %0, t; }" : "=r"(a) : "l"(p));
    return a;
}
__device__ __forceinline__ void ldsm4(unsigned& r0, unsigned& r1, unsigned& r2, unsigned& r3, unsigned a) {
    asm volatile("ldmatrix.sync.aligned.m8n8.x4.shared.b16 {%0,%1,%2,%3}, [%4];"
                 : "=r"(r0), "=r"(r1), "=r"(r2), "=r"(r3) : "r"(a));
}
__device__ __forceinline__ void ldsm2(unsigned& r0, unsigned& r1, unsigned a) {
    asm volatile("ldmatrix.sync.aligned.m8n8.x2.shared.b16 {%0,%1}, [%2];"
                 : "=r"(r0), "=r"(r1) : "r"(a));
}
__device__ __forceinline__ void mma16816(float* c,
                                         unsigned a0, unsigned a1, unsigned a2, unsigned a3,
                                         unsigned b0, unsigned b1) {
    asm volatile("mma.sync.aligned.m16n8k16.row.col.f32.bf16.bf16.f32 "
                 "{%0,%1,%2,%3}, {%4,%5,%6,%7}, {%8,%9}, {%0,%1,%2,%3};"
                 : "+f"(c[0]), "+f"(c[1]), "+f"(c[2]), "+f"(c[3])
                 : "r"(a0), "r"(a1), "r"(a2), "r"(a3), "r"(b0), "r"(b1));
}
__device__ __forceinline__ unsigned pk2(float lo, float hi) {  // lower half = lo
    unsigned r; asm("cvt.rn.bf16x2.f32 %0, %1, %2;" : "=r"(r) : "f"(hi), "f"(lo)); return r;
}
__device__ __forceinline__ float lo_f(unsigned h) { return __uint_as_float(h << 16); }
__device__ __forceinline__ float hi_f(unsigned h) { return __uint_as_float(h & 0xffff0000u); }
__device__ __forceinline__ float ex2f(float x) {
    float r; asm("ex2.approx.ftz.f32 %0, %1;" : "=f"(r) : "f"(x)); return r;
}
__device__ __forceinline__ void cvt8(const float* v, unsigned* hw, unsigned* lw) {
#pragma unroll
    for (int i = 0; i < 4; i++) {
        unsigned h = pk2(v[2*i], v[2*i+1]);
        hw[i] = h;
        lw[i] = pk2(v[2*i] - lo_f(h), v[2*i+1] - hi_f(h));
    }
}
__device__ __forceinline__ void cpa16(unsigned d, const void* g) {
    asm volatile("cp.async.cg.shared.global [%0], [%1], 16;" :: "r"(d), "l"(g));
}
#define CP_COMMIT() asm volatile("cp.async.commit_group;" ::: "memory")
#define CP_WAIT1()  asm volatile("cp.async.wait_group 1;" ::: "memory")
#define CP_WAIT0()  asm volatile("cp.async.wait_group 0;" ::: "memory")

// ---------------------------------------------------------------------------
// Kernel 1: 1x1 conv qkv. grid (100, 2, 4)
// ---------------------------------------------------------------------------
__global__ __launch_bounds__(256) void qkv_kernel(
    const float* __restrict__ x, const float* __restrict__ w, const float* __restrict__ bias)
{
    __shared__ float ws[64][100];
    __shared__ float xs[64][64];
    const int b = blockIdx.z, half = blockIdx.y, n0 = blockIdx.x * 64;
    const int tid = threadIdx.x, obase = half * 96;

    for (int idx = tid; idx < 96 * 64; idx += 256) {
        int o = idx >> 6, c = idx & 63;
        ws[c][o] = w[(size_t)(obase + o) * 64 + c];
    }
    for (int idx = tid; idx < 64 * 64; idx += 256) {
        int c = idx >> 6, p = idx & 63;
        xs[c][p] = x[((size_t)b * 64 + c) * NN + n0 + p];
    }
    __syncthreads();

    const int p = tid & 63, o0 = (tid >> 6) * 24;
    float acc[24];
#pragma unroll
    for (int j = 0; j < 24; j++) acc[j] = 0.f;
#pragma unroll 4
    for (int c = 0; c < 64; c++) {
        float xv = xs[c][p];
#pragma unroll
        for (int j4 = 0; j4 < 24; j4 += 4) {
            float4 wv = *(const float4*)&ws[c][o0 + j4];
            acc[j4+0] += xv * wv.x; acc[j4+1] += xv * wv.y;
            acc[j4+2] += xv * wv.z; acc[j4+3] += xv * wv.w;
        }
    }
    const int n = n0 + p, h = n / 80, wq = n % 80, nt = wq * 80 + h;
#pragma unroll
    for (int j4 = 0; j4 < 24; j4 += 4) {
        const int o = obase + o0 + j4;
        float4 v4;
        v4.x = acc[j4+0] + bias[o+0]; v4.y = acc[j4+1] + bias[o+1];
        v4.z = acc[j4+2] + bias[o+2]; v4.w = acc[j4+3] + bias[o+3];
        if (o < 64) {
            *(float4*)&g_Q[((size_t)b*NN + nt)*64 + o] = v4;
        } else if (o < 128) {
            *(float4*)&g_Kc[((size_t)b*NN + n)*64 + (o-64)] = v4;
        } else {
            *(float4*)&g_V[((size_t)b*NN + nt)*64 + (o-128)] = v4;
        }
    }
}

// ---------------------------------------------------------------------------
// row norms + max norm
// ---------------------------------------------------------------------------
__global__ void qn_kernel() {
    const int b = blockIdx.y, n = blockIdx.x * 256 + threadIdx.x;
    const float* q = g_Q + ((size_t)b * NN + n) * 64;
    float s = 0.f;
#pragma unroll
    for (int j = 0; j < 64; j += 4) {
        float4 v = *(const float4*)(q + j);
        s += v.x*v.x + v.y*v.y + v.z*v.z + v.w*v.w;
    }
    g_qn[(size_t)b * NN + n] = sqrtf(s);
}
__global__ void kmax_kernel() {
    __shared__ float red[256];
    const int b = blockIdx.x, tid = threadIdx.x;
    float m = 0.f;
    for (int n = tid; n < NN; n += 256) m = fmaxf(m, g_qn[(size_t)b * NN + n]);
    red[tid] = m; __syncthreads();
    for (int s = 128; s; s >>= 1) { if (tid < s) red[tid] = fmaxf(red[tid], red[tid+s]); __syncthreads(); }
    if (!tid) g_knm[b] = red[0];
}

// ---------------------------------------------------------------------------
// repack to bf16 hi/lo swizzled tiles. grid (100, 4), 256 thr
// ---------------------------------------------------------------------------
__global__ __launch_bounds__(256) void repack_kernel() {
    const int kt = blockIdx.x, b = blockIdx.y, tid = threadIdx.x;
    uint4* dQ = g_Qt + (size_t)(b * 100 + kt) * 1024;
    uint4* dK = g_Kt + (size_t)(b * 100 + kt) * 1024;
    uint4* dV = g_Vt + (size_t)(b * 100 + kt) * 1024;

    for (int u = tid; u < 512; u += 256) {
        const int r = u >> 3, cu = u & 7;
        const int du = r * 8 + (cu ^ (r & 7));
        {   // Q
            const float* s = g_Q + ((size_t)b * NN + kt * 64 + r) * 64 + cu * 8;
            float v[8];
            *(float4*)v = *(const float4*)s; *(float4*)(v + 4) = *(const float4*)(s + 4);
            uint4 hw, lw; cvt8(v, (unsigned*)&hw, (unsigned*)&lw);
            dQ[du] = hw; dQ[512 + du] = lw;
        }
        {   // K: key r -> m = kt*64+r, source row nt(m)
            const int m = kt * 64 + r;
            const int nt = (m % 80) * 80 + m / 80;
            const float* s = g_Q + ((size_t)b * NN + nt) * 64 + cu * 8;
            float v[8];
            *(float4*)v = *(const float4*)s; *(float4*)(v + 4) = *(const float4*)(s + 4);
            uint4 hw, lw; cvt8(v, (unsigned*)&hw, (unsigned*)&lw);
            dK[du] = hw; dK[512 + du] = lw;
        }
        {   // V: row = ch r, keys cu*8..cu*8+7
            const float* s = g_V + ((size_t)b * NN + kt * 64 + cu * 8) * 64 + r;
            float v[8];
#pragma unroll
            for (int j = 0; j < 8; j++) v[j] = s[j * 64];
            uint4 hw, lw; cvt8(v, (unsigned*)&hw, (unsigned*)&lw);
            dV[du] = hw; dV[512 + du] = lw;
        }
    }
}

// ---------------------------------------------------------------------------
// channel attention (unchanged)
// ---------------------------------------------------------------------------
__global__ __launch_bounds__(256) void chan_logits_kernel() {
    const int b = blockIdx.y, chunk = blockIdx.x, tid = threadIdx.x;
    const int tx = tid & 15, ty = tid >> 4;
    const float* __restrict__ Kc = g_Kc + (size_t)b * NN * CC;
    const float* __restrict__ Qm = g_Q  + (size_t)b * NN * CC;
    float acc[4][4];
#pragma unroll
    for (int i = 0; i < 4; i++)
#pragma unroll
        for (int j = 0; j < 4; j++) acc[i][j] = 0.f;
    const int m0 = chunk * 200;
#pragma unroll 2
    for (int m = m0; m < m0 + 200; m++) {
        float4 kv4 = *(const float4*)(Kc + (size_t)m*64 + ty*4);
        float4 qv4 = *(const float4*)(Qm + (size_t)m*64 + tx*4);
        float kv[4] = {kv4.x, kv4.y, kv4.z, kv4.w};
        float qv[4] = {qv4.x, qv4.y, qv4.z, qv4.w};
#pragma unroll
        for (int i = 0; i < 4; i++)
#pragma unroll
            for (int j = 0; j < 4; j++) acc[i][j] += kv[i] * qv[j];
    }
    float* Lp = g_Lp + ((size_t)b*32 + chunk) * 64 * 64;
#pragma unroll
    for (int i = 0; i < 4; i++)
        *(float4*)(Lp + (size_t)(ty*4 + i)*64 + tx*4) =
            make_float4(acc[i][0], acc[i][1], acc[i][2], acc[i][3]);
}

__global__ void chan_softmax_kernel() {
    const int b = blockIdx.x, c = threadIdx.x;
    float s[64];
#pragma unroll
    for (int j = 0; j < 64; j++) s[j] = 0.f;
    for (int ch = 0; ch < 32; ch++) {
        const float* p = g_Lp + (((size_t)b*32 + ch)*64 + c)*64;
#pragma unroll
        for (int j4 = 0; j4 < 64; j4 += 4) {
            float4 v = *(const float4*)(p + j4);
            s[j4+0] += v.x; s[j4+1] += v.y; s[j4+2] += v.z; s[j4+3] += v.w;
        }
    }
    float mx = -INFINITY;
#pragma unroll
    for (int j = 0; j < 64; j++) mx = fmaxf(mx, s[j]);
    float sum = 0.f;
#pragma unroll
    for (int j = 0; j < 64; j++) { s[j] = expf(s[j] - mx); sum += s[j]; }
    const float inv = 1.f / sum;
    float* o = g_ma + ((size_t)b*64 + c)*64;
#pragma unroll
    for (int j4 = 0; j4 < 64; j4 += 4)
        *(float4*)(o + j4) = make_float4(s[j4]*inv, s[j4+1]*inv, s[j4+2]*inv, s[j4+3]*inv);
}

__global__ __launch_bounds__(256) void chan_apply_kernel(float* __restrict__ out) {
    __shared__ float vs[64][64];
    __shared__ float mas[64][65];
    const int b = blockIdx.y, n0 = blockIdx.x * 64, tid = threadIdx.x;
    const int tx = tid & 15, ty = tid >> 4;
    for (int idx = tid; idx < 4096; idx += 256) {
        int c = idx >> 6, cp = idx & 63;
        mas[cp][c] = g_ma[((size_t)b*64 + c)*64 + cp];
    }
    {
        int p = tid >> 2, cb = (tid & 3) * 16;
        int n = n0 + p, nt = (n % 80) * 80 + n / 80;
        const float* vp = g_V + ((size_t)b*NN + nt)*64 + cb;
#pragma unroll
        for (int k = 0; k < 4; k++) {
            float4 v4 = *(const float4*)(vp + 4*k);
            vs[cb+4*k+0][p] = v4.x; vs[cb+4*k+1][p] = v4.y;
            vs[cb+4*k+2][p] = v4.z; vs[cb+4*k+3][p] = v4.w;
        }
    }
    __syncthreads();
    float acc[4][4];
#pragma unroll
    for (int i = 0; i < 4; i++)
#pragma unroll
        for (int j = 0; j < 4; j++) acc[i][j] = 0.f;
#pragma unroll 4
    for (int cp = 0; cp < 64; cp++) {
        float mv[4];
#pragma unroll
        for (int i = 0; i < 4; i++) mv[i] = mas[cp][ty*4 + i];
        float4 v4 = *(const float4*)&vs[cp][tx*4];
        float vv[4] = {v4.x, v4.y, v4.z, v4.w};
#pragma unroll
        for (int i = 0; i < 4; i++)
#pragma unroll
            for (int j = 0; j < 4; j++) acc[i][j] += mv[i] * vv[j];
    }
#pragma unroll
    for (int i = 0; i < 4; i++)
        *(float4*)(out + ((size_t)b*64 + ty*4 + i)*NN + n0 + tx*4) =
            make_float4(acc[i][0], acc[i][1], acc[i][2], acc[i][3]);
}

// ---------------------------------------------------------------------------
// warp-MMA flash v2. grid (50 row-tiles, 4 kv-quarters, 4 b), 256 thr.
// 128 rows/CTA (warp=16 rows), 25 key-tiles of 64, cp.async 2-stage K/V.
// smem (96KB dyn): Qh 0, Ql 16K, K[2] at 32K+16K*s (hi+8K lo), V[2] at 64K+16K*s
// ---------------------------------------------------------------------------
__global__ __launch_bounds__(256, 2) void flash_wm2() {
    extern __shared__ char smc[];
    const unsigned sb = smem_u32(smc);
    const int rt = blockIdx.x, quarter = blockIdx.y, b = blockIdx.z;
    const int tid = threadIdx.x, warp = tid >> 5, lane = tid & 31;
    const int g = lane >> 2, t = lane & 3;
    const int n0 = rt * 128;
    const int kt0 = quarter * 25;
    const float L2E = 1.4426950408889634f;

    // ---- stage-0 K/V prefetch (cp.async) ----
    {
        const uint4* sk = g_Kt + (size_t)(b * 100 + kt0) * 1024;
        const uint4* sv = g_Vt + (size_t)(b * 100 + kt0) * 1024;
#pragma unroll
        for (int j = 0; j < 4; j++) {
            int i = tid + j * 256;
            cpa16(sb + 32768u + i * 16, sk + i);
            cpa16(sb + 65536u + i * 16, sv + i);
        }
        CP_COMMIT();
    }
    // ---- Q tiles (2 x 64 rows) plain copy ----
    {
        uint4* dh = (uint4*)smc;
        uint4* dl = (uint4*)(smc + 16384);
#pragma unroll
        for (int j = 0; j < 2; j++) {
            const uint4* src = g_Qt + (size_t)(b * 100 + rt * 2 + j) * 1024;
#pragma unroll
            for (int i = 0; i < 2; i++) {
                int u = tid + i * 256;
                dh[j * 512 + u] = src[u];
                dl[j * 512 + u] = src[512 + u];
            }
        }
    }
    const float knm = g_knm[b];
    const float mh1 = g_qn[(size_t)b * NN + n0 + warp * 16 + g] * knm * L2E;
    const float mh2 = g_qn[(size_t)b * NN + n0 + warp * 16 + g + 8] * knm * L2E;

    const int subA = lane >> 3, lrA = lane & 7;
    const int rA = warp * 16 + ((subA & 1) << 3) + lrA;
    const int cbA = (subA >> 1) << 4;
    const int lrB = lane & 7, subB = (lane >> 3) & 1;

    float O[8][4];
#pragma unroll
    for (int nb = 0; nb < 8; nb++)
#pragma unroll
        for (int j = 0; j < 4; j++) O[nb][j] = 0.f;
    float d1 = 0.f, d2 = 0.f;

    for (int it = 0; it < 25; it++) {
        const unsigned koff = 32768u + (unsigned)(it & 1) * 16384u;
        const unsigned voff = 65536u + (unsigned)(it & 1) * 16384u;
        __syncthreads();   // all warps done reading prior buffers
        if (it + 1 < 25) { // prefetch next stage
            const uint4* sk = g_Kt + (size_t)(b * 100 + kt0 + it + 1) * 1024;
            const uint4* sv = g_Vt + (size_t)(b * 100 + kt0 + it + 1) * 1024;
            const unsigned nk = 32768u + (unsigned)((it + 1) & 1) * 16384u;
            const unsigned nv = 65536u + (unsigned)((it + 1) & 1) * 16384u;
#pragma unroll
            for (int j = 0; j < 4; j++) {
                int i = tid + j * 256;
                cpa16(nk + sb + i * 16, sk + i);
                cpa16(nv + sb + i * 16, sv + i);
            }
            CP_COMMIT();
            CP_WAIT1();
        } else {
            CP_WAIT0();
        }
        __syncthreads();   // stage data visible to all warps

        // ---- S = Q K^T (3-way bf16 split, fragment reuse) ----
        float S[8][4];
#pragma unroll
        for (int nb = 0; nb < 8; nb++)
#pragma unroll
            for (int j = 0; j < 4; j++) S[nb][j] = 0.f;

#pragma unroll
        for (int kc = 0; kc < 4; kc++) {
            const int byteA = kc * 32 + cbA;
            const unsigned aswz = (unsigned)(byteA ^ ((rA & 7) << 4));
            unsigned qh0, qh1, qh2, qh3, ql0, ql1, ql2, ql3;
            ldsm4(qh0, qh1, qh2, qh3, sb + 0u     + rA * 128 + aswz);
            ldsm4(ql0, ql1, ql2, ql3, sb + 16384u + rA * 128 + aswz);
#pragma unroll
            for (int nb = 0; nb < 8; nb++) {
                const int rB = nb * 8 + lrB;
                const unsigned bswz = (unsigned)((kc * 32 + (subB << 4)) ^ ((rB & 7) << 4));
                unsigned kh0, kh1, kl0, kl1;
                ldsm2(kh0, kh1, sb + koff + rB * 128 + bswz);
                ldsm2(kl0, kl1, sb + koff + 8192u + rB * 128 + bswz);
                mma16816(S[nb], qh0, qh1, qh2, qh3, kh0, kh1);
                mma16816(S[nb], ql0, ql1, ql2, ql3, kh0, kh1);
                mma16816(S[nb], qh0, qh1, qh2, qh3, kl0, kl1);
            }
        }

        // ---- exp + pack P (hi/lo) into A-fragments ----
        unsigned Ph[4][4], Pl[4][4];
#pragma unroll
        for (int nb = 0; nb < 8; nb++) {
            float e0 = ex2f(fmaf(S[nb][0], L2E, -mh1));
            float e1 = ex2f(fmaf(S[nb][1], L2E, -mh1));
            float e2 = ex2f(fmaf(S[nb][2], L2E, -mh2));
            float e3 = ex2f(fmaf(S[nb][3], L2E, -mh2));
            d1 += e0 + e1; d2 += e2 + e3;
            unsigned hA = pk2(e0, e1), hB = pk2(e2, e3);
            unsigned lA = pk2(e0 - lo_f(hA), e1 - hi_f(hA));
            unsigned lB = pk2(e2 - lo_f(hB), e3 - hi_f(hB));
            const int kc = nb >> 1, o = (nb & 1) << 1;
            Ph[kc][o] = hA; Ph[kc][o + 1] = hB;
            Pl[kc][o] = lA; Pl[kc][o + 1] = lB;
        }

        // ---- O += P V (3-way split, Vh reused) ----
#pragma unroll
        for (int kc = 0; kc < 4; kc++) {
#pragma unroll
            for (int nb = 0; nb < 8; nb++) {
                const int rB = nb * 8 + lrB;
                const unsigned bswz = (unsigned)((kc * 32 + (subB << 4)) ^ ((rB & 7) << 4));
                unsigned vh0, vh1, vl0, vl1;
                ldsm2(vh0, vh1, sb + voff + rB * 128 + bswz);
                ldsm2(vl0, vl1, sb + voff + 8192u + rB * 128 + bswz);
                mma16816(O[nb], Ph[kc][0], Ph[kc][1], Ph[kc][2], Ph[kc][3], vh0, vh1);
                mma16816(O[nb], Pl[kc][0], Pl[kc][1], Pl[kc][2], Pl[kc][3], vh0, vh1);
                mma16816(O[nb], Ph[kc][0], Ph[kc][1], Ph[kc][2], Ph[kc][3], vl0, vl1);
            }
        }
    }

    // ---- epilogue: reduce denominators, store partials ----
    d1 += __shfl_xor_sync(0xffffffffu, d1, 1);
    d1 += __shfl_xor_sync(0xffffffffu, d1, 2);
    d2 += __shfl_xor_sync(0xffffffffu, d2, 1);
    d2 += __shfl_xor_sync(0xffffffffu, d2, 2);
    const int cta = (b * 4 + quarter) * 50 + rt;
    if (t == 0) {
        g_Od[cta * 128 + warp * 16 + g] = d1;
        g_Od[cta * 128 + warp * 16 + g + 8] = d2;
    }
    float* U = g_Op + (size_t)cta * 8192;
#pragma unroll
    for (int nb = 0; nb < 8; nb++) {
        const int ch = nb * 8 + t * 2;
        *(float2*)&U[(warp * 16 + g) * 64 + ch]     = make_float2(O[nb][0], O[nb][1]);
        *(float2*)&U[(warp * 16 + g + 8) * 64 + ch] = make_float2(O[nb][2], O[nb][3]);
    }
}

// ---------------------------------------------------------------------------
// combine quarters: out += (sum_q U_q) / (sum_q d_q). grid (100, 4), 256 thr
// ---------------------------------------------------------------------------
__global__ __launch_bounds__(256) void combine_kernel(float* __restrict__ out) {
    __shared__ float sden[64];
    __shared__ float sO[64 * 65];
    const int rt64 = blockIdx.x, b = blockIdx.y, tid = threadIdx.x;
    const int rtb = rt64 >> 1, ro = (rt64 & 1) * 64;
    int c_q[4];
#pragma unroll
    for (int q = 0; q < 4; q++) c_q[q] = (b * 4 + q) * 50 + rtb;

    if (tid < 64) {
        float s = 0.f;
#pragma unroll
        for (int q = 0; q < 4; q++) s += g_Od[c_q[q] * 128 + ro + tid];
        sden[tid] = 1.f / s;
    }
    __syncthreads();
#pragma unroll
    for (int i = 0; i < 16; i++) {
        int idx = tid + i * 256, r = idx >> 6, c = idx & 63;
        float s = 0.f;
#pragma unroll
        for (int q = 0; q < 4; q++)
            s += g_Op[(size_t)c_q[q] * 8192 + (ro + r) * 64 + c];
        sO[r * 65 + c] = s * sden[r];
    }
    __syncthreads();
    const int n0 = rt64 * 64;
#pragma unroll
    for (int i = 0; i < 16; i++) {
        int idx = tid + i * 256, c = idx >> 6, r = idx & 63;
        out[((size_t)b * 64 + c) * NN + n0 + r] += sO[r * 65 + c];
    }
}

// ---------------------------------------------------------------------------
extern "C" void kernel_launch(void* const* d_in, const int* in_sizes, int n_in,
                              void* d_out, int out_size)
{
    const float* x    = (const float*)d_in[0];
    const float* w    = (const float*)d_in[1];
    const float* bias = (const float*)d_in[2];
    float* out = (float*)d_out;

    const int fsm = 98304;
    cudaFuncSetAttribute(flash_wm2, cudaFuncAttributeMaxDynamicSharedMemorySize, fsm);

    qkv_kernel<<<dim3(100, 2, 4), 256>>>(x, w, bias);
    qn_kernel<<<dim3(25, 4), 256>>>();
    kmax_kernel<<<4, 256>>>();
    repack_kernel<<<dim3(100, 4), 256>>>();
    chan_logits_kernel<<<dim3(32, 4), 256>>>();
    chan_softmax_kernel<<<4, 64>>>();
    chan_apply_kernel<<<dim3(100, 4), 256>>>(out);
    flash_wm2<<<dim3(50, 4, 4), 256, fsm>>>();
    combine_kernel<<<dim3(100, 4), 256>>>(out);
}

// round 8
// speedup vs baseline: 5.0732x; 1.0722x over previous
#include <cuda_runtime.h>
#include <cuda_bf16.h>
#include <cuda_fp16.h>
#include <math.h>
#include <stdint.h>

#define BB 4
#define CC 64
#define NN 6400

// ---------------- scratch ----------------
__device__ float g_Q [BB * NN * CC];   // [b][n][c], row n = q(h=n%80, w=n/80)
__device__ float g_V [BB * NN * CC];   // [b][m][c], row m = v(h=m%80, w=m/80)
__device__ float g_Kc[BB * NN * CC];   // [b][m][c], k natural order
__device__ float g_Lp[BB * 32 * CC * CC];
__device__ float g_ma[BB * CC * CC];
// MMA tiles, ldmatrix-swizzled
__device__ uint4 g_Qt[BB * 100 * 1024];  // bf16 hi(512)+lo(512): [row64][ch64]
__device__ uint4 g_Kt[BB * 100 * 1024];  // bf16 hi+lo: [key64][ch64]
__device__ uint4 g_Vt[BB * 100 * 512];   // fp16 single: [ch64][key64]
// split-kv partials: 800 CTAs x 128 rows
__device__ float g_Op[800 * 128 * 64];
__device__ float g_Od[800 * 128];
__device__ float g_Om[800 * 128];

// ---------------- helpers ----------------
__device__ __forceinline__ unsigned smem_u32(const void* p) {
    unsigned a;
    asm("{ .reg .u64 t; cvta.to.shared.u64 t, %1; cvt.u32.u64 %0, t; }" : "=r"(a) : "l"(p));
    return a;
}
__device__ __forceinline__ void ldsm4(unsigned& r0, unsigned& r1, unsigned& r2, unsigned& r3, unsigned a) {
    asm volatile("ldmatrix.sync.aligned.m8n8.x4.shared.b16 {%0,%1,%2,%3}, [%4];"
                 : "=r"(r0), "=r"(r1), "=r"(r2), "=r"(r3) : "r"(a));
}
__device__ __forceinline__ void mma_bf(float* c,
                                       unsigned a0, unsigned a1, unsigned a2, unsigned a3,
                                       unsigned b0, unsigned b1) {
    asm volatile("mma.sync.aligned.m16n8k16.row.col.f32.bf16.bf16.f32 "
                 "{%0,%1,%2,%3}, {%4,%5,%6,%7}, {%8,%9}, {%0,%1,%2,%3};"
                 : "+f"(c[0]), "+f"(c[1]), "+f"(c[2]), "+f"(c[3])
                 : "r"(a0), "r"(a1), "r"(a2), "r"(a3), "r"(b0), "r"(b1));
}
__device__ __forceinline__ void mma_h(float* c,
                                      unsigned a0, unsigned a1, unsigned a2, unsigned a3,
                                      unsigned b0, unsigned b1) {
    asm volatile("mma.sync.aligned.m16n8k16.row.col.f32.f16.f16.f32 "
                 "{%0,%1,%2,%3}, {%4,%5,%6,%7}, {%8,%9}, {%0,%1,%2,%3};"
                 : "+f"(c[0]), "+f"(c[1]), "+f"(c[2]), "+f"(c[3])
                 : "r"(a0), "r"(a1), "r"(a2), "r"(a3), "r"(b0), "r"(b1));
}
__device__ __forceinline__ unsigned pk2(float lo, float hi) {  // bf16x2, lower = lo
    unsigned r; asm("cvt.rn.bf16x2.f32 %0, %1, %2;" : "=r"(r) : "f"(hi), "f"(lo)); return r;
}
__device__ __forceinline__ unsigned pk2h(float lo, float hi) { // f16x2, lower = lo
    unsigned r; asm("cvt.rn.f16x2.f32 %0, %1, %2;" : "=r"(r) : "f"(hi), "f"(lo)); return r;
}
__device__ __forceinline__ float lo_f(unsigned h) { return __uint_as_float(h << 16); }
__device__ __forceinline__ float hi_f(unsigned h) { return __uint_as_float(h & 0xffff0000u); }
__device__ __forceinline__ float lo_h(unsigned u) {
    __half2 h = *reinterpret_cast<__half2*>(&u); return __low2float(h);
}
__device__ __forceinline__ float hi_h(unsigned u) {
    __half2 h = *reinterpret_cast<__half2*>(&u); return __high2float(h);
}
__device__ __forceinline__ float ex2f(float x) {
    float r; asm("ex2.approx.ftz.f32 %0, %1;" : "=f"(r) : "f"(x)); return r;
}
__device__ __forceinline__ void cvt8(const float* v, unsigned* hw, unsigned* lw) {
#pragma unroll
    for (int i = 0; i < 4; i++) {
        unsigned h = pk2(v[2*i], v[2*i+1]);
        hw[i] = h;
        lw[i] = pk2(v[2*i] - lo_f(h), v[2*i+1] - hi_f(h));
    }
}
__device__ __forceinline__ void cpa16(unsigned d, const void* g) {
    asm volatile("cp.async.cg.shared.global [%0], [%1], 16;" :: "r"(d), "l"(g));
}
#define CP_COMMIT() asm volatile("cp.async.commit_group;" ::: "memory")
#define CP_WAIT1()  asm volatile("cp.async.wait_group 1;" ::: "memory")
#define CP_WAIT0()  asm volatile("cp.async.wait_group 0;" ::: "memory")

// ---------------------------------------------------------------------------
// Kernel 1: 1x1 conv qkv. grid (100, 2, 4)
// ---------------------------------------------------------------------------
__global__ __launch_bounds__(256) void qkv_kernel(
    const float* __restrict__ x, const float* __restrict__ w, const float* __restrict__ bias)
{
    __shared__ float ws[64][100];
    __shared__ float xs[64][64];
    const int b = blockIdx.z, half = blockIdx.y, n0 = blockIdx.x * 64;
    const int tid = threadIdx.x, obase = half * 96;

    for (int idx = tid; idx < 96 * 64; idx += 256) {
        int o = idx >> 6, c = idx & 63;
        ws[c][o] = w[(size_t)(obase + o) * 64 + c];
    }
    for (int idx = tid; idx < 64 * 64; idx += 256) {
        int c = idx >> 6, p = idx & 63;
        xs[c][p] = x[((size_t)b * 64 + c) * NN + n0 + p];
    }
    __syncthreads();

    const int p = tid & 63, o0 = (tid >> 6) * 24;
    float acc[24];
#pragma unroll
    for (int j = 0; j < 24; j++) acc[j] = 0.f;
#pragma unroll 4
    for (int c = 0; c < 64; c++) {
        float xv = xs[c][p];
#pragma unroll
        for (int j4 = 0; j4 < 24; j4 += 4) {
            float4 wv = *(const float4*)&ws[c][o0 + j4];
            acc[j4+0] += xv * wv.x; acc[j4+1] += xv * wv.y;
            acc[j4+2] += xv * wv.z; acc[j4+3] += xv * wv.w;
        }
    }
    const int n = n0 + p, h = n / 80, wq = n % 80, nt = wq * 80 + h;
#pragma unroll
    for (int j4 = 0; j4 < 24; j4 += 4) {
        const int o = obase + o0 + j4;
        float4 v4;
        v4.x = acc[j4+0] + bias[o+0]; v4.y = acc[j4+1] + bias[o+1];
        v4.z = acc[j4+2] + bias[o+2]; v4.w = acc[j4+3] + bias[o+3];
        if (o < 64) {
            *(float4*)&g_Q[((size_t)b*NN + nt)*64 + o] = v4;
        } else if (o < 128) {
            *(float4*)&g_Kc[((size_t)b*NN + n)*64 + (o-64)] = v4;
        } else {
            *(float4*)&g_V[((size_t)b*NN + nt)*64 + (o-128)] = v4;
        }
    }
}

// ---------------------------------------------------------------------------
// repack: Q/K bf16 hi/lo, V fp16 single; ldmatrix-swizzled. grid (100, 4)
// ---------------------------------------------------------------------------
__global__ __launch_bounds__(256) void repack_kernel() {
    const int kt = blockIdx.x, b = blockIdx.y, tid = threadIdx.x;
    uint4* dQ = g_Qt + (size_t)(b * 100 + kt) * 1024;
    uint4* dK = g_Kt + (size_t)(b * 100 + kt) * 1024;
    uint4* dV = g_Vt + (size_t)(b * 100 + kt) * 512;

    for (int u = tid; u < 512; u += 256) {
        const int r = u >> 3, cu = u & 7;
        const int du = r * 8 + (cu ^ (r & 7));
        {   // Q
            const float* s = g_Q + ((size_t)b * NN + kt * 64 + r) * 64 + cu * 8;
            float v[8];
            *(float4*)v = *(const float4*)s; *(float4*)(v + 4) = *(const float4*)(s + 4);
            uint4 hw, lw; cvt8(v, (unsigned*)&hw, (unsigned*)&lw);
            dQ[du] = hw; dQ[512 + du] = lw;
        }
        {   // K: key r -> m = kt*64+r, source row nt(m)
            const int m = kt * 64 + r;
            const int nt = (m % 80) * 80 + m / 80;
            const float* s = g_Q + ((size_t)b * NN + nt) * 64 + cu * 8;
            float v[8];
            *(float4*)v = *(const float4*)s; *(float4*)(v + 4) = *(const float4*)(s + 4);
            uint4 hw, lw; cvt8(v, (unsigned*)&hw, (unsigned*)&lw);
            dK[du] = hw; dK[512 + du] = lw;
        }
        {   // V fp16: row = ch r, keys cu*8..cu*8+7
            const float* s = g_V + ((size_t)b * NN + kt * 64 + cu * 8) * 64 + r;
            float v[8];
#pragma unroll
            for (int j = 0; j < 8; j++) v[j] = s[j * 64];
            uint4 hw; unsigned* hww = (unsigned*)&hw;
#pragma unroll
            for (int i = 0; i < 4; i++) hww[i] = pk2h(v[2*i], v[2*i+1]);
            dV[du] = hw;
        }
    }
}

// ---------------------------------------------------------------------------
// channel attention (unchanged)
// ---------------------------------------------------------------------------
__global__ __launch_bounds__(256) void chan_logits_kernel() {
    const int b = blockIdx.y, chunk = blockIdx.x, tid = threadIdx.x;
    const int tx = tid & 15, ty = tid >> 4;
    const float* __restrict__ Kc = g_Kc + (size_t)b * NN * CC;
    const float* __restrict__ Qm = g_Q  + (size_t)b * NN * CC;
    float acc[4][4];
#pragma unroll
    for (int i = 0; i < 4; i++)
#pragma unroll
        for (int j = 0; j < 4; j++) acc[i][j] = 0.f;
    const int m0 = chunk * 200;
#pragma unroll 2
    for (int m = m0; m < m0 + 200; m++) {
        float4 kv4 = *(const float4*)(Kc + (size_t)m*64 + ty*4);
        float4 qv4 = *(const float4*)(Qm + (size_t)m*64 + tx*4);
        float kv[4] = {kv4.x, kv4.y, kv4.z, kv4.w};
        float qv[4] = {qv4.x, qv4.y, qv4.z, qv4.w};
#pragma unroll
        for (int i = 0; i < 4; i++)
#pragma unroll
            for (int j = 0; j < 4; j++) acc[i][j] += kv[i] * qv[j];
    }
    float* Lp = g_Lp + ((size_t)b*32 + chunk) * 64 * 64;
#pragma unroll
    for (int i = 0; i < 4; i++)
        *(float4*)(Lp + (size_t)(ty*4 + i)*64 + tx*4) =
            make_float4(acc[i][0], acc[i][1], acc[i][2], acc[i][3]);
}

__global__ void chan_softmax_kernel() {
    const int b = blockIdx.x, c = threadIdx.x;
    float s[64];
#pragma unroll
    for (int j = 0; j < 64; j++) s[j] = 0.f;
    for (int ch = 0; ch < 32; ch++) {
        const float* p = g_Lp + (((size_t)b*32 + ch)*64 + c)*64;
#pragma unroll
        for (int j4 = 0; j4 < 64; j4 += 4) {
            float4 v = *(const float4*)(p + j4);
            s[j4+0] += v.x; s[j4+1] += v.y; s[j4+2] += v.z; s[j4+3] += v.w;
        }
    }
    float mx = -INFINITY;
#pragma unroll
    for (int j = 0; j < 64; j++) mx = fmaxf(mx, s[j]);
    float sum = 0.f;
#pragma unroll
    for (int j = 0; j < 64; j++) { s[j] = expf(s[j] - mx); sum += s[j]; }
    const float inv = 1.f / sum;
    float* o = g_ma + ((size_t)b*64 + c)*64;
#pragma unroll
    for (int j4 = 0; j4 < 64; j4 += 4)
        *(float4*)(o + j4) = make_float4(s[j4]*inv, s[j4+1]*inv, s[j4+2]*inv, s[j4+3]*inv);
}

__global__ __launch_bounds__(256) void chan_apply_kernel(float* __restrict__ out) {
    __shared__ float vs[64][64];
    __shared__ float mas[64][65];
    const int b = blockIdx.y, n0 = blockIdx.x * 64, tid = threadIdx.x;
    const int tx = tid & 15, ty = tid >> 4;
    for (int idx = tid; idx < 4096; idx += 256) {
        int c = idx >> 6, cp = idx & 63;
        mas[cp][c] = g_ma[((size_t)b*64 + c)*64 + cp];
    }
    {
        int p = tid >> 2, cb = (tid & 3) * 16;
        int n = n0 + p, nt = (n % 80) * 80 + n / 80;
        const float* vp = g_V + ((size_t)b*NN + nt)*64 + cb;
#pragma unroll
        for (int k = 0; k < 4; k++) {
            float4 v4 = *(const float4*)(vp + 4*k);
            vs[cb+4*k+0][p] = v4.x; vs[cb+4*k+1][p] = v4.y;
            vs[cb+4*k+2][p] = v4.z; vs[cb+4*k+3][p] = v4.w;
        }
    }
    __syncthreads();
    float acc[4][4];
#pragma unroll
    for (int i = 0; i < 4; i++)
#pragma unroll
        for (int j = 0; j < 4; j++) acc[i][j] = 0.f;
#pragma unroll 4
    for (int cp = 0; cp < 64; cp++) {
        float mv[4];
#pragma unroll
        for (int i = 0; i < 4; i++) mv[i] = mas[cp][ty*4 + i];
        float4 v4 = *(const float4*)&vs[cp][tx*4];
        float vv[4] = {v4.x, v4.y, v4.z, v4.w};
#pragma unroll
        for (int i = 0; i < 4; i++)
#pragma unroll
            for (int j = 0; j < 4; j++) acc[i][j] += mv[i] * vv[j];
    }
#pragma unroll
    for (int i = 0; i < 4; i++)
        *(float4*)(out + ((size_t)b*64 + ty*4 + i)*NN + n0 + tx*4) =
            make_float4(acc[i][0], acc[i][1], acc[i][2], acc[i][3]);
}

// ---------------------------------------------------------------------------
// warp-MMA flash v3: online softmax, fp16 2-pass O-phase, ldsm.x4 B-loads.
// grid (50, 4, 4), 256 thr, 128 rows/CTA, 25 key-tiles, 2-stage cp.async.
// smem (80KB): Qh 0, Ql 16K; stage s at 32K + s*24K: Kh(8K) Kl(8K) Vf16(8K)
// ---------------------------------------------------------------------------
__global__ __launch_bounds__(256, 2) void flash_wm3() {
    extern __shared__ char smc[];
    const unsigned sb = smem_u32(smc);
    const int rt = blockIdx.x, quarter = blockIdx.y, b = blockIdx.z;
    const int tid = threadIdx.x, warp = tid >> 5, lane = tid & 31;
    const int g = lane >> 2, t = lane & 3;
    const int n0 = rt * 128, kt0 = quarter * 25;
    const float L2E = 1.4426950408889634f;

    // ---- stage-0 prefetch ----
    {
        const uint4* sk = g_Kt + (size_t)(b * 100 + kt0) * 1024;
        const uint4* sv = g_Vt + (size_t)(b * 100 + kt0) * 512;
        const unsigned base = sb + 32768u;
#pragma unroll
        for (int j = 0; j < 4; j++) {
            int i = tid + j * 256;
            cpa16(base + i * 16, sk + i);
        }
#pragma unroll
        for (int j = 0; j < 2; j++) {
            int i = tid + j * 256;
            cpa16(base + 16384u + i * 16, sv + i);
        }
        CP_COMMIT();
    }
    // ---- Q tiles copy ----
    {
        uint4* dh = (uint4*)smc;
        uint4* dl = (uint4*)(smc + 16384);
#pragma unroll
        for (int j = 0; j < 2; j++) {
            const uint4* src = g_Qt + (size_t)(b * 100 + rt * 2 + j) * 1024;
#pragma unroll
            for (int i = 0; i < 2; i++) {
                int u = tid + i * 256;
                dh[j * 512 + u] = src[u];
                dl[j * 512 + u] = src[512 + u];
            }
        }
    }

    const int subA = lane >> 3, lrA = lane & 7;
    const int rA = warp * 16 + ((subA & 1) << 3) + lrA;
    const int cbA = (subA >> 1) << 4;
    // B-operand ldsm.x4 lane mapping: 4 matrices = {nb even lo, nb even hi, nb odd lo, nb odd hi}
    const int rB16 = ((lane >> 4) << 3) + (lane & 7);     // row within 16-row pair
    const int bsel = ((lane >> 3) & 1) << 4;              // 16B chunk select

    float O[8][4];
#pragma unroll
    for (int nb = 0; nb < 8; nb++)
#pragma unroll
        for (int j = 0; j < 4; j++) O[nb][j] = 0.f;
    float d1 = 0.f, d2 = 0.f, m1 = -INFINITY, m2 = -INFINITY;

    for (int it = 0; it < 25; it++) {
        const unsigned koff = 32768u + (unsigned)(it & 1) * 24576u;
        const unsigned voff = koff + 16384u;
        __syncthreads();
        if (it + 1 < 25) {
            const uint4* sk = g_Kt + (size_t)(b * 100 + kt0 + it + 1) * 1024;
            const uint4* sv = g_Vt + (size_t)(b * 100 + kt0 + it + 1) * 512;
            const unsigned nbase = sb + 32768u + (unsigned)((it + 1) & 1) * 24576u;
#pragma unroll
            for (int j = 0; j < 4; j++) {
                int i = tid + j * 256;
                cpa16(nbase + i * 16, sk + i);
            }
#pragma unroll
            for (int j = 0; j < 2; j++) {
                int i = tid + j * 256;
                cpa16(nbase + 16384u + i * 16, sv + i);
            }
            CP_COMMIT();
            CP_WAIT1();
        } else {
            CP_WAIT0();
        }
        __syncthreads();

        // ---- S = Q K^T (3-way bf16 split, x4 B-loads) ----
        float S[8][4];
#pragma unroll
        for (int nb = 0; nb < 8; nb++)
#pragma unroll
            for (int j = 0; j < 4; j++) S[nb][j] = 0.f;

#pragma unroll
        for (int kc = 0; kc < 4; kc++) {
            const unsigned aswz = (unsigned)((kc * 32 + cbA) ^ ((rA & 7) << 4));
            unsigned qh0, qh1, qh2, qh3, ql0, ql1, ql2, ql3;
            ldsm4(qh0, qh1, qh2, qh3, sb + 0u     + rA * 128 + aswz);
            ldsm4(ql0, ql1, ql2, ql3, sb + 16384u + rA * 128 + aswz);
#pragma unroll
            for (int nbp = 0; nbp < 4; nbp++) {
                const int rB = nbp * 16 + rB16;
                const unsigned bswz = (unsigned)((kc * 32 + bsel) ^ ((rB & 7) << 4));
                const unsigned addr = sb + koff + rB * 128 + bswz;
                unsigned kh0, kh1, kh2, kh3, kl0, kl1, kl2, kl3;
                ldsm4(kh0, kh1, kh2, kh3, addr);
                ldsm4(kl0, kl1, kl2, kl3, addr + 8192u);
                mma_bf(S[2*nbp],   qh0, qh1, qh2, qh3, kh0, kh1);
                mma_bf(S[2*nbp],   ql0, ql1, ql2, ql3, kh0, kh1);
                mma_bf(S[2*nbp],   qh0, qh1, qh2, qh3, kl0, kl1);
                mma_bf(S[2*nbp+1], qh0, qh1, qh2, qh3, kh2, kh3);
                mma_bf(S[2*nbp+1], ql0, ql1, ql2, ql3, kh2, kh3);
                mma_bf(S[2*nbp+1], qh0, qh1, qh2, qh3, kl2, kl3);
            }
        }

        // ---- online softmax (rows r1 = warp*16+g, r2 = +8) ----
        float tm1 = -INFINITY, tm2 = -INFINITY;
#pragma unroll
        for (int nb = 0; nb < 8; nb++) {
            tm1 = fmaxf(tm1, fmaxf(S[nb][0], S[nb][1]));
            tm2 = fmaxf(tm2, fmaxf(S[nb][2], S[nb][3]));
        }
        tm1 = fmaxf(tm1, __shfl_xor_sync(0xffffffffu, tm1, 1));
        tm1 = fmaxf(tm1, __shfl_xor_sync(0xffffffffu, tm1, 2));
        tm2 = fmaxf(tm2, __shfl_xor_sync(0xffffffffu, tm2, 1));
        tm2 = fmaxf(tm2, __shfl_xor_sync(0xffffffffu, tm2, 2));
        const float m1n = fmaxf(m1, tm1), m2n = fmaxf(m2, tm2);
        const float sc1 = ex2f((m1 - m1n) * L2E), sc2 = ex2f((m2 - m2n) * L2E);
        const float b1 = m1n * L2E, b2 = m2n * L2E;
        m1 = m1n; m2 = m2n;

        unsigned Ph[4][4], Pl[4][4];
        float ds1 = 0.f, ds2 = 0.f;
#pragma unroll
        for (int nb = 0; nb < 8; nb++) {
            float e0 = ex2f(fmaf(S[nb][0], L2E, -b1));
            float e1 = ex2f(fmaf(S[nb][1], L2E, -b1));
            float e2 = ex2f(fmaf(S[nb][2], L2E, -b2));
            float e3 = ex2f(fmaf(S[nb][3], L2E, -b2));
            ds1 += e0 + e1; ds2 += e2 + e3;
            unsigned hA = pk2h(e0, e1), hB = pk2h(e2, e3);
            unsigned lA = pk2h(e0 - lo_h(hA), e1 - hi_h(hA));
            unsigned lB = pk2h(e2 - lo_h(hB), e3 - hi_h(hB));
            const int kc = nb >> 1, o = (nb & 1) << 1;
            Ph[kc][o] = hA; Ph[kc][o + 1] = hB;
            Pl[kc][o] = lA; Pl[kc][o + 1] = lB;
        }
        d1 = d1 * sc1 + ds1;
        d2 = d2 * sc2 + ds2;
#pragma unroll
        for (int nb = 0; nb < 8; nb++) {
            O[nb][0] *= sc1; O[nb][1] *= sc1;
            O[nb][2] *= sc2; O[nb][3] *= sc2;
        }

        // ---- O += P V (fp16, 2 passes, x4 V-loads) ----
#pragma unroll
        for (int kc = 0; kc < 4; kc++) {
#pragma unroll
            for (int nbp = 0; nbp < 4; nbp++) {
                const int rB = nbp * 16 + rB16;
                const unsigned bswz = (unsigned)((kc * 32 + bsel) ^ ((rB & 7) << 4));
                unsigned v0, v1, v2, v3;
                ldsm4(v0, v1, v2, v3, sb + voff + rB * 128 + bswz);
                mma_h(O[2*nbp],   Ph[kc][0], Ph[kc][1], Ph[kc][2], Ph[kc][3], v0, v1);
                mma_h(O[2*nbp],   Pl[kc][0], Pl[kc][1], Pl[kc][2], Pl[kc][3], v0, v1);
                mma_h(O[2*nbp+1], Ph[kc][0], Ph[kc][1], Ph[kc][2], Ph[kc][3], v2, v3);
                mma_h(O[2*nbp+1], Pl[kc][0], Pl[kc][1], Pl[kc][2], Pl[kc][3], v2, v3);
            }
        }
    }

    // ---- epilogue: reduce denominators, store (m, d, O) partials ----
    d1 += __shfl_xor_sync(0xffffffffu, d1, 1);
    d1 += __shfl_xor_sync(0xffffffffu, d1, 2);
    d2 += __shfl_xor_sync(0xffffffffu, d2, 1);
    d2 += __shfl_xor_sync(0xffffffffu, d2, 2);
    const int cta = (b * 4 + quarter) * 50 + rt;
    if (t == 0) {
        g_Od[cta * 128 + warp * 16 + g]     = d1;
        g_Od[cta * 128 + warp * 16 + g + 8] = d2;
        g_Om[cta * 128 + warp * 16 + g]     = m1;
        g_Om[cta * 128 + warp * 16 + g + 8] = m2;
    }
    float* U = g_Op + (size_t)cta * 8192;
#pragma unroll
    for (int nb = 0; nb < 8; nb++) {
        const int ch = nb * 8 + t * 2;
        *(float2*)&U[(warp * 16 + g) * 64 + ch]     = make_float2(O[nb][0], O[nb][1]);
        *(float2*)&U[(warp * 16 + g + 8) * 64 + ch] = make_float2(O[nb][2], O[nb][3]);
    }
}

// ---------------------------------------------------------------------------
// combine quarters with max-merge. grid (100, 4), 256 thr
// ---------------------------------------------------------------------------
__global__ __launch_bounds__(256) void combine_kernel(float* __restrict__ out) {
    __shared__ float sden[64];
    __shared__ float sw[4][64];
    __shared__ float sO[64 * 65];
    const int rt64 = blockIdx.x, b = blockIdx.y, tid = threadIdx.x;
    const int rtb = rt64 >> 1, ro = (rt64 & 1) * 64;
    const float L2E = 1.4426950408889634f;
    int c_q[4];
#pragma unroll
    for (int q = 0; q < 4; q++) c_q[q] = (b * 4 + q) * 50 + rtb;

    if (tid < 64) {
        float mq[4], dq[4], M = -INFINITY;
#pragma unroll
        for (int q = 0; q < 4; q++) {
            mq[q] = g_Om[c_q[q] * 128 + ro + tid];
            dq[q] = g_Od[c_q[q] * 128 + ro + tid];
            M = fmaxf(M, mq[q]);
        }
        float den = 0.f;
#pragma unroll
        for (int q = 0; q < 4; q++) {
            float wq = ex2f((mq[q] - M) * L2E);
            sw[q][tid] = wq;
            den += wq * dq[q];
        }
        sden[tid] = 1.f / den;
    }
    __syncthreads();
#pragma unroll
    for (int i = 0; i < 16; i++) {
        int idx = tid + i * 256, r = idx >> 6, c = idx & 63;
        float s = 0.f;
#pragma unroll
        for (int q = 0; q < 4; q++)
            s += sw[q][r] * g_Op[(size_t)c_q[q] * 8192 + (ro + r) * 64 + c];
        sO[r * 65 + c] = s * sden[r];
    }
    __syncthreads();
    const int n0 = rt64 * 64;
#pragma unroll
    for (int i = 0; i < 16; i++) {
        int idx = tid + i * 256, c = idx >> 6, r = idx & 63;
        out[((size_t)b * 64 + c) * NN + n0 + r] += sO[r * 65 + c];
    }
}

// ---------------------------------------------------------------------------
extern "C" void kernel_launch(void* const* d_in, const int* in_sizes, int n_in,
                              void* d_out, int out_size)
{
    const float* x    = (const float*)d_in[0];
    const float* w    = (const float*)d_in[1];
    const float* bias = (const float*)d_in[2];
    float* out = (float*)d_out;

    const int fsm = 32768 + 2 * 24576;  // 81920 B
    cudaFuncSetAttribute(flash_wm3, cudaFuncAttributeMaxDynamicSharedMemorySize, fsm);

    qkv_kernel<<<dim3(100, 2, 4), 256>>>(x, w, bias);
    repack_kernel<<<dim3(100, 4), 256>>>();
    chan_logits_kernel<<<dim3(32, 4), 256>>>();
    chan_softmax_kernel<<<4, 64>>>();
    chan_apply_kernel<<<dim3(100, 4), 256>>>(out);
    flash_wm3<<<dim3(50, 4, 4), 256, fsm>>>();
    combine_kernel<<<dim3(100, 4), 256>>>(out);
}

// round 9
// speedup vs baseline: 6.5516x; 1.2914x over previous
#include <cuda_runtime.h>
#include <cuda_bf16.h>
#include <cuda_fp16.h>
#include <math.h>
#include <stdint.h>

#define BB 4
#define CC 64
#define NN 6400

// ---------------- scratch ----------------
__device__ float g_Q [BB * NN * CC];   // [b][n][c], row n = q(h=n%80, w=n/80)
__device__ float g_V [BB * NN * CC];   // [b][m][c], row m = v(h=m%80, w=m/80)
__device__ float g_Kc[BB * NN * CC];   // [b][m][c], k natural order
__device__ float g_Lp[BB * 32 * CC * CC];
__device__ float g_ma[BB * CC * CC];
// MMA tiles, ldmatrix-swizzled
__device__ uint4 g_Qt[BB * 100 * 1024];  // bf16 hi(512)+lo(512): [row64][ch64]
__device__ uint4 g_Kt[BB * 100 * 1024];  // bf16 hi+lo: [key64][ch64]
__device__ uint4 g_Vt[BB * 100 * 512];   // fp16 single: [ch64][key64]
// split-kv partials: 800 CTAs x 128 rows
__device__ float g_Op[800 * 128 * 64];
__device__ float g_Od[800 * 128];
__device__ float g_Om[800 * 128];

// ---------------- helpers ----------------
__device__ __forceinline__ unsigned smem_u32(const void* p) {
    unsigned a;
    asm("{ .reg .u64 t; cvta.to.shared.u64 t, %1; cvt.u32.u64 %0, t; }" : "=r"(a) : "l"(p));
    return a;
}
__device__ __forceinline__ void ldsm4(unsigned& r0, unsigned& r1, unsigned& r2, unsigned& r3, unsigned a) {
    asm volatile("ldmatrix.sync.aligned.m8n8.x4.shared.b16 {%0,%1,%2,%3}, [%4];"
                 : "=r"(r0), "=r"(r1), "=r"(r2), "=r"(r3) : "r"(a));
}
__device__ __forceinline__ void mma_bf(float* c,
                                       unsigned a0, unsigned a1, unsigned a2, unsigned a3,
                                       unsigned b0, unsigned b1) {
    asm volatile("mma.sync.aligned.m16n8k16.row.col.f32.bf16.bf16.f32 "
                 "{%0,%1,%2,%3}, {%4,%5,%6,%7}, {%8,%9}, {%0,%1,%2,%3};"
                 : "+f"(c[0]), "+f"(c[1]), "+f"(c[2]), "+f"(c[3])
                 : "r"(a0), "r"(a1), "r"(a2), "r"(a3), "r"(b0), "r"(b1));
}
__device__ __forceinline__ void mma_h(float* c,
                                      unsigned a0, unsigned a1, unsigned a2, unsigned a3,
                                      unsigned b0, unsigned b1) {
    asm volatile("mma.sync.aligned.m16n8k16.row.col.f32.f16.f16.f32 "
                 "{%0,%1,%2,%3}, {%4,%5,%6,%7}, {%8,%9}, {%0,%1,%2,%3};"
                 : "+f"(c[0]), "+f"(c[1]), "+f"(c[2]), "+f"(c[3])
                 : "r"(a0), "r"(a1), "r"(a2), "r"(a3), "r"(b0), "r"(b1));
}
__device__ __forceinline__ unsigned pk2(float lo, float hi) {  // bf16x2, lower = lo
    unsigned r; asm("cvt.rn.bf16x2.f32 %0, %1, %2;" : "=r"(r) : "f"(hi), "f"(lo)); return r;
}
__device__ __forceinline__ unsigned pk2h(float lo, float hi) { // f16x2, lower = lo
    unsigned r; asm("cvt.rn.f16x2.f32 %0, %1, %2;" : "=r"(r) : "f"(hi), "f"(lo)); return r;
}
__device__ __forceinline__ float lo_f(unsigned h) { return __uint_as_float(h << 16); }
__device__ __forceinline__ float hi_f(unsigned h) { return __uint_as_float(h & 0xffff0000u); }
__device__ __forceinline__ float ex2f(float x) {
    float r; asm("ex2.approx.ftz.f32 %0, %1;" : "=f"(r) : "f"(x)); return r;
}
__device__ __forceinline__ void cvt8(const float* v, unsigned* hw, unsigned* lw) {
#pragma unroll
    for (int i = 0; i < 4; i++) {
        unsigned h = pk2(v[2*i], v[2*i+1]);
        hw[i] = h;
        lw[i] = pk2(v[2*i] - lo_f(h), v[2*i+1] - hi_f(h));
    }
}
__device__ __forceinline__ void cpa16(unsigned d, const void* g) {
    asm volatile("cp.async.cg.shared.global [%0], [%1], 16;" :: "r"(d), "l"(g));
}
#define CP_COMMIT() asm volatile("cp.async.commit_group;" ::: "memory")
#define CP_WAIT1()  asm volatile("cp.async.wait_group 1;" ::: "memory")
#define CP_WAIT0()  asm volatile("cp.async.wait_group 0;" ::: "memory")

// ---------------------------------------------------------------------------
// Kernel 1: 1x1 conv qkv. grid (100, 2, 4)
// ---------------------------------------------------------------------------
__global__ __launch_bounds__(256) void qkv_kernel(
    const float* __restrict__ x, const float* __restrict__ w, const float* __restrict__ bias)
{
    __shared__ float ws[64][100];
    __shared__ float xs[64][64];
    const int b = blockIdx.z, half = blockIdx.y, n0 = blockIdx.x * 64;
    const int tid = threadIdx.x, obase = half * 96;

    for (int idx = tid; idx < 96 * 64; idx += 256) {
        int o = idx >> 6, c = idx & 63;
        ws[c][o] = w[(size_t)(obase + o) * 64 + c];
    }
    for (int idx = tid; idx < 64 * 64; idx += 256) {
        int c = idx >> 6, p = idx & 63;
        xs[c][p] = x[((size_t)b * 64 + c) * NN + n0 + p];
    }
    __syncthreads();

    const int p = tid & 63, o0 = (tid >> 6) * 24;
    float acc[24];
#pragma unroll
    for (int j = 0; j < 24; j++) acc[j] = 0.f;
#pragma unroll 4
    for (int c = 0; c < 64; c++) {
        float xv = xs[c][p];
#pragma unroll
        for (int j4 = 0; j4 < 24; j4 += 4) {
            float4 wv = *(const float4*)&ws[c][o0 + j4];
            acc[j4+0] += xv * wv.x; acc[j4+1] += xv * wv.y;
            acc[j4+2] += xv * wv.z; acc[j4+3] += xv * wv.w;
        }
    }
    const int n = n0 + p, h = n / 80, wq = n % 80, nt = wq * 80 + h;
#pragma unroll
    for (int j4 = 0; j4 < 24; j4 += 4) {
        const int o = obase + o0 + j4;
        float4 v4;
        v4.x = acc[j4+0] + bias[o+0]; v4.y = acc[j4+1] + bias[o+1];
        v4.z = acc[j4+2] + bias[o+2]; v4.w = acc[j4+3] + bias[o+3];
        if (o < 64) {
            *(float4*)&g_Q[((size_t)b*NN + nt)*64 + o] = v4;
        } else if (o < 128) {
            *(float4*)&g_Kc[((size_t)b*NN + n)*64 + (o-64)] = v4;
        } else {
            *(float4*)&g_V[((size_t)b*NN + nt)*64 + (o-128)] = v4;
        }
    }
}

// ---------------------------------------------------------------------------
// repack: Q/K bf16 hi/lo, V fp16 single; ldmatrix-swizzled. grid (100, 4)
// ---------------------------------------------------------------------------
__global__ __launch_bounds__(256) void repack_kernel() {
    const int kt = blockIdx.x, b = blockIdx.y, tid = threadIdx.x;
    uint4* dQ = g_Qt + (size_t)(b * 100 + kt) * 1024;
    uint4* dK = g_Kt + (size_t)(b * 100 + kt) * 1024;
    uint4* dV = g_Vt + (size_t)(b * 100 + kt) * 512;

    for (int u = tid; u < 512; u += 256) {
        const int r = u >> 3, cu = u & 7;
        const int du = r * 8 + (cu ^ (r & 7));
        {   // Q
            const float* s = g_Q + ((size_t)b * NN + kt * 64 + r) * 64 + cu * 8;
            float v[8];
            *(float4*)v = *(const float4*)s; *(float4*)(v + 4) = *(const float4*)(s + 4);
            uint4 hw, lw; cvt8(v, (unsigned*)&hw, (unsigned*)&lw);
            dQ[du] = hw; dQ[512 + du] = lw;
        }
        {   // K: key r -> m = kt*64+r, source row nt(m)
            const int m = kt * 64 + r;
            const int nt = (m % 80) * 80 + m / 80;
            const float* s = g_Q + ((size_t)b * NN + nt) * 64 + cu * 8;
            float v[8];
            *(float4*)v = *(const float4*)s; *(float4*)(v + 4) = *(const float4*)(s + 4);
            uint4 hw, lw; cvt8(v, (unsigned*)&hw, (unsigned*)&lw);
            dK[du] = hw; dK[512 + du] = lw;
        }
        {   // V fp16: row = ch r, keys cu*8..cu*8+7
            const float* s = g_V + ((size_t)b * NN + kt * 64 + cu * 8) * 64 + r;
            float v[8];
#pragma unroll
            for (int j = 0; j < 8; j++) v[j] = s[j * 64];
            uint4 hw; unsigned* hww = (unsigned*)&hw;
#pragma unroll
            for (int i = 0; i < 4; i++) hww[i] = pk2h(v[2*i], v[2*i+1]);
            dV[du] = hw;
        }
    }
}

// ---------------------------------------------------------------------------
// channel attention logits (unchanged)
// ---------------------------------------------------------------------------
__global__ __launch_bounds__(256) void chan_logits_kernel() {
    const int b = blockIdx.y, chunk = blockIdx.x, tid = threadIdx.x;
    const int tx = tid & 15, ty = tid >> 4;
    const float* __restrict__ Kc = g_Kc + (size_t)b * NN * CC;
    const float* __restrict__ Qm = g_Q  + (size_t)b * NN * CC;
    float acc[4][4];
#pragma unroll
    for (int i = 0; i < 4; i++)
#pragma unroll
        for (int j = 0; j < 4; j++) acc[i][j] = 0.f;
    const int m0 = chunk * 200;
#pragma unroll 2
    for (int m = m0; m < m0 + 200; m++) {
        float4 kv4 = *(const float4*)(Kc + (size_t)m*64 + ty*4);
        float4 qv4 = *(const float4*)(Qm + (size_t)m*64 + tx*4);
        float kv[4] = {kv4.x, kv4.y, kv4.z, kv4.w};
        float qv[4] = {qv4.x, qv4.y, qv4.z, qv4.w};
#pragma unroll
        for (int i = 0; i < 4; i++)
#pragma unroll
            for (int j = 0; j < 4; j++) acc[i][j] += kv[i] * qv[j];
    }
    float* Lp = g_Lp + ((size_t)b*32 + chunk) * 64 * 64;
#pragma unroll
    for (int i = 0; i < 4; i++)
        *(float4*)(Lp + (size_t)(ty*4 + i)*64 + tx*4) =
            make_float4(acc[i][0], acc[i][1], acc[i][2], acc[i][3]);
}

// ---------------------------------------------------------------------------
// parallel reduce + softmax. grid (64 rows, 4 b), 64 thr (thread = column)
// ---------------------------------------------------------------------------
__global__ void chan_softmax_kernel() {
    __shared__ float red[2], rs[2];
    const int c = blockIdx.x, b = blockIdx.y, j = threadIdx.x;
    float s = 0.f;
#pragma unroll
    for (int ch = 0; ch < 32; ch++)
        s += g_Lp[(((size_t)b * 32 + ch) * 64 + c) * 64 + j];
    float m = s;
#pragma unroll
    for (int o = 16; o; o >>= 1) m = fmaxf(m, __shfl_xor_sync(0xffffffffu, m, o));
    if ((j & 31) == 0) red[j >> 5] = m;
    __syncthreads();
    m = fmaxf(red[0], red[1]);
    const float e = ex2f((s - m) * 1.4426950408889634f);
    float t = e;
#pragma unroll
    for (int o = 16; o; o >>= 1) t += __shfl_xor_sync(0xffffffffu, t, o);
    if ((j & 31) == 0) rs[j >> 5] = t;
    __syncthreads();
    g_ma[((size_t)b * 64 + c) * 64 + j] = e / (rs[0] + rs[1]);
}

__global__ __launch_bounds__(256) void chan_apply_kernel(float* __restrict__ out) {
    __shared__ float vs[64][64];
    __shared__ float mas[64][65];
    const int b = blockIdx.y, n0 = blockIdx.x * 64, tid = threadIdx.x;
    const int tx = tid & 15, ty = tid >> 4;
    for (int idx = tid; idx < 4096; idx += 256) {
        int c = idx >> 6, cp = idx & 63;
        mas[cp][c] = g_ma[((size_t)b*64 + c)*64 + cp];
    }
    {
        int p = tid >> 2, cb = (tid & 3) * 16;
        int n = n0 + p, nt = (n % 80) * 80 + n / 80;
        const float* vp = g_V + ((size_t)b*NN + nt)*64 + cb;
#pragma unroll
        for (int k = 0; k < 4; k++) {
            float4 v4 = *(const float4*)(vp + 4*k);
            vs[cb+4*k+0][p] = v4.x; vs[cb+4*k+1][p] = v4.y;
            vs[cb+4*k+2][p] = v4.z; vs[cb+4*k+3][p] = v4.w;
        }
    }
    __syncthreads();
    float acc[4][4];
#pragma unroll
    for (int i = 0; i < 4; i++)
#pragma unroll
        for (int j = 0; j < 4; j++) acc[i][j] = 0.f;
#pragma unroll 4
    for (int cp = 0; cp < 64; cp++) {
        float mv[4];
#pragma unroll
        for (int i = 0; i < 4; i++) mv[i] = mas[cp][ty*4 + i];
        float4 v4 = *(const float4*)&vs[cp][tx*4];
        float vv[4] = {v4.x, v4.y, v4.z, v4.w};
#pragma unroll
        for (int i = 0; i < 4; i++)
#pragma unroll
            for (int j = 0; j < 4; j++) acc[i][j] += mv[i] * vv[j];
    }
#pragma unroll
    for (int i = 0; i < 4; i++)
        *(float4*)(out + ((size_t)b*64 + ty*4 + i)*NN + n0 + tx*4) =
            make_float4(acc[i][0], acc[i][1], acc[i][2], acc[i][3]);
}

// ---------------------------------------------------------------------------
// warp-MMA flash v4: online softmax, single-fp16-P O-phase, ldsm.x4 B-loads.
// grid (50, 4, 4), 256 thr, 128 rows/CTA, 25 key-tiles, 2-stage cp.async.
// smem (80KB): Qh 0, Ql 16K; stage s at 32K + s*24K: Kh(8K) Kl(8K) Vf16(8K)
// ---------------------------------------------------------------------------
__global__ __launch_bounds__(256, 2) void flash_wm4() {
    extern __shared__ char smc[];
    const unsigned sb = smem_u32(smc);
    const int rt = blockIdx.x, quarter = blockIdx.y, b = blockIdx.z;
    const int tid = threadIdx.x, warp = tid >> 5, lane = tid & 31;
    const int g = lane >> 2, t = lane & 3;
    const int kt0 = quarter * 25;
    const float L2E = 1.4426950408889634f;

    // ---- stage-0 prefetch ----
    {
        const uint4* sk = g_Kt + (size_t)(b * 100 + kt0) * 1024;
        const uint4* sv = g_Vt + (size_t)(b * 100 + kt0) * 512;
        const unsigned base = sb + 32768u;
#pragma unroll
        for (int j = 0; j < 4; j++) {
            int i = tid + j * 256;
            cpa16(base + i * 16, sk + i);
        }
#pragma unroll
        for (int j = 0; j < 2; j++) {
            int i = tid + j * 256;
            cpa16(base + 16384u + i * 16, sv + i);
        }
        CP_COMMIT();
    }
    // ---- Q tiles copy ----
    {
        uint4* dh = (uint4*)smc;
        uint4* dl = (uint4*)(smc + 16384);
#pragma unroll
        for (int j = 0; j < 2; j++) {
            const uint4* src = g_Qt + (size_t)(b * 100 + rt * 2 + j) * 1024;
#pragma unroll
            for (int i = 0; i < 2; i++) {
                int u = tid + i * 256;
                dh[j * 512 + u] = src[u];
                dl[j * 512 + u] = src[512 + u];
            }
        }
    }

    const int subA = lane >> 3, lrA = lane & 7;
    const int rA = warp * 16 + ((subA & 1) << 3) + lrA;
    const int cbA = (subA >> 1) << 4;
    const int rB16 = ((lane >> 4) << 3) + (lane & 7);
    const int bsel = ((lane >> 3) & 1) << 4;

    float O[8][4];
#pragma unroll
    for (int nb = 0; nb < 8; nb++)
#pragma unroll
        for (int j = 0; j < 4; j++) O[nb][j] = 0.f;
    float d1 = 0.f, d2 = 0.f, m1 = -INFINITY, m2 = -INFINITY;

    for (int it = 0; it < 25; it++) {
        const unsigned koff = 32768u + (unsigned)(it & 1) * 24576u;
        const unsigned voff = koff + 16384u;
        __syncthreads();
        if (it + 1 < 25) {
            const uint4* sk = g_Kt + (size_t)(b * 100 + kt0 + it + 1) * 1024;
            const uint4* sv = g_Vt + (size_t)(b * 100 + kt0 + it + 1) * 512;
            const unsigned nbase = sb + 32768u + (unsigned)((it + 1) & 1) * 24576u;
#pragma unroll
            for (int j = 0; j < 4; j++) {
                int i = tid + j * 256;
                cpa16(nbase + i * 16, sk + i);
            }
#pragma unroll
            for (int j = 0; j < 2; j++) {
                int i = tid + j * 256;
                cpa16(nbase + 16384u + i * 16, sv + i);
            }
            CP_COMMIT();
            CP_WAIT1();
        } else {
            CP_WAIT0();
        }
        __syncthreads();

        // ---- S = Q K^T (3-way bf16 split, x4 B-loads) ----
        float S[8][4];
#pragma unroll
        for (int nb = 0; nb < 8; nb++)
#pragma unroll
            for (int j = 0; j < 4; j++) S[nb][j] = 0.f;

#pragma unroll
        for (int kc = 0; kc < 4; kc++) {
            const unsigned aswz = (unsigned)((kc * 32 + cbA) ^ ((rA & 7) << 4));
            unsigned qh0, qh1, qh2, qh3, ql0, ql1, ql2, ql3;
            ldsm4(qh0, qh1, qh2, qh3, sb + 0u     + rA * 128 + aswz);
            ldsm4(ql0, ql1, ql2, ql3, sb + 16384u + rA * 128 + aswz);
#pragma unroll
            for (int nbp = 0; nbp < 4; nbp++) {
                const int rB = nbp * 16 + rB16;
                const unsigned bswz = (unsigned)((kc * 32 + bsel) ^ ((rB & 7) << 4));
                const unsigned addr = sb + koff + rB * 128 + bswz;
                unsigned kh0, kh1, kh2, kh3, kl0, kl1, kl2, kl3;
                ldsm4(kh0, kh1, kh2, kh3, addr);
                ldsm4(kl0, kl1, kl2, kl3, addr + 8192u);
                mma_bf(S[2*nbp],   qh0, qh1, qh2, qh3, kh0, kh1);
                mma_bf(S[2*nbp],   ql0, ql1, ql2, ql3, kh0, kh1);
                mma_bf(S[2*nbp],   qh0, qh1, qh2, qh3, kl0, kl1);
                mma_bf(S[2*nbp+1], qh0, qh1, qh2, qh3, kh2, kh3);
                mma_bf(S[2*nbp+1], ql0, ql1, ql2, ql3, kh2, kh3);
                mma_bf(S[2*nbp+1], qh0, qh1, qh2, qh3, kl2, kl3);
            }
        }

        // ---- online softmax (rows r1 = warp*16+g, r2 = +8) ----
        float tm1 = -INFINITY, tm2 = -INFINITY;
#pragma unroll
        for (int nb = 0; nb < 8; nb++) {
            tm1 = fmaxf(tm1, fmaxf(S[nb][0], S[nb][1]));
            tm2 = fmaxf(tm2, fmaxf(S[nb][2], S[nb][3]));
        }
        tm1 = fmaxf(tm1, __shfl_xor_sync(0xffffffffu, tm1, 1));
        tm1 = fmaxf(tm1, __shfl_xor_sync(0xffffffffu, tm1, 2));
        tm2 = fmaxf(tm2, __shfl_xor_sync(0xffffffffu, tm2, 1));
        tm2 = fmaxf(tm2, __shfl_xor_sync(0xffffffffu, tm2, 2));
        const float m1n = fmaxf(m1, tm1), m2n = fmaxf(m2, tm2);
        const float sc1 = ex2f((m1 - m1n) * L2E), sc2 = ex2f((m2 - m2n) * L2E);
        const float b1 = m1n * L2E, b2 = m2n * L2E;
        m1 = m1n; m2 = m2n;

        unsigned Ph[4][4];
        float ds1 = 0.f, ds2 = 0.f;
#pragma unroll
        for (int nb = 0; nb < 8; nb++) {
            float e0 = ex2f(fmaf(S[nb][0], L2E, -b1));
            float e1 = ex2f(fmaf(S[nb][1], L2E, -b1));
            float e2 = ex2f(fmaf(S[nb][2], L2E, -b2));
            float e3 = ex2f(fmaf(S[nb][3], L2E, -b2));
            ds1 += e0 + e1; ds2 += e2 + e3;
            const int kc = nb >> 1, o = (nb & 1) << 1;
            Ph[kc][o]     = pk2h(e0, e1);
            Ph[kc][o + 1] = pk2h(e2, e3);
        }
        d1 = d1 * sc1 + ds1;
        d2 = d2 * sc2 + ds2;
#pragma unroll
        for (int nb = 0; nb < 8; nb++) {
            O[nb][0] *= sc1; O[nb][1] *= sc1;
            O[nb][2] *= sc2; O[nb][3] *= sc2;
        }

        // ---- O += P V (fp16 single pass, x4 V-loads) ----
#pragma unroll
        for (int kc = 0; kc < 4; kc++) {
#pragma unroll
            for (int nbp = 0; nbp < 4; nbp++) {
                const int rB = nbp * 16 + rB16;
                const unsigned bswz = (unsigned)((kc * 32 + bsel) ^ ((rB & 7) << 4));
                unsigned v0, v1, v2, v3;
                ldsm4(v0, v1, v2, v3, sb + voff + rB * 128 + bswz);
                mma_h(O[2*nbp],   Ph[kc][0], Ph[kc][1], Ph[kc][2], Ph[kc][3], v0, v1);
                mma_h(O[2*nbp+1], Ph[kc][0], Ph[kc][1], Ph[kc][2], Ph[kc][3], v2, v3);
            }
        }
    }

    // ---- epilogue: reduce denominators, store (m, d, O) partials ----
    d1 += __shfl_xor_sync(0xffffffffu, d1, 1);
    d1 += __shfl_xor_sync(0xffffffffu, d1, 2);
    d2 += __shfl_xor_sync(0xffffffffu, d2, 1);
    d2 += __shfl_xor_sync(0xffffffffu, d2, 2);
    const int cta = (b * 4 + quarter) * 50 + rt;
    if (t == 0) {
        g_Od[cta * 128 + warp * 16 + g]     = d1;
        g_Od[cta * 128 + warp * 16 + g + 8] = d2;
        g_Om[cta * 128 + warp * 16 + g]     = m1;
        g_Om[cta * 128 + warp * 16 + g + 8] = m2;
    }
    float* U = g_Op + (size_t)cta * 8192;
#pragma unroll
    for (int nb = 0; nb < 8; nb++) {
        const int ch = nb * 8 + t * 2;
        *(float2*)&U[(warp * 16 + g) * 64 + ch]     = make_float2(O[nb][0], O[nb][1]);
        *(float2*)&U[(warp * 16 + g + 8) * 64 + ch] = make_float2(O[nb][2], O[nb][3]);
    }
}

// ---------------------------------------------------------------------------
// combine quarters with max-merge. grid (100, 4), 256 thr
// ---------------------------------------------------------------------------
__global__ __launch_bounds__(256) void combine_kernel(float* __restrict__ out) {
    __shared__ float sden[64];
    __shared__ float sw[4][64];
    __shared__ float sO[64 * 65];
    const int rt64 = blockIdx.x, b = blockIdx.y, tid = threadIdx.x;
    const int rtb = rt64 >> 1, ro = (rt64 & 1) * 64;
    const float L2E = 1.4426950408889634f;
    int c_q[4];
#pragma unroll
    for (int q = 0; q < 4; q++) c_q[q] = (b * 4 + q) * 50 + rtb;

    if (tid < 64) {
        float mq[4], dq[4], M = -INFINITY;
#pragma unroll
        for (int q = 0; q < 4; q++) {
            mq[q] = g_Om[c_q[q] * 128 + ro + tid];
            dq[q] = g_Od[c_q[q] * 128 + ro + tid];
            M = fmaxf(M, mq[q]);
        }
        float den = 0.f;
#pragma unroll
        for (int q = 0; q < 4; q++) {
            float wq = ex2f((mq[q] - M) * L2E);
            sw[q][tid] = wq;
            den += wq * dq[q];
        }
        sden[tid] = 1.f / den;
    }
    __syncthreads();
#pragma unroll
    for (int i = 0; i < 16; i++) {
        int idx = tid + i * 256, r = idx >> 6, c = idx & 63;
        float s = 0.f;
#pragma unroll
        for (int q = 0; q < 4; q++)
            s += sw[q][r] * g_Op[(size_t)c_q[q] * 8192 + (ro + r) * 64 + c];
        sO[r * 65 + c] = s * sden[r];
    }
    __syncthreads();
    const int n0 = rt64 * 64;
#pragma unroll
    for (int i = 0; i < 16; i++) {
        int idx = tid + i * 256, c = idx >> 6, r = idx & 63;
        out[((size_t)b * 64 + c) * NN + n0 + r] += sO[r * 65 + c];
    }
}

// ---------------------------------------------------------------------------
extern "C" void kernel_launch(void* const* d_in, const int* in_sizes, int n_in,
                              void* d_out, int out_size)
{
    const float* x    = (const float*)d_in[0];
    const float* w    = (const float*)d_in[1];
    const float* bias = (const float*)d_in[2];
    float* out = (float*)d_out;

    const int fsm = 32768 + 2 * 24576;  // 81920 B
    cudaFuncSetAttribute(flash_wm4, cudaFuncAttributeMaxDynamicSharedMemorySize, fsm);

    qkv_kernel<<<dim3(100, 2, 4), 256>>>(x, w, bias);
    repack_kernel<<<dim3(100, 4), 256>>>();
    chan_logits_kernel<<<dim3(32, 4), 256>>>();
    chan_softmax_kernel<<<dim3(64, 4), 64>>>();
    chan_apply_kernel<<<dim3(100, 4), 256>>>(out);
    flash_wm4<<<dim3(50, 4, 4), 256, fsm>>>();
    combine_kernel<<<dim3(100, 4), 256>>>(out);
}

// round 10
// speedup vs baseline: 6.7050x; 1.0234x over previous
#include <cuda_runtime.h>
#include <cuda_bf16.h>
#include <cuda_fp16.h>
#include <math.h>
#include <stdint.h>

#define BB 4
#define CC 64
#define NN 6400

// ---------------- scratch ----------------
__device__ float g_Q [BB * NN * CC];   // [b][n][c], row n = q(h=n%80, w=n/80)
__device__ float g_V [BB * NN * CC];   // [b][m][c], row m = v(h=m%80, w=m/80)
__device__ float g_Kc[BB * NN * CC];   // [b][m][c], k natural order
__device__ float g_Lp[BB * 32 * CC * CC];
__device__ float g_ma[BB * CC * CC];
// MMA tiles, ldmatrix-swizzled
__device__ uint4 g_Qt[BB * 100 * 1024];  // bf16 hi(512)+lo(512): [row64][ch64]
__device__ uint4 g_Kt[BB * 100 * 1024];  // bf16 hi+lo: [key64][ch64]
__device__ uint4 g_Vt[BB * 100 * 512];   // fp16 single: [ch64][key64]
// split-kv partials: 800 CTAs x 128 rows
__device__ float g_Op[800 * 128 * 64];
__device__ float g_Od[800 * 128];
__device__ float g_Om[800 * 128];

// ---------------- helpers ----------------
__device__ __forceinline__ unsigned smem_u32(const void* p) {
    unsigned a;
    asm("{ .reg .u64 t; cvta.to.shared.u64 t, %1; cvt.u32.u64 %0, t; }" : "=r"(a) : "l"(p));
    return a;
}
__device__ __forceinline__ void ldsm4(unsigned& r0, unsigned& r1, unsigned& r2, unsigned& r3, unsigned a) {
    asm volatile("ldmatrix.sync.aligned.m8n8.x4.shared.b16 {%0,%1,%2,%3}, [%4];"
                 : "=r"(r0), "=r"(r1), "=r"(r2), "=r"(r3) : "r"(a));
}
__device__ __forceinline__ void mma_bf(float* c,
                                       unsigned a0, unsigned a1, unsigned a2, unsigned a3,
                                       unsigned b0, unsigned b1) {
    asm volatile("mma.sync.aligned.m16n8k16.row.col.f32.bf16.bf16.f32 "
                 "{%0,%1,%2,%3}, {%4,%5,%6,%7}, {%8,%9}, {%0,%1,%2,%3};"
                 : "+f"(c[0]), "+f"(c[1]), "+f"(c[2]), "+f"(c[3])
                 : "r"(a0), "r"(a1), "r"(a2), "r"(a3), "r"(b0), "r"(b1));
}
__device__ __forceinline__ void mma_h(float* c,
                                      unsigned a0, unsigned a1, unsigned a2, unsigned a3,
                                      unsigned b0, unsigned b1) {
    asm volatile("mma.sync.aligned.m16n8k16.row.col.f32.f16.f16.f32 "
                 "{%0,%1,%2,%3}, {%4,%5,%6,%7}, {%8,%9}, {%0,%1,%2,%3};"
                 : "+f"(c[0]), "+f"(c[1]), "+f"(c[2]), "+f"(c[3])
                 : "r"(a0), "r"(a1), "r"(a2), "r"(a3), "r"(b0), "r"(b1));
}
__device__ __forceinline__ unsigned pk2(float lo, float hi) {  // bf16x2, lower = lo
    unsigned r; asm("cvt.rn.bf16x2.f32 %0, %1, %2;" : "=r"(r) : "f"(hi), "f"(lo)); return r;
}
__device__ __forceinline__ unsigned pk2h(float lo, float hi) { // f16x2, lower = lo
    unsigned r; asm("cvt.rn.f16x2.f32 %0, %1, %2;" : "=r"(r) : "f"(hi), "f"(lo)); return r;
}
__device__ __forceinline__ float lo_f(unsigned h) { return __uint_as_float(h << 16); }
__device__ __forceinline__ float hi_f(unsigned h) { return __uint_as_float(h & 0xffff0000u); }
__device__ __forceinline__ float ex2f(float x) {
    float r; asm("ex2.approx.ftz.f32 %0, %1;" : "=f"(r) : "f"(x)); return r;
}
__device__ __forceinline__ void cvt8(const float* v, unsigned* hw, unsigned* lw) {
#pragma unroll
    for (int i = 0; i < 4; i++) {
        unsigned h = pk2(v[2*i], v[2*i+1]);
        hw[i] = h;
        lw[i] = pk2(v[2*i] - lo_f(h), v[2*i+1] - hi_f(h));
    }
}
__device__ __forceinline__ void cpa16(unsigned d, const void* g) {
    asm volatile("cp.async.cg.shared.global [%0], [%1], 16;" :: "r"(d), "l"(g));
}
#define CP_COMMIT() asm volatile("cp.async.commit_group;" ::: "memory")
#define CP_WAIT1()  asm volatile("cp.async.wait_group 1;" ::: "memory")
#define CP_WAIT0()  asm volatile("cp.async.wait_group 0;" ::: "memory")

// ---------------------------------------------------------------------------
// Kernel 1: 1x1 conv qkv. grid (100, 2, 4)
// ---------------------------------------------------------------------------
__global__ __launch_bounds__(256) void qkv_kernel(
    const float* __restrict__ x, const float* __restrict__ w, const float* __restrict__ bias)
{
    __shared__ float ws[64][100];
    __shared__ float xs[64][64];
    const int b = blockIdx.z, half = blockIdx.y, n0 = blockIdx.x * 64;
    const int tid = threadIdx.x, obase = half * 96;

    for (int idx = tid; idx < 96 * 64; idx += 256) {
        int o = idx >> 6, c = idx & 63;
        ws[c][o] = w[(size_t)(obase + o) * 64 + c];
    }
    for (int idx = tid; idx < 64 * 64; idx += 256) {
        int c = idx >> 6, p = idx & 63;
        xs[c][p] = x[((size_t)b * 64 + c) * NN + n0 + p];
    }
    __syncthreads();

    const int p = tid & 63, o0 = (tid >> 6) * 24;
    float acc[24];
#pragma unroll
    for (int j = 0; j < 24; j++) acc[j] = 0.f;
#pragma unroll 4
    for (int c = 0; c < 64; c++) {
        float xv = xs[c][p];
#pragma unroll
        for (int j4 = 0; j4 < 24; j4 += 4) {
            float4 wv = *(const float4*)&ws[c][o0 + j4];
            acc[j4+0] += xv * wv.x; acc[j4+1] += xv * wv.y;
            acc[j4+2] += xv * wv.z; acc[j4+3] += xv * wv.w;
        }
    }
    const int n = n0 + p, h = n / 80, wq = n % 80, nt = wq * 80 + h;
#pragma unroll
    for (int j4 = 0; j4 < 24; j4 += 4) {
        const int o = obase + o0 + j4;
        float4 v4;
        v4.x = acc[j4+0] + bias[o+0]; v4.y = acc[j4+1] + bias[o+1];
        v4.z = acc[j4+2] + bias[o+2]; v4.w = acc[j4+3] + bias[o+3];
        if (o < 64) {
            *(float4*)&g_Q[((size_t)b*NN + nt)*64 + o] = v4;
        } else if (o < 128) {
            *(float4*)&g_Kc[((size_t)b*NN + n)*64 + (o-64)] = v4;
        } else {
            *(float4*)&g_V[((size_t)b*NN + nt)*64 + (o-128)] = v4;
        }
    }
}

// ---------------------------------------------------------------------------
// repack: Q/K bf16 hi/lo, V fp16 single; ldmatrix-swizzled. grid (100, 4)
// ---------------------------------------------------------------------------
__global__ __launch_bounds__(256) void repack_kernel() {
    const int kt = blockIdx.x, b = blockIdx.y, tid = threadIdx.x;
    uint4* dQ = g_Qt + (size_t)(b * 100 + kt) * 1024;
    uint4* dK = g_Kt + (size_t)(b * 100 + kt) * 1024;
    uint4* dV = g_Vt + (size_t)(b * 100 + kt) * 512;

    for (int u = tid; u < 512; u += 256) {
        const int r = u >> 3, cu = u & 7;
        const int du = r * 8 + (cu ^ (r & 7));
        {   // Q
            const float* s = g_Q + ((size_t)b * NN + kt * 64 + r) * 64 + cu * 8;
            float v[8];
            *(float4*)v = *(const float4*)s; *(float4*)(v + 4) = *(const float4*)(s + 4);
            uint4 hw, lw; cvt8(v, (unsigned*)&hw, (unsigned*)&lw);
            dQ[du] = hw; dQ[512 + du] = lw;
        }
        {   // K: key r -> m = kt*64+r, source row nt(m)
            const int m = kt * 64 + r;
            const int nt = (m % 80) * 80 + m / 80;
            const float* s = g_Q + ((size_t)b * NN + nt) * 64 + cu * 8;
            float v[8];
            *(float4*)v = *(const float4*)s; *(float4*)(v + 4) = *(const float4*)(s + 4);
            uint4 hw, lw; cvt8(v, (unsigned*)&hw, (unsigned*)&lw);
            dK[du] = hw; dK[512 + du] = lw;
        }
        {   // V fp16: row = ch r, keys cu*8..cu*8+7
            const float* s = g_V + ((size_t)b * NN + kt * 64 + cu * 8) * 64 + r;
            float v[8];
#pragma unroll
            for (int j = 0; j < 8; j++) v[j] = s[j * 64];
            uint4 hw; unsigned* hww = (unsigned*)&hw;
#pragma unroll
            for (int i = 0; i < 4; i++) hww[i] = pk2h(v[2*i], v[2*i+1]);
            dV[du] = hw;
        }
    }
}

// ---------------------------------------------------------------------------
// channel attention logits (unchanged)
// ---------------------------------------------------------------------------
__global__ __launch_bounds__(256) void chan_logits_kernel() {
    const int b = blockIdx.y, chunk = blockIdx.x, tid = threadIdx.x;
    const int tx = tid & 15, ty = tid >> 4;
    const float* __restrict__ Kc = g_Kc + (size_t)b * NN * CC;
    const float* __restrict__ Qm = g_Q  + (size_t)b * NN * CC;
    float acc[4][4];
#pragma unroll
    for (int i = 0; i < 4; i++)
#pragma unroll
        for (int j = 0; j < 4; j++) acc[i][j] = 0.f;
    const int m0 = chunk * 200;
#pragma unroll 2
    for (int m = m0; m < m0 + 200; m++) {
        float4 kv4 = *(const float4*)(Kc + (size_t)m*64 + ty*4);
        float4 qv4 = *(const float4*)(Qm + (size_t)m*64 + tx*4);
        float kv[4] = {kv4.x, kv4.y, kv4.z, kv4.w};
        float qv[4] = {qv4.x, qv4.y, qv4.z, qv4.w};
#pragma unroll
        for (int i = 0; i < 4; i++)
#pragma unroll
            for (int j = 0; j < 4; j++) acc[i][j] += kv[i] * qv[j];
    }
    float* Lp = g_Lp + ((size_t)b*32 + chunk) * 64 * 64;
#pragma unroll
    for (int i = 0; i < 4; i++)
        *(float4*)(Lp + (size_t)(ty*4 + i)*64 + tx*4) =
            make_float4(acc[i][0], acc[i][1], acc[i][2], acc[i][3]);
}

// ---------------------------------------------------------------------------
// parallel reduce + softmax. grid (64 rows, 4 b), 64 thr (thread = column)
// ---------------------------------------------------------------------------
__global__ void chan_softmax_kernel() {
    __shared__ float red[2], rs[2];
    const int c = blockIdx.x, b = blockIdx.y, j = threadIdx.x;
    float s = 0.f;
#pragma unroll
    for (int ch = 0; ch < 32; ch++)
        s += g_Lp[(((size_t)b * 32 + ch) * 64 + c) * 64 + j];
    float m = s;
#pragma unroll
    for (int o = 16; o; o >>= 1) m = fmaxf(m, __shfl_xor_sync(0xffffffffu, m, o));
    if ((j & 31) == 0) red[j >> 5] = m;
    __syncthreads();
    m = fmaxf(red[0], red[1]);
    const float e = ex2f((s - m) * 1.4426950408889634f);
    float t = e;
#pragma unroll
    for (int o = 16; o; o >>= 1) t += __shfl_xor_sync(0xffffffffu, t, o);
    if ((j & 31) == 0) rs[j >> 5] = t;
    __syncthreads();
    g_ma[((size_t)b * 64 + c) * 64 + j] = e / (rs[0] + rs[1]);
}

__global__ __launch_bounds__(256) void chan_apply_kernel(float* __restrict__ out) {
    __shared__ float vs[64][64];
    __shared__ float mas[64][65];
    const int b = blockIdx.y, n0 = blockIdx.x * 64, tid = threadIdx.x;
    const int tx = tid & 15, ty = tid >> 4;
    for (int idx = tid; idx < 4096; idx += 256) {
        int c = idx >> 6, cp = idx & 63;
        mas[cp][c] = g_ma[((size_t)b*64 + c)*64 + cp];
    }
    {
        int p = tid >> 2, cb = (tid & 3) * 16;
        int n = n0 + p, nt = (n % 80) * 80 + n / 80;
        const float* vp = g_V + ((size_t)b*NN + nt)*64 + cb;
#pragma unroll
        for (int k = 0; k < 4; k++) {
            float4 v4 = *(const float4*)(vp + 4*k);
            vs[cb+4*k+0][p] = v4.x; vs[cb+4*k+1][p] = v4.y;
            vs[cb+4*k+2][p] = v4.z; vs[cb+4*k+3][p] = v4.w;
        }
    }
    __syncthreads();
    float acc[4][4];
#pragma unroll
    for (int i = 0; i < 4; i++)
#pragma unroll
        for (int j = 0; j < 4; j++) acc[i][j] = 0.f;
#pragma unroll 4
    for (int cp = 0; cp < 64; cp++) {
        float mv[4];
#pragma unroll
        for (int i = 0; i < 4; i++) mv[i] = mas[cp][ty*4 + i];
        float4 v4 = *(const float4*)&vs[cp][tx*4];
        float vv[4] = {v4.x, v4.y, v4.z, v4.w};
#pragma unroll
        for (int i = 0; i < 4; i++)
#pragma unroll
            for (int j = 0; j < 4; j++) acc[i][j] += mv[i] * vv[j];
    }
#pragma unroll
    for (int i = 0; i < 4; i++)
        *(float4*)(out + ((size_t)b*64 + ty*4 + i)*NN + n0 + tx*4) =
            make_float4(acc[i][0], acc[i][1], acc[i][2], acc[i][3]);
}

// ---------------------------------------------------------------------------
// warp-MMA flash v5: M=32 rows/warp (2 halves share K/V fragments).
// grid (50, 4, 4), 128 thr / 4 warps, 128 rows/CTA, 25 key-tiles, 2-stage.
// smem (80KB): Qh 0, Ql 16K; stage s at 32K + s*24K: Kh(8K) Kl(8K) Vf16(8K)
// ---------------------------------------------------------------------------
__global__ __launch_bounds__(128, 2) void flash_wm5() {
    extern __shared__ char smc[];
    const unsigned sb = smem_u32(smc);
    const int rt = blockIdx.x, quarter = blockIdx.y, b = blockIdx.z;
    const int tid = threadIdx.x, warp = tid >> 5, lane = tid & 31;
    const int g = lane >> 2, t = lane & 3;
    const int kt0 = quarter * 25;
    const float L2E = 1.4426950408889634f;

    // ---- stage-0 prefetch ----
    {
        const uint4* sk = g_Kt + (size_t)(b * 100 + kt0) * 1024;
        const uint4* sv = g_Vt + (size_t)(b * 100 + kt0) * 512;
        const unsigned base = sb + 32768u;
#pragma unroll
        for (int j = 0; j < 8; j++) { int i = tid + j * 128; cpa16(base + i * 16, sk + i); }
#pragma unroll
        for (int j = 0; j < 4; j++) { int i = tid + j * 128; cpa16(base + 16384u + i * 16, sv + i); }
        CP_COMMIT();
    }
    // ---- Q tiles copy (2 x 64 rows, hi+lo) ----
    {
        uint4* dh = (uint4*)smc;
        uint4* dl = (uint4*)(smc + 16384);
#pragma unroll
        for (int j = 0; j < 2; j++) {
            const uint4* src = g_Qt + (size_t)(b * 100 + rt * 2 + j) * 1024;
#pragma unroll
            for (int i = 0; i < 4; i++) {
                int u = tid + i * 128;
                dh[j * 512 + u] = src[u];
                dl[j * 512 + u] = src[512 + u];
            }
        }
    }

    const int subA = lane >> 3, lrA = lane & 7;
    const int rAb = ((subA & 1) << 3) + lrA;   // row offset within 16-row half
    const int cbA = (subA >> 1) << 4;
    const int rB16 = ((lane >> 4) << 3) + (lane & 7);
    const int bsel = ((lane >> 3) & 1) << 4;

    float O[2][8][4];
#pragma unroll
    for (int h = 0; h < 2; h++)
#pragma unroll
        for (int nb = 0; nb < 8; nb++)
#pragma unroll
            for (int j = 0; j < 4; j++) O[h][nb][j] = 0.f;
    float dd[2][2], mm[2][2];
#pragma unroll
    for (int h = 0; h < 2; h++) { dd[h][0] = dd[h][1] = 0.f; mm[h][0] = mm[h][1] = -INFINITY; }

    for (int it = 0; it < 25; it++) {
        const unsigned koff = 32768u + (unsigned)(it & 1) * 24576u;
        const unsigned voff = koff + 16384u;
        __syncthreads();
        if (it + 1 < 25) {
            const uint4* sk = g_Kt + (size_t)(b * 100 + kt0 + it + 1) * 1024;
            const uint4* sv = g_Vt + (size_t)(b * 100 + kt0 + it + 1) * 512;
            const unsigned nbase = sb + 32768u + (unsigned)((it + 1) & 1) * 24576u;
#pragma unroll
            for (int j = 0; j < 8; j++) { int i = tid + j * 128; cpa16(nbase + i * 16, sk + i); }
#pragma unroll
            for (int j = 0; j < 4; j++) { int i = tid + j * 128; cpa16(nbase + 16384u + i * 16, sv + i); }
            CP_COMMIT();
            CP_WAIT1();
        } else {
            CP_WAIT0();
        }
        __syncthreads();

        // ---- S = Q K^T (3-way bf16 split, K frags shared by both halves) ----
        float S[2][8][4];
#pragma unroll
        for (int h = 0; h < 2; h++)
#pragma unroll
            for (int nb = 0; nb < 8; nb++)
#pragma unroll
                for (int j = 0; j < 4; j++) S[h][nb][j] = 0.f;

#pragma unroll
        for (int kc = 0; kc < 4; kc++) {
            unsigned qh[2][4], ql[2][4];
#pragma unroll
            for (int h = 0; h < 2; h++) {
                const int rA = warp * 32 + h * 16 + rAb;
                const unsigned aswz = (unsigned)((kc * 32 + cbA) ^ ((rA & 7) << 4));
                ldsm4(qh[h][0], qh[h][1], qh[h][2], qh[h][3], sb + 0u     + rA * 128 + aswz);
                ldsm4(ql[h][0], ql[h][1], ql[h][2], ql[h][3], sb + 16384u + rA * 128 + aswz);
            }
#pragma unroll
            for (int nbp = 0; nbp < 4; nbp++) {
                const int rB = nbp * 16 + rB16;
                const unsigned bswz = (unsigned)((kc * 32 + bsel) ^ ((rB & 7) << 4));
                const unsigned addr = sb + koff + rB * 128 + bswz;
                unsigned kh0, kh1, kh2, kh3, kl0, kl1, kl2, kl3;
                ldsm4(kh0, kh1, kh2, kh3, addr);
                ldsm4(kl0, kl1, kl2, kl3, addr + 8192u);
#pragma unroll
                for (int h = 0; h < 2; h++) {
                    mma_bf(S[h][2*nbp],   qh[h][0], qh[h][1], qh[h][2], qh[h][3], kh0, kh1);
                    mma_bf(S[h][2*nbp],   ql[h][0], ql[h][1], ql[h][2], ql[h][3], kh0, kh1);
                    mma_bf(S[h][2*nbp],   qh[h][0], qh[h][1], qh[h][2], qh[h][3], kl0, kl1);
                    mma_bf(S[h][2*nbp+1], qh[h][0], qh[h][1], qh[h][2], qh[h][3], kh2, kh3);
                    mma_bf(S[h][2*nbp+1], ql[h][0], ql[h][1], ql[h][2], ql[h][3], kh2, kh3);
                    mma_bf(S[h][2*nbp+1], qh[h][0], qh[h][1], qh[h][2], qh[h][3], kl2, kl3);
                }
            }
        }

        // ---- online softmax per half ----
        unsigned Ph[2][4][4];
#pragma unroll
        for (int h = 0; h < 2; h++) {
            float tm1 = -INFINITY, tm2 = -INFINITY;
#pragma unroll
            for (int nb = 0; nb < 8; nb++) {
                tm1 = fmaxf(tm1, fmaxf(S[h][nb][0], S[h][nb][1]));
                tm2 = fmaxf(tm2, fmaxf(S[h][nb][2], S[h][nb][3]));
            }
            tm1 = fmaxf(tm1, __shfl_xor_sync(0xffffffffu, tm1, 1));
            tm1 = fmaxf(tm1, __shfl_xor_sync(0xffffffffu, tm1, 2));
            tm2 = fmaxf(tm2, __shfl_xor_sync(0xffffffffu, tm2, 1));
            tm2 = fmaxf(tm2, __shfl_xor_sync(0xffffffffu, tm2, 2));
            const float m1n = fmaxf(mm[h][0], tm1), m2n = fmaxf(mm[h][1], tm2);
            const float sc1 = ex2f((mm[h][0] - m1n) * L2E), sc2 = ex2f((mm[h][1] - m2n) * L2E);
            const float b1 = m1n * L2E, b2 = m2n * L2E;
            mm[h][0] = m1n; mm[h][1] = m2n;

            float ds1 = 0.f, ds2 = 0.f;
#pragma unroll
            for (int nb = 0; nb < 8; nb++) {
                float e0 = ex2f(fmaf(S[h][nb][0], L2E, -b1));
                float e1 = ex2f(fmaf(S[h][nb][1], L2E, -b1));
                float e2 = ex2f(fmaf(S[h][nb][2], L2E, -b2));
                float e3 = ex2f(fmaf(S[h][nb][3], L2E, -b2));
                ds1 += e0 + e1; ds2 += e2 + e3;
                const int kc = nb >> 1, o = (nb & 1) << 1;
                Ph[h][kc][o]     = pk2h(e0, e1);
                Ph[h][kc][o + 1] = pk2h(e2, e3);
            }
            dd[h][0] = dd[h][0] * sc1 + ds1;
            dd[h][1] = dd[h][1] * sc2 + ds2;
#pragma unroll
            for (int nb = 0; nb < 8; nb++) {
                O[h][nb][0] *= sc1; O[h][nb][1] *= sc1;
                O[h][nb][2] *= sc2; O[h][nb][3] *= sc2;
            }
        }

        // ---- O += P V (fp16, V frags shared by both halves) ----
#pragma unroll
        for (int kc = 0; kc < 4; kc++) {
#pragma unroll
            for (int nbp = 0; nbp < 4; nbp++) {
                const int rB = nbp * 16 + rB16;
                const unsigned bswz = (unsigned)((kc * 32 + bsel) ^ ((rB & 7) << 4));
                unsigned v0, v1, v2, v3;
                ldsm4(v0, v1, v2, v3, sb + voff + rB * 128 + bswz);
#pragma unroll
                for (int h = 0; h < 2; h++) {
                    mma_h(O[h][2*nbp],   Ph[h][kc][0], Ph[h][kc][1], Ph[h][kc][2], Ph[h][kc][3], v0, v1);
                    mma_h(O[h][2*nbp+1], Ph[h][kc][0], Ph[h][kc][1], Ph[h][kc][2], Ph[h][kc][3], v2, v3);
                }
            }
        }
    }

    // ---- epilogue per half: reduce denominators, store (m, d, O) partials ----
    const int cta = (b * 4 + quarter) * 50 + rt;
    float* U = g_Op + (size_t)cta * 8192;
#pragma unroll
    for (int h = 0; h < 2; h++) {
        float d1 = dd[h][0], d2 = dd[h][1];
        d1 += __shfl_xor_sync(0xffffffffu, d1, 1);
        d1 += __shfl_xor_sync(0xffffffffu, d1, 2);
        d2 += __shfl_xor_sync(0xffffffffu, d2, 1);
        d2 += __shfl_xor_sync(0xffffffffu, d2, 2);
        const int r0 = warp * 32 + h * 16;
        if (t == 0) {
            g_Od[cta * 128 + r0 + g]     = d1;
            g_Od[cta * 128 + r0 + g + 8] = d2;
            g_Om[cta * 128 + r0 + g]     = mm[h][0];
            g_Om[cta * 128 + r0 + g + 8] = mm[h][1];
        }
#pragma unroll
        for (int nb = 0; nb < 8; nb++) {
            const int ch = nb * 8 + t * 2;
            *(float2*)&U[(r0 + g) * 64 + ch]     = make_float2(O[h][nb][0], O[h][nb][1]);
            *(float2*)&U[(r0 + g + 8) * 64 + ch] = make_float2(O[h][nb][2], O[h][nb][3]);
        }
    }
}

// ---------------------------------------------------------------------------
// combine quarters with max-merge. grid (100, 4), 256 thr
// ---------------------------------------------------------------------------
__global__ __launch_bounds__(256) void combine_kernel(float* __restrict__ out) {
    __shared__ float sden[64];
    __shared__ float sw[4][64];
    __shared__ float sO[64 * 65];
    const int rt64 = blockIdx.x, b = blockIdx.y, tid = threadIdx.x;
    const int rtb = rt64 >> 1, ro = (rt64 & 1) * 64;
    const float L2E = 1.4426950408889634f;
    int c_q[4];
#pragma unroll
    for (int q = 0; q < 4; q++) c_q[q] = (b * 4 + q) * 50 + rtb;

    if (tid < 64) {
        float mq[4], dq[4], M = -INFINITY;
#pragma unroll
        for (int q = 0; q < 4; q++) {
            mq[q] = g_Om[c_q[q] * 128 + ro + tid];
            dq[q] = g_Od[c_q[q] * 128 + ro + tid];
            M = fmaxf(M, mq[q]);
        }
        float den = 0.f;
#pragma unroll
        for (int q = 0; q < 4; q++) {
            float wq = ex2f((mq[q] - M) * L2E);
            sw[q][tid] = wq;
            den += wq * dq[q];
        }
        sden[tid] = 1.f / den;
    }
    __syncthreads();
#pragma unroll
    for (int i = 0; i < 16; i++) {
        int idx = tid + i * 256, r = idx >> 6, c = idx & 63;
        float s = 0.f;
#pragma unroll
        for (int q = 0; q < 4; q++)
            s += sw[q][r] * g_Op[(size_t)c_q[q] * 8192 + (ro + r) * 64 + c];
        sO[r * 65 + c] = s * sden[r];
    }
    __syncthreads();
    const int n0 = rt64 * 64;
#pragma unroll
    for (int i = 0; i < 16; i++) {
        int idx = tid + i * 256, c = idx >> 6, r = idx & 63;
        out[((size_t)b * 64 + c) * NN + n0 + r] += sO[r * 65 + c];
    }
}

// ---------------------------------------------------------------------------
extern "C" void kernel_launch(void* const* d_in, const int* in_sizes, int n_in,
                              void* d_out, int out_size)
{
    const float* x    = (const float*)d_in[0];
    const float* w    = (const float*)d_in[1];
    const float* bias = (const float*)d_in[2];
    float* out = (float*)d_out;

    const int fsm = 32768 + 2 * 24576;  // 81920 B
    cudaFuncSetAttribute(flash_wm5, cudaFuncAttributeMaxDynamicSharedMemorySize, fsm);

    qkv_kernel<<<dim3(100, 2, 4), 256>>>(x, w, bias);
    repack_kernel<<<dim3(100, 4), 256>>>();
    chan_logits_kernel<<<dim3(32, 4), 256>>>();
    chan_softmax_kernel<<<dim3(64, 4), 64>>>();
    chan_apply_kernel<<<dim3(100, 4), 256>>>(out);
    flash_wm5<<<dim3(50, 4, 4), 128, fsm>>>();
    combine_kernel<<<dim3(100, 4), 256>>>(out);
}

// round 12
// speedup vs baseline: 6.8402x; 1.0202x over previous
#include <cuda_runtime.h>
#include <cuda_bf16.h>
#include <cuda_fp16.h>
#include <math.h>
#include <stdint.h>

#define BB 4
#define CC 64
#define NN 6400

// ---------------- scratch ----------------
__device__ float g_Q [BB * NN * CC];   // [b][n][c], row n = q(h=n%80, w=n/80)
__device__ float g_V [BB * NN * CC];   // [b][m][c], row m = v(h=m%80, w=m/80)
__device__ float g_Kc[BB * NN * CC];   // [b][m][c], k natural order
__device__ float g_Lp[BB * 32 * CC * CC];
__device__ float g_ma[BB * CC * CC];
// MMA tiles, ldmatrix-swizzled
__device__ uint4 g_Qt[BB * 100 * 1024];  // bf16 hi(512)+lo(512): [row64][ch64]
__device__ uint4 g_Kt[BB * 100 * 1024];  // bf16 hi+lo: [key64][ch64]
__device__ uint4 g_Vt[BB * 100 * 512];   // fp16 single: [ch64][key64]
// split-kv partials: 800 CTAs x 128 rows; O stored fp16x2 (ch pairs)
__device__ unsigned g_Oph[800 * 128 * 32];
__device__ float g_Od[800 * 128];
__device__ float g_Om[800 * 128];

// ---------------- helpers ----------------
__device__ __forceinline__ unsigned smem_u32(const void* p) {
    unsigned a;
    asm("{ .reg .u64 t; cvta.to.shared.u64 t, %1; cvt.u32.u64 %0, t; }" : "=r"(a) : "l"(p));
    return a;
}
__device__ __forceinline__ void ldsm4(unsigned& r0, unsigned& r1, unsigned& r2, unsigned& r3, unsigned a) {
    asm volatile("ldmatrix.sync.aligned.m8n8.x4.shared.b16 {%0,%1,%2,%3}, [%4];"
                 : "=r"(r0), "=r"(r1), "=r"(r2), "=r"(r3) : "r"(a));
}
__device__ __forceinline__ void mma_bf(float* c,
                                       unsigned a0, unsigned a1, unsigned a2, unsigned a3,
                                       unsigned b0, unsigned b1) {
    asm volatile("mma.sync.aligned.m16n8k16.row.col.f32.bf16.bf16.f32 "
                 "{%0,%1,%2,%3}, {%4,%5,%6,%7}, {%8,%9}, {%0,%1,%2,%3};"
                 : "+f"(c[0]), "+f"(c[1]), "+f"(c[2]), "+f"(c[3])
                 : "r"(a0), "r"(a1), "r"(a2), "r"(a3), "r"(b0), "r"(b1));
}
__device__ __forceinline__ void mma_h(float* c,
                                      unsigned a0, unsigned a1, unsigned a2, unsigned a3,
                                      unsigned b0, unsigned b1) {
    asm volatile("mma.sync.aligned.m16n8k16.row.col.f32.f16.f16.f32 "
                 "{%0,%1,%2,%3}, {%4,%5,%6,%7}, {%8,%9}, {%0,%1,%2,%3};"
                 : "+f"(c[0]), "+f"(c[1]), "+f"(c[2]), "+f"(c[3])
                 : "r"(a0), "r"(a1), "r"(a2), "r"(a3), "r"(b0), "r"(b1));
}
__device__ __forceinline__ unsigned pk2(float lo, float hi) {  // bf16x2, lower = lo
    unsigned r; asm("cvt.rn.bf16x2.f32 %0, %1, %2;" : "=r"(r) : "f"(hi), "f"(lo)); return r;
}
__device__ __forceinline__ unsigned pk2h(float lo, float hi) { // f16x2, lower = lo
    unsigned r; asm("cvt.rn.f16x2.f32 %0, %1, %2;" : "=r"(r) : "f"(hi), "f"(lo)); return r;
}
__device__ __forceinline__ float lo_f(unsigned h) { return __uint_as_float(h << 16); }
__device__ __forceinline__ float hi_f(unsigned h) { return __uint_as_float(h & 0xffff0000u); }
__device__ __forceinline__ float ex2f(float x) {
    float r; asm("ex2.approx.ftz.f32 %0, %1;" : "=f"(r) : "f"(x)); return r;
}
__device__ __forceinline__ void cvt8(const float* v, unsigned* hw, unsigned* lw) {
#pragma unroll
    for (int i = 0; i < 4; i++) {
        unsigned h = pk2(v[2*i], v[2*i+1]);
        hw[i] = h;
        lw[i] = pk2(v[2*i] - lo_f(h), v[2*i+1] - hi_f(h));
    }
}
__device__ __forceinline__ void cpa16(unsigned d, const void* g) {
    asm volatile("cp.async.cg.shared.global [%0], [%1], 16;" :: "r"(d), "l"(g));
}
#define CP_COMMIT() asm volatile("cp.async.commit_group;" ::: "memory")
#define CP_WAIT1()  asm volatile("cp.async.wait_group 1;" ::: "memory")
#define CP_WAIT0()  asm volatile("cp.async.wait_group 0;" ::: "memory")

// ---------------------------------------------------------------------------
// Kernel 1: 1x1 conv qkv. grid (100, 2, 4)
// ---------------------------------------------------------------------------
__global__ __launch_bounds__(256) void qkv_kernel(
    const float* __restrict__ x, const float* __restrict__ w, const float* __restrict__ bias)
{
    __shared__ float ws[64][100];
    __shared__ float xs[64][64];
    const int b = blockIdx.z, half = blockIdx.y, n0 = blockIdx.x * 64;
    const int tid = threadIdx.x, obase = half * 96;

    for (int idx = tid; idx < 96 * 64; idx += 256) {
        int o = idx >> 6, c = idx & 63;
        ws[c][o] = w[(size_t)(obase + o) * 64 + c];
    }
    for (int idx = tid; idx < 64 * 64; idx += 256) {
        int c = idx >> 6, p = idx & 63;
        xs[c][p] = x[((size_t)b * 64 + c) * NN + n0 + p];
    }
    __syncthreads();

    const int p = tid & 63, o0 = (tid >> 6) * 24;
    float acc[24];
#pragma unroll
    for (int j = 0; j < 24; j++) acc[j] = 0.f;
#pragma unroll 4
    for (int c = 0; c < 64; c++) {
        float xv = xs[c][p];
#pragma unroll
        for (int j4 = 0; j4 < 24; j4 += 4) {
            float4 wv = *(const float4*)&ws[c][o0 + j4];
            acc[j4+0] += xv * wv.x; acc[j4+1] += xv * wv.y;
            acc[j4+2] += xv * wv.z; acc[j4+3] += xv * wv.w;
        }
    }
    const int n = n0 + p, h = n / 80, wq = n % 80, nt = wq * 80 + h;
#pragma unroll
    for (int j4 = 0; j4 < 24; j4 += 4) {
        const int o = obase + o0 + j4;
        float4 v4;
        v4.x = acc[j4+0] + bias[o+0]; v4.y = acc[j4+1] + bias[o+1];
        v4.z = acc[j4+2] + bias[o+2]; v4.w = acc[j4+3] + bias[o+3];
        if (o < 64) {
            *(float4*)&g_Q[((size_t)b*NN + nt)*64 + o] = v4;
        } else if (o < 128) {
            *(float4*)&g_Kc[((size_t)b*NN + n)*64 + (o-64)] = v4;
        } else {
            *(float4*)&g_V[((size_t)b*NN + nt)*64 + (o-128)] = v4;
        }
    }
}

// ---------------------------------------------------------------------------
// repack: Q/K bf16 hi/lo, V fp16 single; ldmatrix-swizzled. grid (100, 4)
// ---------------------------------------------------------------------------
__global__ __launch_bounds__(256) void repack_kernel() {
    const int kt = blockIdx.x, b = blockIdx.y, tid = threadIdx.x;
    uint4* dQ = g_Qt + (size_t)(b * 100 + kt) * 1024;
    uint4* dK = g_Kt + (size_t)(b * 100 + kt) * 1024;
    uint4* dV = g_Vt + (size_t)(b * 100 + kt) * 512;

    for (int u = tid; u < 512; u += 256) {
        const int r = u >> 3, cu = u & 7;
        const int du = r * 8 + (cu ^ (r & 7));
        {   // Q
            const float* s = g_Q + ((size_t)b * NN + kt * 64 + r) * 64 + cu * 8;
            float v[8];
            *(float4*)v = *(const float4*)s; *(float4*)(v + 4) = *(const float4*)(s + 4);
            uint4 hw, lw; cvt8(v, (unsigned*)&hw, (unsigned*)&lw);
            dQ[du] = hw; dQ[512 + du] = lw;
        }
        {   // K: key r -> m = kt*64+r, source row nt(m)
            const int m = kt * 64 + r;
            const int nt = (m % 80) * 80 + m / 80;
            const float* s = g_Q + ((size_t)b * NN + nt) * 64 + cu * 8;
            float v[8];
            *(float4*)v = *(const float4*)s; *(float4*)(v + 4) = *(const float4*)(s + 4);
            uint4 hw, lw; cvt8(v, (unsigned*)&hw, (unsigned*)&lw);
            dK[du] = hw; dK[512 + du] = lw;
        }
        {   // V fp16: row = ch r, keys cu*8..cu*8+7
            const float* s = g_V + ((size_t)b * NN + kt * 64 + cu * 8) * 64 + r;
            float v[8];
#pragma unroll
            for (int j = 0; j < 8; j++) v[j] = s[j * 64];
            uint4 hw; unsigned* hww = (unsigned*)&hw;
#pragma unroll
            for (int i = 0; i < 4; i++) hww[i] = pk2h(v[2*i], v[2*i+1]);
            dV[du] = hw;
        }
    }
}

// ---------------------------------------------------------------------------
// channel attention logits (unchanged)
// ---------------------------------------------------------------------------
__global__ __launch_bounds__(256) void chan_logits_kernel() {
    const int b = blockIdx.y, chunk = blockIdx.x, tid = threadIdx.x;
    const int tx = tid & 15, ty = tid >> 4;
    const float* __restrict__ Kc = g_Kc + (size_t)b * NN * CC;
    const float* __restrict__ Qm = g_Q  + (size_t)b * NN * CC;
    float acc[4][4];
#pragma unroll
    for (int i = 0; i < 4; i++)
#pragma unroll
        for (int j = 0; j < 4; j++) acc[i][j] = 0.f;
    const int m0 = chunk * 200;
#pragma unroll 2
    for (int m = m0; m < m0 + 200; m++) {
        float4 kv4 = *(const float4*)(Kc + (size_t)m*64 + ty*4);
        float4 qv4 = *(const float4*)(Qm + (size_t)m*64 + tx*4);
        float kv[4] = {kv4.x, kv4.y, kv4.z, kv4.w};
        float qv[4] = {qv4.x, qv4.y, qv4.z, qv4.w};
#pragma unroll
        for (int i = 0; i < 4; i++)
#pragma unroll
            for (int j = 0; j < 4; j++) acc[i][j] += kv[i] * qv[j];
    }
    float* Lp = g_Lp + ((size_t)b*32 + chunk) * 64 * 64;
#pragma unroll
    for (int i = 0; i < 4; i++)
        *(float4*)(Lp + (size_t)(ty*4 + i)*64 + tx*4) =
            make_float4(acc[i][0], acc[i][1], acc[i][2], acc[i][3]);
}

// ---------------------------------------------------------------------------
// parallel reduce + softmax. grid (64 rows, 4 b), 64 thr (thread = column)
// ---------------------------------------------------------------------------
__global__ void chan_softmax_kernel() {
    __shared__ float red[2], rs[2];
    const int c = blockIdx.x, b = blockIdx.y, j = threadIdx.x;
    float s = 0.f;
#pragma unroll
    for (int ch = 0; ch < 32; ch++)
        s += g_Lp[(((size_t)b * 32 + ch) * 64 + c) * 64 + j];
    float m = s;
#pragma unroll
    for (int o = 16; o; o >>= 1) m = fmaxf(m, __shfl_xor_sync(0xffffffffu, m, o));
    if ((j & 31) == 0) red[j >> 5] = m;
    __syncthreads();
    m = fmaxf(red[0], red[1]);
    const float e = ex2f((s - m) * 1.4426950408889634f);
    float t = e;
#pragma unroll
    for (int o = 16; o; o >>= 1) t += __shfl_xor_sync(0xffffffffu, t, o);
    if ((j & 31) == 0) rs[j >> 5] = t;
    __syncthreads();
    g_ma[((size_t)b * 64 + c) * 64 + j] = e / (rs[0] + rs[1]);
}

// ---------------------------------------------------------------------------
// warp-MMA flash v5 (unchanged mainloop), epilogue stores fp16 partials.
// grid (50, 4, 4), 128 thr / 4 warps, 128 rows/CTA, 25 key-tiles, 2-stage.
// smem (80KB): Qh 0, Ql 16K; stage s at 32K + s*24K: Kh(8K) Kl(8K) Vf16(8K)
// ---------------------------------------------------------------------------
__global__ __launch_bounds__(128, 2) void flash_wm5() {
    extern __shared__ char smc[];
    const unsigned sb = smem_u32(smc);
    const int rt = blockIdx.x, quarter = blockIdx.y, b = blockIdx.z;
    const int tid = threadIdx.x, warp = tid >> 5, lane = tid & 31;
    const int g = lane >> 2, t = lane & 3;
    const int kt0 = quarter * 25;
    const float L2E = 1.4426950408889634f;

    // ---- stage-0 prefetch ----
    {
        const uint4* sk = g_Kt + (size_t)(b * 100 + kt0) * 1024;
        const uint4* sv = g_Vt + (size_t)(b * 100 + kt0) * 512;
        const unsigned base = sb + 32768u;
#pragma unroll
        for (int j = 0; j < 8; j++) { int i = tid + j * 128; cpa16(base + i * 16, sk + i); }
#pragma unroll
        for (int j = 0; j < 4; j++) { int i = tid + j * 128; cpa16(base + 16384u + i * 16, sv + i); }
        CP_COMMIT();
    }
    // ---- Q tiles copy (2 x 64 rows, hi+lo) ----
    {
        uint4* dh = (uint4*)smc;
        uint4* dl = (uint4*)(smc + 16384);
#pragma unroll
        for (int j = 0; j < 2; j++) {
            const uint4* src = g_Qt + (size_t)(b * 100 + rt * 2 + j) * 1024;
#pragma unroll
            for (int i = 0; i < 4; i++) {
                int u = tid + i * 128;
                dh[j * 512 + u] = src[u];
                dl[j * 512 + u] = src[512 + u];
            }
        }
    }

    const int subA = lane >> 3, lrA = lane & 7;
    const int rAb = ((subA & 1) << 3) + lrA;   // row offset within 16-row half
    const int cbA = (subA >> 1) << 4;
    const int rB16 = ((lane >> 4) << 3) + (lane & 7);
    const int bsel = ((lane >> 3) & 1) << 4;

    float O[2][8][4];
#pragma unroll
    for (int h = 0; h < 2; h++)
#pragma unroll
        for (int nb = 0; nb < 8; nb++)
#pragma unroll
            for (int j = 0; j < 4; j++) O[h][nb][j] = 0.f;
    float dd[2][2], mm[2][2];
#pragma unroll
    for (int h = 0; h < 2; h++) { dd[h][0] = dd[h][1] = 0.f; mm[h][0] = mm[h][1] = -INFINITY; }

    for (int it = 0; it < 25; it++) {
        const unsigned koff = 32768u + (unsigned)(it & 1) * 24576u;
        const unsigned voff = koff + 16384u;
        __syncthreads();
        if (it + 1 < 25) {
            const uint4* sk = g_Kt + (size_t)(b * 100 + kt0 + it + 1) * 1024;
            const uint4* sv = g_Vt + (size_t)(b * 100 + kt0 + it + 1) * 512;
            const unsigned nbase = sb + 32768u + (unsigned)((it + 1) & 1) * 24576u;
#pragma unroll
            for (int j = 0; j < 8; j++) { int i = tid + j * 128; cpa16(nbase + i * 16, sk + i); }
#pragma unroll
            for (int j = 0; j < 4; j++) { int i = tid + j * 128; cpa16(nbase + 16384u + i * 16, sv + i); }
            CP_COMMIT();
            CP_WAIT1();
        } else {
            CP_WAIT0();
        }
        __syncthreads();

        // ---- S = Q K^T (3-way bf16 split, K frags shared by both halves) ----
        float S[2][8][4];
#pragma unroll
        for (int h = 0; h < 2; h++)
#pragma unroll
            for (int nb = 0; nb < 8; nb++)
#pragma unroll
                for (int j = 0; j < 4; j++) S[h][nb][j] = 0.f;

#pragma unroll
        for (int kc = 0; kc < 4; kc++) {
            unsigned qh[2][4], ql[2][4];
#pragma unroll
            for (int h = 0; h < 2; h++) {
                const int rA = warp * 32 + h * 16 + rAb;
                const unsigned aswz = (unsigned)((kc * 32 + cbA) ^ ((rA & 7) << 4));
                ldsm4(qh[h][0], qh[h][1], qh[h][2], qh[h][3], sb + 0u     + rA * 128 + aswz);
                ldsm4(ql[h][0], ql[h][1], ql[h][2], ql[h][3], sb + 16384u + rA * 128 + aswz);
            }
#pragma unroll
            for (int nbp = 0; nbp < 4; nbp++) {
                const int rB = nbp * 16 + rB16;
                const unsigned bswz = (unsigned)((kc * 32 + bsel) ^ ((rB & 7) << 4));
                const unsigned addr = sb + koff + rB * 128 + bswz;
                unsigned kh0, kh1, kh2, kh3, kl0, kl1, kl2, kl3;
                ldsm4(kh0, kh1, kh2, kh3, addr);
                ldsm4(kl0, kl1, kl2, kl3, addr + 8192u);
#pragma unroll
                for (int h = 0; h < 2; h++) {
                    mma_bf(S[h][2*nbp],   qh[h][0], qh[h][1], qh[h][2], qh[h][3], kh0, kh1);
                    mma_bf(S[h][2*nbp],   ql[h][0], ql[h][1], ql[h][2], ql[h][3], kh0, kh1);
                    mma_bf(S[h][2*nbp],   qh[h][0], qh[h][1], qh[h][2], qh[h][3], kl0, kl1);
                    mma_bf(S[h][2*nbp+1], qh[h][0], qh[h][1], qh[h][2], qh[h][3], kh2, kh3);
                    mma_bf(S[h][2*nbp+1], ql[h][0], ql[h][1], ql[h][2], ql[h][3], kh2, kh3);
                    mma_bf(S[h][2*nbp+1], qh[h][0], qh[h][1], qh[h][2], qh[h][3], kl2, kl3);
                }
            }
        }

        // ---- online softmax per half ----
        unsigned Ph[2][4][4];
#pragma unroll
        for (int h = 0; h < 2; h++) {
            float tm1 = -INFINITY, tm2 = -INFINITY;
#pragma unroll
            for (int nb = 0; nb < 8; nb++) {
                tm1 = fmaxf(tm1, fmaxf(S[h][nb][0], S[h][nb][1]));
                tm2 = fmaxf(tm2, fmaxf(S[h][nb][2], S[h][nb][3]));
            }
            tm1 = fmaxf(tm1, __shfl_xor_sync(0xffffffffu, tm1, 1));
            tm1 = fmaxf(tm1, __shfl_xor_sync(0xffffffffu, tm1, 2));
            tm2 = fmaxf(tm2, __shfl_xor_sync(0xffffffffu, tm2, 1));
            tm2 = fmaxf(tm2, __shfl_xor_sync(0xffffffffu, tm2, 2));
            const float m1n = fmaxf(mm[h][0], tm1), m2n = fmaxf(mm[h][1], tm2);
            const float sc1 = ex2f((mm[h][0] - m1n) * L2E), sc2 = ex2f((mm[h][1] - m2n) * L2E);
            const float b1 = m1n * L2E, b2 = m2n * L2E;
            mm[h][0] = m1n; mm[h][1] = m2n;

            float ds1 = 0.f, ds2 = 0.f;
#pragma unroll
            for (int nb = 0; nb < 8; nb++) {
                float e0 = ex2f(fmaf(S[h][nb][0], L2E, -b1));
                float e1 = ex2f(fmaf(S[h][nb][1], L2E, -b1));
                float e2 = ex2f(fmaf(S[h][nb][2], L2E, -b2));
                float e3 = ex2f(fmaf(S[h][nb][3], L2E, -b2));
                ds1 += e0 + e1; ds2 += e2 + e3;
                const int kc = nb >> 1, o = (nb & 1) << 1;
                Ph[h][kc][o]     = pk2h(e0, e1);
                Ph[h][kc][o + 1] = pk2h(e2, e3);
            }
            dd[h][0] = dd[h][0] * sc1 + ds1;
            dd[h][1] = dd[h][1] * sc2 + ds2;
#pragma unroll
            for (int nb = 0; nb < 8; nb++) {
                O[h][nb][0] *= sc1; O[h][nb][1] *= sc1;
                O[h][nb][2] *= sc2; O[h][nb][3] *= sc2;
            }
        }

        // ---- O += P V (fp16, V frags shared by both halves) ----
#pragma unroll
        for (int kc = 0; kc < 4; kc++) {
#pragma unroll
            for (int nbp = 0; nbp < 4; nbp++) {
                const int rB = nbp * 16 + rB16;
                const unsigned bswz = (unsigned)((kc * 32 + bsel) ^ ((rB & 7) << 4));
                unsigned v0, v1, v2, v3;
                ldsm4(v0, v1, v2, v3, sb + voff + rB * 128 + bswz);
#pragma unroll
                for (int h = 0; h < 2; h++) {
                    mma_h(O[h][2*nbp],   Ph[h][kc][0], Ph[h][kc][1], Ph[h][kc][2], Ph[h][kc][3], v0, v1);
                    mma_h(O[h][2*nbp+1], Ph[h][kc][0], Ph[h][kc][1], Ph[h][kc][2], Ph[h][kc][3], v2, v3);
                }
            }
        }
    }

    // ---- epilogue per half: reduce denominators, store (m, d, O-fp16) ----
    const int cta = (b * 4 + quarter) * 50 + rt;
    unsigned* Uh = g_Oph + (size_t)cta * 4096;
#pragma unroll
    for (int h = 0; h < 2; h++) {
        float d1 = dd[h][0], d2 = dd[h][1];
        d1 += __shfl_xor_sync(0xffffffffu, d1, 1);
        d1 += __shfl_xor_sync(0xffffffffu, d1, 2);
        d2 += __shfl_xor_sync(0xffffffffu, d2, 1);
        d2 += __shfl_xor_sync(0xffffffffu, d2, 2);
        const int r0 = warp * 32 + h * 16;
        if (t == 0) {
            g_Od[cta * 128 + r0 + g]     = d1;
            g_Od[cta * 128 + r0 + g + 8] = d2;
            g_Om[cta * 128 + r0 + g]     = mm[h][0];
            g_Om[cta * 128 + r0 + g + 8] = mm[h][1];
        }
#pragma unroll
        for (int nb = 0; nb < 8; nb++) {
            Uh[(r0 + g) * 32 + nb * 4 + t]     = pk2h(O[h][nb][0], O[h][nb][1]);
            Uh[(r0 + g + 8) * 32 + nb * 4 + t] = pk2h(O[h][nb][2], O[h][nb][3]);
        }
    }
}

// ---------------------------------------------------------------------------
// fused channel-apply + spatial combine. grid (100, 4), 256 thr.
// out[ch][px] = chanO[ch][px] + (sum_q w_q U_q[px][ch]) / den[px]
// ---------------------------------------------------------------------------
__global__ __launch_bounds__(256) void chan_spatial_kernel(float* __restrict__ out) {
    __shared__ float vs[64][64];
    __shared__ float mas[64][65];
    __shared__ float sO[64 * 65];   // [px][ch], spatial normalized
    __shared__ float sden[64];
    __shared__ float sw[4][64];
    const int rt64 = blockIdx.x, b = blockIdx.y, tid = threadIdx.x;
    const int tx = tid & 15, ty = tid >> 4;
    const int n0 = rt64 * 64;
    const int rtb = rt64 >> 1, ro = (rt64 & 1) * 64;
    const float L2E = 1.4426950408889634f;
    int c_q[4];
#pragma unroll
    for (int q = 0; q < 4; q++) c_q[q] = (b * 4 + q) * 50 + rtb;

    // per-row merge weights + denominator
    if (tid < 64) {
        float mq[4], dq[4], M = -INFINITY;
#pragma unroll
        for (int q = 0; q < 4; q++) {
            mq[q] = g_Om[c_q[q] * 128 + ro + tid];
            dq[q] = g_Od[c_q[q] * 128 + ro + tid];
            M = fmaxf(M, mq[q]);
        }
        float den = 0.f;
#pragma unroll
        for (int q = 0; q < 4; q++) {
            float wq = ex2f((mq[q] - M) * L2E);
            sw[q][tid] = wq;
            den += wq * dq[q];
        }
        sden[tid] = 1.f / den;
    }
    // mas[cp][c] = g_ma[b][c][cp]
    for (int idx = tid; idx < 4096; idx += 256) {
        int c = idx >> 6, cp = idx & 63;
        mas[cp][c] = g_ma[((size_t)b * 64 + c) * 64 + cp];
    }
    // vs[cp][p] = g_V[b][nt(n0+p)][cp]
    {
        int p = tid >> 2, cb = (tid & 3) * 16;
        int n = n0 + p, nt = (n % 80) * 80 + n / 80;
        const float* vp = g_V + ((size_t)b * NN + nt) * 64 + cb;
#pragma unroll
        for (int k = 0; k < 4; k++) {
            float4 v4 = *(const float4*)(vp + 4 * k);
            vs[cb+4*k+0][p] = v4.x; vs[cb+4*k+1][p] = v4.y;
            vs[cb+4*k+2][p] = v4.z; vs[cb+4*k+3][p] = v4.w;
        }
    }
    __syncthreads();

    // spatial: merge 4 quarters (fp16 partials) into sO
#pragma unroll
    for (int i = 0; i < 8; i++) {
        int u = tid + i * 256;           // 2048 = 64 px * 32 ch-pairs
        int r = u >> 5, cp2 = u & 31;
        float s0 = 0.f, s1 = 0.f;
#pragma unroll
        for (int q = 0; q < 4; q++) {
            unsigned pk = g_Oph[(size_t)c_q[q] * 4096 + (ro + r) * 32 + cp2];
            __half2 h2 = *reinterpret_cast<__half2*>(&pk);
            float2 f = __half22float2(h2);
            s0 += sw[q][r] * f.x;
            s1 += sw[q][r] * f.y;
        }
        sO[r * 65 + cp2 * 2]     = s0 * sden[r];
        sO[r * 65 + cp2 * 2 + 1] = s1 * sden[r];
    }

    // channel attention matmul (registers)
    float acc[4][4];
#pragma unroll
    for (int i = 0; i < 4; i++)
#pragma unroll
        for (int j = 0; j < 4; j++) acc[i][j] = 0.f;
#pragma unroll 4
    for (int cp = 0; cp < 64; cp++) {
        float mv[4];
#pragma unroll
        for (int i = 0; i < 4; i++) mv[i] = mas[cp][ty * 4 + i];
        float4 v4 = *(const float4*)&vs[cp][tx * 4];
        float vv[4] = {v4.x, v4.y, v4.z, v4.w};
#pragma unroll
        for (int i = 0; i < 4; i++)
#pragma unroll
            for (int j = 0; j < 4; j++) acc[i][j] += mv[i] * vv[j];
    }
    __syncthreads();

    // write out = chan + spatial (single store)
#pragma unroll
    for (int i = 0; i < 4; i++) {
        const int ch = ty * 4 + i;
        float4 o4;
        o4.x = acc[i][0] + sO[(tx * 4 + 0) * 65 + ch];
        o4.y = acc[i][1] + sO[(tx * 4 + 1) * 65 + ch];
        o4.z = acc[i][2] + sO[(tx * 4 + 2) * 65 + ch];
        o4.w = acc[i][3] + sO[(tx * 4 + 3) * 65 + ch];
        *(float4*)(out + ((size_t)b * 64 + ch) * NN + n0 + tx * 4) = o4;
    }
}

// ---------------------------------------------------------------------------
extern "C" void kernel_launch(void* const* d_in, const int* in_sizes, int n_in,
                              void* d_out, int out_size)
{
    const float* x    = (const float*)d_in[0];
    const float* w    = (const float*)d_in[1];
    const float* bias = (const float*)d_in[2];
    float* out = (float*)d_out;

    const int fsm = 32768 + 2 * 24576;  // 81920 B
    cudaFuncSetAttribute(flash_wm5, cudaFuncAttributeMaxDynamicSharedMemorySize, fsm);

    qkv_kernel<<<dim3(100, 2, 4), 256>>>(x, w, bias);
    repack_kernel<<<dim3(100, 4), 256>>>();
    chan_logits_kernel<<<dim3(32, 4), 256>>>();
    chan_softmax_kernel<<<dim3(64, 4), 64>>>();
    flash_wm5<<<dim3(50, 4, 4), 128, fsm>>>();
    chan_spatial_kernel<<<dim3(100, 4), 256>>>(out);
}

// round 13
// speedup vs baseline: 6.8424x; 1.0003x over previous
#include <cuda_runtime.h>
#include <cuda_bf16.h>
#include <cuda_fp16.h>
#include <math.h>
#include <stdint.h>

#define BB 4
#define CC 64
#define NN 6400

// ---------------- scratch ----------------
__device__ float g_Q [BB * NN * CC];   // [b][n][c], row n = q(h=n%80, w=n/80)
__device__ float g_V [BB * NN * CC];   // [b][m][c], row m = v(h=m%80, w=m/80)
__device__ float g_Kc[BB * NN * CC];   // [b][m][c], k natural order
__device__ float g_Lp[BB * 32 * CC * CC];
__device__ float g_ma[BB * CC * CC];
// MMA tiles, ldmatrix-swizzled
__device__ uint4 g_Qt[BB * 100 * 1024];  // bf16 hi(512)+lo(512): [row64][ch64]
__device__ uint4 g_Kt[BB * 100 * 1024];  // bf16 hi+lo: [key64][ch64]
__device__ uint4 g_Vt[BB * 100 * 512];   // fp16 single: [ch64][key64]
// split-kv partials: 800 CTAs x 128 rows; O stored fp16x2 (ch pairs)
__device__ unsigned g_Oph[800 * 128 * 32];
__device__ float g_Od[800 * 128];
__device__ float g_Om[800 * 128];

// ---------------- helpers ----------------
__device__ __forceinline__ unsigned smem_u32(const void* p) {
    unsigned a;
    asm("{ .reg .u64 t; cvta.to.shared.u64 t, %1; cvt.u32.u64 %0, t; }" : "=r"(a) : "l"(p));
    return a;
}
__device__ __forceinline__ void ldsm4(unsigned& r0, unsigned& r1, unsigned& r2, unsigned& r3, unsigned a) {
    asm volatile("ldmatrix.sync.aligned.m8n8.x4.shared.b16 {%0,%1,%2,%3}, [%4];"
                 : "=r"(r0), "=r"(r1), "=r"(r2), "=r"(r3) : "r"(a));
}
__device__ __forceinline__ void mma_bf(float* c,
                                       unsigned a0, unsigned a1, unsigned a2, unsigned a3,
                                       unsigned b0, unsigned b1) {
    asm volatile("mma.sync.aligned.m16n8k16.row.col.f32.bf16.bf16.f32 "
                 "{%0,%1,%2,%3}, {%4,%5,%6,%7}, {%8,%9}, {%0,%1,%2,%3};"
                 : "+f"(c[0]), "+f"(c[1]), "+f"(c[2]), "+f"(c[3])
                 : "r"(a0), "r"(a1), "r"(a2), "r"(a3), "r"(b0), "r"(b1));
}
__device__ __forceinline__ void mma_h(float* c,
                                      unsigned a0, unsigned a1, unsigned a2, unsigned a3,
                                      unsigned b0, unsigned b1) {
    asm volatile("mma.sync.aligned.m16n8k16.row.col.f32.f16.f16.f32 "
                 "{%0,%1,%2,%3}, {%4,%5,%6,%7}, {%8,%9}, {%0,%1,%2,%3};"
                 : "+f"(c[0]), "+f"(c[1]), "+f"(c[2]), "+f"(c[3])
                 : "r"(a0), "r"(a1), "r"(a2), "r"(a3), "r"(b0), "r"(b1));
}
__device__ __forceinline__ unsigned pk2(float lo, float hi) {  // bf16x2, lower = lo
    unsigned r; asm("cvt.rn.bf16x2.f32 %0, %1, %2;" : "=r"(r) : "f"(hi), "f"(lo)); return r;
}
__device__ __forceinline__ unsigned pk2h(float lo, float hi) { // f16x2, lower = lo
    unsigned r; asm("cvt.rn.f16x2.f32 %0, %1, %2;" : "=r"(r) : "f"(hi), "f"(lo)); return r;
}
__device__ __forceinline__ float lo_f(unsigned h) { return __uint_as_float(h << 16); }
__device__ __forceinline__ float hi_f(unsigned h) { return __uint_as_float(h & 0xffff0000u); }
__device__ __forceinline__ float ex2f(float x) {
    float r; asm("ex2.approx.ftz.f32 %0, %1;" : "=f"(r) : "f"(x)); return r;
}
__device__ __forceinline__ void cvt8(const float* v, unsigned* hw, unsigned* lw) {
#pragma unroll
    for (int i = 0; i < 4; i++) {
        unsigned h = pk2(v[2*i], v[2*i+1]);
        hw[i] = h;
        lw[i] = pk2(v[2*i] - lo_f(h), v[2*i+1] - hi_f(h));
    }
}
__device__ __forceinline__ void cpa16(unsigned d, const void* g) {
    asm volatile("cp.async.cg.shared.global [%0], [%1], 16;" :: "r"(d), "l"(g));
}
#define CP_COMMIT() asm volatile("cp.async.commit_group;" ::: "memory")
#define CP_WAIT1()  asm volatile("cp.async.wait_group 1;" ::: "memory")
#define CP_WAIT0()  asm volatile("cp.async.wait_group 0;" ::: "memory")

// ---------------------------------------------------------------------------
// Kernel 1: 1x1 conv qkv. grid (100, 2, 4)
// ---------------------------------------------------------------------------
__global__ __launch_bounds__(256) void qkv_kernel(
    const float* __restrict__ x, const float* __restrict__ w, const float* __restrict__ bias)
{
    __shared__ float ws[64][100];
    __shared__ float xs[64][64];
    const int b = blockIdx.z, half = blockIdx.y, n0 = blockIdx.x * 64;
    const int tid = threadIdx.x, obase = half * 96;

    for (int idx = tid; idx < 96 * 64; idx += 256) {
        int o = idx >> 6, c = idx & 63;
        ws[c][o] = w[(size_t)(obase + o) * 64 + c];
    }
    for (int idx = tid; idx < 64 * 64; idx += 256) {
        int c = idx >> 6, p = idx & 63;
        xs[c][p] = x[((size_t)b * 64 + c) * NN + n0 + p];
    }
    __syncthreads();

    const int p = tid & 63, o0 = (tid >> 6) * 24;
    float acc[24];
#pragma unroll
    for (int j = 0; j < 24; j++) acc[j] = 0.f;
#pragma unroll 4
    for (int c = 0; c < 64; c++) {
        float xv = xs[c][p];
#pragma unroll
        for (int j4 = 0; j4 < 24; j4 += 4) {
            float4 wv = *(const float4*)&ws[c][o0 + j4];
            acc[j4+0] += xv * wv.x; acc[j4+1] += xv * wv.y;
            acc[j4+2] += xv * wv.z; acc[j4+3] += xv * wv.w;
        }
    }
    const int n = n0 + p, h = n / 80, wq = n % 80, nt = wq * 80 + h;
#pragma unroll
    for (int j4 = 0; j4 < 24; j4 += 4) {
        const int o = obase + o0 + j4;
        float4 v4;
        v4.x = acc[j4+0] + bias[o+0]; v4.y = acc[j4+1] + bias[o+1];
        v4.z = acc[j4+2] + bias[o+2]; v4.w = acc[j4+3] + bias[o+3];
        if (o < 64) {
            *(float4*)&g_Q[((size_t)b*NN + nt)*64 + o] = v4;
        } else if (o < 128) {
            *(float4*)&g_Kc[((size_t)b*NN + n)*64 + (o-64)] = v4;
        } else {
            *(float4*)&g_V[((size_t)b*NN + nt)*64 + (o-128)] = v4;
        }
    }
}

// ---------------------------------------------------------------------------
// repack: Q/K bf16 hi/lo, V fp16 single; ldmatrix-swizzled. grid (100, 4)
// ---------------------------------------------------------------------------
__global__ __launch_bounds__(256) void repack_kernel() {
    const int kt = blockIdx.x, b = blockIdx.y, tid = threadIdx.x;
    uint4* dQ = g_Qt + (size_t)(b * 100 + kt) * 1024;
    uint4* dK = g_Kt + (size_t)(b * 100 + kt) * 1024;
    uint4* dV = g_Vt + (size_t)(b * 100 + kt) * 512;

    for (int u = tid; u < 512; u += 256) {
        const int r = u >> 3, cu = u & 7;
        const int du = r * 8 + (cu ^ (r & 7));
        {   // Q
            const float* s = g_Q + ((size_t)b * NN + kt * 64 + r) * 64 + cu * 8;
            float v[8];
            *(float4*)v = *(const float4*)s; *(float4*)(v + 4) = *(const float4*)(s + 4);
            uint4 hw, lw; cvt8(v, (unsigned*)&hw, (unsigned*)&lw);
            dQ[du] = hw; dQ[512 + du] = lw;
        }
        {   // K: key r -> m = kt*64+r, source row nt(m)
            const int m = kt * 64 + r;
            const int nt = (m % 80) * 80 + m / 80;
            const float* s = g_Q + ((size_t)b * NN + nt) * 64 + cu * 8;
            float v[8];
            *(float4*)v = *(const float4*)s; *(float4*)(v + 4) = *(const float4*)(s + 4);
            uint4 hw, lw; cvt8(v, (unsigned*)&hw, (unsigned*)&lw);
            dK[du] = hw; dK[512 + du] = lw;
        }
        {   // V fp16: row = ch r, keys cu*8..cu*8+7
            const float* s = g_V + ((size_t)b * NN + kt * 64 + cu * 8) * 64 + r;
            float v[8];
#pragma unroll
            for (int j = 0; j < 8; j++) v[j] = s[j * 64];
            uint4 hw; unsigned* hww = (unsigned*)&hw;
#pragma unroll
            for (int i = 0; i < 4; i++) hww[i] = pk2h(v[2*i], v[2*i+1]);
            dV[du] = hw;
        }
    }
}

// ---------------------------------------------------------------------------
// channel attention logits (unchanged)
// ---------------------------------------------------------------------------
__global__ __launch_bounds__(256) void chan_logits_kernel() {
    const int b = blockIdx.y, chunk = blockIdx.x, tid = threadIdx.x;
    const int tx = tid & 15, ty = tid >> 4;
    const float* __restrict__ Kc = g_Kc + (size_t)b * NN * CC;
    const float* __restrict__ Qm = g_Q  + (size_t)b * NN * CC;
    float acc[4][4];
#pragma unroll
    for (int i = 0; i < 4; i++)
#pragma unroll
        for (int j = 0; j < 4; j++) acc[i][j] = 0.f;
    const int m0 = chunk * 200;
#pragma unroll 2
    for (int m = m0; m < m0 + 200; m++) {
        float4 kv4 = *(const float4*)(Kc + (size_t)m*64 + ty*4);
        float4 qv4 = *(const float4*)(Qm + (size_t)m*64 + tx*4);
        float kv[4] = {kv4.x, kv4.y, kv4.z, kv4.w};
        float qv[4] = {qv4.x, qv4.y, qv4.z, qv4.w};
#pragma unroll
        for (int i = 0; i < 4; i++)
#pragma unroll
            for (int j = 0; j < 4; j++) acc[i][j] += kv[i] * qv[j];
    }
    float* Lp = g_Lp + ((size_t)b*32 + chunk) * 64 * 64;
#pragma unroll
    for (int i = 0; i < 4; i++)
        *(float4*)(Lp + (size_t)(ty*4 + i)*64 + tx*4) =
            make_float4(acc[i][0], acc[i][1], acc[i][2], acc[i][3]);
}

// ---------------------------------------------------------------------------
// parallel reduce + softmax. grid (64 rows, 4 b), 64 thr (thread = column)
// ---------------------------------------------------------------------------
__global__ void chan_softmax_kernel() {
    __shared__ float red[2], rs[2];
    const int c = blockIdx.x, b = blockIdx.y, j = threadIdx.x;
    float s = 0.f;
#pragma unroll
    for (int ch = 0; ch < 32; ch++)
        s += g_Lp[(((size_t)b * 32 + ch) * 64 + c) * 64 + j];
    float m = s;
#pragma unroll
    for (int o = 16; o; o >>= 1) m = fmaxf(m, __shfl_xor_sync(0xffffffffu, m, o));
    if ((j & 31) == 0) red[j >> 5] = m;
    __syncthreads();
    m = fmaxf(red[0], red[1]);
    const float e = ex2f((s - m) * 1.4426950408889634f);
    float t = e;
#pragma unroll
    for (int o = 16; o; o >>= 1) t += __shfl_xor_sync(0xffffffffu, t, o);
    if ((j & 31) == 0) rs[j >> 5] = t;
    __syncthreads();
    g_ma[((size_t)b * 64 + c) * 64 + j] = e / (rs[0] + rs[1]);
}

// ---------------------------------------------------------------------------
// warp-MMA flash v6: pass-major MMA ordering (accumulator reuse distance 4).
// grid (50, 4, 4), 128 thr / 4 warps, 128 rows/CTA, 25 key-tiles, 2-stage.
// smem (80KB): Qh 0, Ql 16K; stage s at 32K + s*24K: Kh(8K) Kl(8K) Vf16(8K)
// ---------------------------------------------------------------------------
__global__ __launch_bounds__(128, 2) void flash_wm6() {
    extern __shared__ char smc[];
    const unsigned sb = smem_u32(smc);
    const int rt = blockIdx.x, quarter = blockIdx.y, b = blockIdx.z;
    const int tid = threadIdx.x, warp = tid >> 5, lane = tid & 31;
    const int g = lane >> 2, t = lane & 3;
    const int kt0 = quarter * 25;
    const float L2E = 1.4426950408889634f;

    // ---- stage-0 prefetch ----
    {
        const uint4* sk = g_Kt + (size_t)(b * 100 + kt0) * 1024;
        const uint4* sv = g_Vt + (size_t)(b * 100 + kt0) * 512;
        const unsigned base = sb + 32768u;
#pragma unroll
        for (int j = 0; j < 8; j++) { int i = tid + j * 128; cpa16(base + i * 16, sk + i); }
#pragma unroll
        for (int j = 0; j < 4; j++) { int i = tid + j * 128; cpa16(base + 16384u + i * 16, sv + i); }
        CP_COMMIT();
    }
    // ---- Q tiles copy (2 x 64 rows, hi+lo) ----
    {
        uint4* dh = (uint4*)smc;
        uint4* dl = (uint4*)(smc + 16384);
#pragma unroll
        for (int j = 0; j < 2; j++) {
            const uint4* src = g_Qt + (size_t)(b * 100 + rt * 2 + j) * 1024;
#pragma unroll
            for (int i = 0; i < 4; i++) {
                int u = tid + i * 128;
                dh[j * 512 + u] = src[u];
                dl[j * 512 + u] = src[512 + u];
            }
        }
    }

    const int subA = lane >> 3, lrA = lane & 7;
    const int rAb = ((subA & 1) << 3) + lrA;   // row offset within 16-row half
    const int cbA = (subA >> 1) << 4;
    const int rB16 = ((lane >> 4) << 3) + (lane & 7);
    const int bsel = ((lane >> 3) & 1) << 4;

    float O[2][8][4];
#pragma unroll
    for (int h = 0; h < 2; h++)
#pragma unroll
        for (int nb = 0; nb < 8; nb++)
#pragma unroll
            for (int j = 0; j < 4; j++) O[h][nb][j] = 0.f;
    float dd[2][2], mm[2][2];
#pragma unroll
    for (int h = 0; h < 2; h++) { dd[h][0] = dd[h][1] = 0.f; mm[h][0] = mm[h][1] = -INFINITY; }

    for (int it = 0; it < 25; it++) {
        const unsigned koff = 32768u + (unsigned)(it & 1) * 24576u;
        const unsigned voff = koff + 16384u;
        __syncthreads();
        if (it + 1 < 25) {
            const uint4* sk = g_Kt + (size_t)(b * 100 + kt0 + it + 1) * 1024;
            const uint4* sv = g_Vt + (size_t)(b * 100 + kt0 + it + 1) * 512;
            const unsigned nbase = sb + 32768u + (unsigned)((it + 1) & 1) * 24576u;
#pragma unroll
            for (int j = 0; j < 8; j++) { int i = tid + j * 128; cpa16(nbase + i * 16, sk + i); }
#pragma unroll
            for (int j = 0; j < 4; j++) { int i = tid + j * 128; cpa16(nbase + 16384u + i * 16, sv + i); }
            CP_COMMIT();
            CP_WAIT1();
        } else {
            CP_WAIT0();
        }
        __syncthreads();

        // ---- S = Q K^T (3-way bf16 split, pass-major: acc reuse distance 4) ----
        float S[2][8][4];
#pragma unroll
        for (int h = 0; h < 2; h++)
#pragma unroll
            for (int nb = 0; nb < 8; nb++)
#pragma unroll
                for (int j = 0; j < 4; j++) S[h][nb][j] = 0.f;

#pragma unroll
        for (int kc = 0; kc < 4; kc++) {
            unsigned qh[2][4], ql[2][4];
#pragma unroll
            for (int h = 0; h < 2; h++) {
                const int rA = warp * 32 + h * 16 + rAb;
                const unsigned aswz = (unsigned)((kc * 32 + cbA) ^ ((rA & 7) << 4));
                ldsm4(qh[h][0], qh[h][1], qh[h][2], qh[h][3], sb + 0u     + rA * 128 + aswz);
                ldsm4(ql[h][0], ql[h][1], ql[h][2], ql[h][3], sb + 16384u + rA * 128 + aswz);
            }
#pragma unroll
            for (int nbp = 0; nbp < 4; nbp++) {
                const int rB = nbp * 16 + rB16;
                const unsigned bswz = (unsigned)((kc * 32 + bsel) ^ ((rB & 7) << 4));
                const unsigned addr = sb + koff + rB * 128 + bswz;
                unsigned kh0, kh1, kh2, kh3, kl0, kl1, kl2, kl3;
                ldsm4(kh0, kh1, kh2, kh3, addr);
                ldsm4(kl0, kl1, kl2, kl3, addr + 8192u);
                // pass 1: qh * kh  (4 independent accs)
                mma_bf(S[0][2*nbp],   qh[0][0], qh[0][1], qh[0][2], qh[0][3], kh0, kh1);
                mma_bf(S[0][2*nbp+1], qh[0][0], qh[0][1], qh[0][2], qh[0][3], kh2, kh3);
                mma_bf(S[1][2*nbp],   qh[1][0], qh[1][1], qh[1][2], qh[1][3], kh0, kh1);
                mma_bf(S[1][2*nbp+1], qh[1][0], qh[1][1], qh[1][2], qh[1][3], kh2, kh3);
                // pass 2: ql * kh
                mma_bf(S[0][2*nbp],   ql[0][0], ql[0][1], ql[0][2], ql[0][3], kh0, kh1);
                mma_bf(S[0][2*nbp+1], ql[0][0], ql[0][1], ql[0][2], ql[0][3], kh2, kh3);
                mma_bf(S[1][2*nbp],   ql[1][0], ql[1][1], ql[1][2], ql[1][3], kh0, kh1);
                mma_bf(S[1][2*nbp+1], ql[1][0], ql[1][1], ql[1][2], ql[1][3], kh2, kh3);
                // pass 3: qh * kl
                mma_bf(S[0][2*nbp],   qh[0][0], qh[0][1], qh[0][2], qh[0][3], kl0, kl1);
                mma_bf(S[0][2*nbp+1], qh[0][0], qh[0][1], qh[0][2], qh[0][3], kl2, kl3);
                mma_bf(S[1][2*nbp],   qh[1][0], qh[1][1], qh[1][2], qh[1][3], kl0, kl1);
                mma_bf(S[1][2*nbp+1], qh[1][0], qh[1][1], qh[1][2], qh[1][3], kl2, kl3);
            }
        }

        // ---- online softmax per half ----
        unsigned Ph[2][4][4];
#pragma unroll
        for (int h = 0; h < 2; h++) {
            float tm1 = -INFINITY, tm2 = -INFINITY;
#pragma unroll
            for (int nb = 0; nb < 8; nb++) {
                tm1 = fmaxf(tm1, fmaxf(S[h][nb][0], S[h][nb][1]));
                tm2 = fmaxf(tm2, fmaxf(S[h][nb][2], S[h][nb][3]));
            }
            tm1 = fmaxf(tm1, __shfl_xor_sync(0xffffffffu, tm1, 1));
            tm1 = fmaxf(tm1, __shfl_xor_sync(0xffffffffu, tm1, 2));
            tm2 = fmaxf(tm2, __shfl_xor_sync(0xffffffffu, tm2, 1));
            tm2 = fmaxf(tm2, __shfl_xor_sync(0xffffffffu, tm2, 2));
            const float m1n = fmaxf(mm[h][0], tm1), m2n = fmaxf(mm[h][1], tm2);
            const float sc1 = ex2f((mm[h][0] - m1n) * L2E), sc2 = ex2f((mm[h][1] - m2n) * L2E);
            const float b1 = m1n * L2E, b2 = m2n * L2E;
            mm[h][0] = m1n; mm[h][1] = m2n;

            float ds1 = 0.f, ds2 = 0.f;
#pragma unroll
            for (int nb = 0; nb < 8; nb++) {
                float e0 = ex2f(fmaf(S[h][nb][0], L2E, -b1));
                float e1 = ex2f(fmaf(S[h][nb][1], L2E, -b1));
                float e2 = ex2f(fmaf(S[h][nb][2], L2E, -b2));
                float e3 = ex2f(fmaf(S[h][nb][3], L2E, -b2));
                ds1 += e0 + e1; ds2 += e2 + e3;
                const int kc = nb >> 1, o = (nb & 1) << 1;
                Ph[h][kc][o]     = pk2h(e0, e1);
                Ph[h][kc][o + 1] = pk2h(e2, e3);
            }
            dd[h][0] = dd[h][0] * sc1 + ds1;
            dd[h][1] = dd[h][1] * sc2 + ds2;
#pragma unroll
            for (int nb = 0; nb < 8; nb++) {
                O[h][nb][0] *= sc1; O[h][nb][1] *= sc1;
                O[h][nb][2] *= sc2; O[h][nb][3] *= sc2;
            }
        }

        // ---- O += P V (fp16, V frags shared; acc distance 4) ----
#pragma unroll
        for (int kc = 0; kc < 4; kc++) {
#pragma unroll
            for (int nbp = 0; nbp < 4; nbp++) {
                const int rB = nbp * 16 + rB16;
                const unsigned bswz = (unsigned)((kc * 32 + bsel) ^ ((rB & 7) << 4));
                unsigned v0, v1, v2, v3;
                ldsm4(v0, v1, v2, v3, sb + voff + rB * 128 + bswz);
                mma_h(O[0][2*nbp],   Ph[0][kc][0], Ph[0][kc][1], Ph[0][kc][2], Ph[0][kc][3], v0, v1);
                mma_h(O[0][2*nbp+1], Ph[0][kc][0], Ph[0][kc][1], Ph[0][kc][2], Ph[0][kc][3], v2, v3);
                mma_h(O[1][2*nbp],   Ph[1][kc][0], Ph[1][kc][1], Ph[1][kc][2], Ph[1][kc][3], v0, v1);
                mma_h(O[1][2*nbp+1], Ph[1][kc][0], Ph[1][kc][1], Ph[1][kc][2], Ph[1][kc][3], v2, v3);
            }
        }
    }

    // ---- epilogue per half: reduce denominators, store (m, d, O-fp16) ----
    const int cta = (b * 4 + quarter) * 50 + rt;
    unsigned* Uh = g_Oph + (size_t)cta * 4096;
#pragma unroll
    for (int h = 0; h < 2; h++) {
        float d1 = dd[h][0], d2 = dd[h][1];
        d1 += __shfl_xor_sync(0xffffffffu, d1, 1);
        d1 += __shfl_xor_sync(0xffffffffu, d1, 2);
        d2 += __shfl_xor_sync(0xffffffffu, d2, 1);
        d2 += __shfl_xor_sync(0xffffffffu, d2, 2);
        const int r0 = warp * 32 + h * 16;
        if (t == 0) {
            g_Od[cta * 128 + r0 + g]     = d1;
            g_Od[cta * 128 + r0 + g + 8] = d2;
            g_Om[cta * 128 + r0 + g]     = mm[h][0];
            g_Om[cta * 128 + r0 + g + 8] = mm[h][1];
        }
#pragma unroll
        for (int nb = 0; nb < 8; nb++) {
            Uh[(r0 + g) * 32 + nb * 4 + t]     = pk2h(O[h][nb][0], O[h][nb][1]);
            Uh[(r0 + g + 8) * 32 + nb * 4 + t] = pk2h(O[h][nb][2], O[h][nb][3]);
        }
    }
}

// ---------------------------------------------------------------------------
// fused channel-apply + spatial combine. grid (100, 4), 256 thr.
// ---------------------------------------------------------------------------
__global__ __launch_bounds__(256) void chan_spatial_kernel(float* __restrict__ out) {
    __shared__ float vs[64][64];
    __shared__ float mas[64][65];
    __shared__ float sO[64 * 65];   // [px][ch], spatial normalized
    __shared__ float sden[64];
    __shared__ float sw[4][64];
    const int rt64 = blockIdx.x, b = blockIdx.y, tid = threadIdx.x;
    const int tx = tid & 15, ty = tid >> 4;
    const int n0 = rt64 * 64;
    const int rtb = rt64 >> 1, ro = (rt64 & 1) * 64;
    const float L2E = 1.4426950408889634f;
    int c_q[4];
#pragma unroll
    for (int q = 0; q < 4; q++) c_q[q] = (b * 4 + q) * 50 + rtb;

    if (tid < 64) {
        float mq[4], dq[4], M = -INFINITY;
#pragma unroll
        for (int q = 0; q < 4; q++) {
            mq[q] = g_Om[c_q[q] * 128 + ro + tid];
            dq[q] = g_Od[c_q[q] * 128 + ro + tid];
            M = fmaxf(M, mq[q]);
        }
        float den = 0.f;
#pragma unroll
        for (int q = 0; q < 4; q++) {
            float wq = ex2f((mq[q] - M) * L2E);
            sw[q][tid] = wq;
            den += wq * dq[q];
        }
        sden[tid] = 1.f / den;
    }
    for (int idx = tid; idx < 4096; idx += 256) {
        int c = idx >> 6, cp = idx & 63;
        mas[cp][c] = g_ma[((size_t)b * 64 + c) * 64 + cp];
    }
    {
        int p = tid >> 2, cb = (tid & 3) * 16;
        int n = n0 + p, nt = (n % 80) * 80 + n / 80;
        const float* vp = g_V + ((size_t)b * NN + nt) * 64 + cb;
#pragma unroll
        for (int k = 0; k < 4; k++) {
            float4 v4 = *(const float4*)(vp + 4 * k);
            vs[cb+4*k+0][p] = v4.x; vs[cb+4*k+1][p] = v4.y;
            vs[cb+4*k+2][p] = v4.z; vs[cb+4*k+3][p] = v4.w;
        }
    }
    __syncthreads();

#pragma unroll
    for (int i = 0; i < 8; i++) {
        int u = tid + i * 256;           // 2048 = 64 px * 32 ch-pairs
        int r = u >> 5, cp2 = u & 31;
        float s0 = 0.f, s1 = 0.f;
#pragma unroll
        for (int q = 0; q < 4; q++) {
            unsigned pk = g_Oph[(size_t)c_q[q] * 4096 + (ro + r) * 32 + cp2];
            __half2 h2 = *reinterpret_cast<__half2*>(&pk);
            float2 f = __half22float2(h2);
            s0 += sw[q][r] * f.x;
            s1 += sw[q][r] * f.y;
        }
        sO[r * 65 + cp2 * 2]     = s0 * sden[r];
        sO[r * 65 + cp2 * 2 + 1] = s1 * sden[r];
    }

    float acc[4][4];
#pragma unroll
    for (int i = 0; i < 4; i++)
#pragma unroll
        for (int j = 0; j < 4; j++) acc[i][j] = 0.f;
#pragma unroll 4
    for (int cp = 0; cp < 64; cp++) {
        float mv[4];
#pragma unroll
        for (int i = 0; i < 4; i++) mv[i] = mas[cp][ty * 4 + i];
        float4 v4 = *(const float4*)&vs[cp][tx * 4];
        float vv[4] = {v4.x, v4.y, v4.z, v4.w};
#pragma unroll
        for (int i = 0; i < 4; i++)
#pragma unroll
            for (int j = 0; j < 4; j++) acc[i][j] += mv[i] * vv[j];
    }
    __syncthreads();

#pragma unroll
    for (int i = 0; i < 4; i++) {
        const int ch = ty * 4 + i;
        float4 o4;
        o4.x = acc[i][0] + sO[(tx * 4 + 0) * 65 + ch];
        o4.y = acc[i][1] + sO[(tx * 4 + 1) * 65 + ch];
        o4.z = acc[i][2] + sO[(tx * 4 + 2) * 65 + ch];
        o4.w = acc[i][3] + sO[(tx * 4 + 3) * 65 + ch];
        *(float4*)(out + ((size_t)b * 64 + ch) * NN + n0 + tx * 4) = o4;
    }
}

// ---------------------------------------------------------------------------
extern "C" void kernel_launch(void* const* d_in, const int* in_sizes, int n_in,
                              void* d_out, int out_size)
{
    const float* x    = (const float*)d_in[0];
    const float* w    = (const float*)d_in[1];
    const float* bias = (const float*)d_in[2];
    float* out = (float*)d_out;

    const int fsm = 32768 + 2 * 24576;  // 81920 B
    cudaFuncSetAttribute(flash_wm6, cudaFuncAttributeMaxDynamicSharedMemorySize, fsm);

    qkv_kernel<<<dim3(100, 2, 4), 256>>>(x, w, bias);
    repack_kernel<<<dim3(100, 4), 256>>>();
    chan_logits_kernel<<<dim3(32, 4), 256>>>();
    chan_softmax_kernel<<<dim3(64, 4), 64>>>();
    flash_wm6<<<dim3(50, 4, 4), 128, fsm>>>();
    chan_spatial_kernel<<<dim3(100, 4), 256>>>(out);
}

// round 14
// speedup vs baseline: 9.7467x; 1.4245x over previous
#include <cuda_runtime.h>
#include <cuda_bf16.h>
#include <cuda_fp16.h>
#include <math.h>
#include <stdint.h>

#define BB 4
#define CC 64
#define NN 6400

// ---------------- scratch ----------------
__device__ float g_Q [BB * NN * CC];   // [b][n][c], row n = q(h=n%80, w=n/80)
__device__ float g_V [BB * NN * CC];   // [b][m][c], row m = v(h=m%80, w=m/80)
__device__ float g_Kc[BB * NN * CC];   // [b][m][c], k natural order
__device__ float g_Lp[BB * 64 * CC * CC];
__device__ float g_ma[BB * CC * CC];
// MMA tiles, ldmatrix-swizzled (all fp16 now)
__device__ uint4 g_Qt[BB * 100 * 512];   // fp16: [row64][ch64]
__device__ uint4 g_Kt[BB * 100 * 512];   // fp16: [key64][ch64]
__device__ uint4 g_Vt[BB * 100 * 512];   // fp16: [ch64][key64]
// split-kv partials: 800 CTAs x 128 rows; O stored fp16x2 (ch pairs)
__device__ unsigned g_Oph[800 * 128 * 32];
__device__ float g_Od[800 * 128];
__device__ float g_Om[800 * 128];

// ---------------- helpers ----------------
__device__ __forceinline__ unsigned smem_u32(const void* p) {
    unsigned a;
    asm("{ .reg .u64 t; cvta.to.shared.u64 t, %1; cvt.u32.u64 %0, t; }" : "=r"(a) : "l"(p));
    return a;
}
__device__ __forceinline__ void ldsm4(unsigned& r0, unsigned& r1, unsigned& r2, unsigned& r3, unsigned a) {
    asm volatile("ldmatrix.sync.aligned.m8n8.x4.shared.b16 {%0,%1,%2,%3}, [%4];"
                 : "=r"(r0), "=r"(r1), "=r"(r2), "=r"(r3) : "r"(a));
}
__device__ __forceinline__ void mma_h(float* c,
                                      unsigned a0, unsigned a1, unsigned a2, unsigned a3,
                                      unsigned b0, unsigned b1) {
    asm volatile("mma.sync.aligned.m16n8k16.row.col.f32.f16.f16.f32 "
                 "{%0,%1,%2,%3}, {%4,%5,%6,%7}, {%8,%9}, {%0,%1,%2,%3};"
                 : "+f"(c[0]), "+f"(c[1]), "+f"(c[2]), "+f"(c[3])
                 : "r"(a0), "r"(a1), "r"(a2), "r"(a3), "r"(b0), "r"(b1));
}
// first-touch variant: D = A*B + 0 (no accumulator read, no zero-init movs)
__device__ __forceinline__ void mma_h_z(float* c,
                                        unsigned a0, unsigned a1, unsigned a2, unsigned a3,
                                        unsigned b0, unsigned b1) {
    asm volatile("mma.sync.aligned.m16n8k16.row.col.f32.f16.f16.f32 "
                 "{%0,%1,%2,%3}, {%4,%5,%6,%7}, {%8,%9}, {%10,%10,%10,%10};"
                 : "=f"(c[0]), "=f"(c[1]), "=f"(c[2]), "=f"(c[3])
                 : "r"(a0), "r"(a1), "r"(a2), "r"(a3), "r"(b0), "r"(b1), "f"(0.f));
}
__device__ __forceinline__ unsigned pk2h(float lo, float hi) { // f16x2, lower = lo
    unsigned r; asm("cvt.rn.f16x2.f32 %0, %1, %2;" : "=r"(r) : "f"(hi), "f"(lo)); return r;
}
__device__ __forceinline__ float ex2f(float x) {
    float r; asm("ex2.approx.ftz.f32 %0, %1;" : "=f"(r) : "f"(x)); return r;
}
__device__ __forceinline__ void cpa16(unsigned d, const void* g) {
    asm volatile("cp.async.cg.shared.global [%0], [%1], 16;" :: "r"(d), "l"(g));
}
#define CP_COMMIT() asm volatile("cp.async.commit_group;" ::: "memory")
#define CP_WAIT1()  asm volatile("cp.async.wait_group 1;" ::: "memory")
#define CP_WAIT0()  asm volatile("cp.async.wait_group 0;" ::: "memory")

// ---------------------------------------------------------------------------
// Kernel 1: 1x1 conv qkv. grid (100, 2, 4)
// ---------------------------------------------------------------------------
__global__ __launch_bounds__(256) void qkv_kernel(
    const float* __restrict__ x, const float* __restrict__ w, const float* __restrict__ bias)
{
    __shared__ float ws[64][100];
    __shared__ float xs[64][64];
    const int b = blockIdx.z, half = blockIdx.y, n0 = blockIdx.x * 64;
    const int tid = threadIdx.x, obase = half * 96;

    for (int idx = tid; idx < 96 * 64; idx += 256) {
        int o = idx >> 6, c = idx & 63;
        ws[c][o] = w[(size_t)(obase + o) * 64 + c];
    }
    for (int idx = tid; idx < 64 * 64; idx += 256) {
        int c = idx >> 6, p = idx & 63;
        xs[c][p] = x[((size_t)b * 64 + c) * NN + n0 + p];
    }
    __syncthreads();

    const int p = tid & 63, o0 = (tid >> 6) * 24;
    float acc[24];
#pragma unroll
    for (int j = 0; j < 24; j++) acc[j] = 0.f;
#pragma unroll 4
    for (int c = 0; c < 64; c++) {
        float xv = xs[c][p];
#pragma unroll
        for (int j4 = 0; j4 < 24; j4 += 4) {
            float4 wv = *(const float4*)&ws[c][o0 + j4];
            acc[j4+0] += xv * wv.x; acc[j4+1] += xv * wv.y;
            acc[j4+2] += xv * wv.z; acc[j4+3] += xv * wv.w;
        }
    }
    const int n = n0 + p, h = n / 80, wq = n % 80, nt = wq * 80 + h;
#pragma unroll
    for (int j4 = 0; j4 < 24; j4 += 4) {
        const int o = obase + o0 + j4;
        float4 v4;
        v4.x = acc[j4+0] + bias[o+0]; v4.y = acc[j4+1] + bias[o+1];
        v4.z = acc[j4+2] + bias[o+2]; v4.w = acc[j4+3] + bias[o+3];
        if (o < 64) {
            *(float4*)&g_Q[((size_t)b*NN + nt)*64 + o] = v4;
        } else if (o < 128) {
            *(float4*)&g_Kc[((size_t)b*NN + n)*64 + (o-64)] = v4;
        } else {
            *(float4*)&g_V[((size_t)b*NN + nt)*64 + (o-128)] = v4;
        }
    }
}

// ---------------------------------------------------------------------------
// repack: Q/K/V all single fp16, ldmatrix-swizzled. grid (100, 4)
// ---------------------------------------------------------------------------
__global__ __launch_bounds__(256) void repack_kernel() {
    const int kt = blockIdx.x, b = blockIdx.y, tid = threadIdx.x;
    uint4* dQ = g_Qt + (size_t)(b * 100 + kt) * 512;
    uint4* dK = g_Kt + (size_t)(b * 100 + kt) * 512;
    uint4* dV = g_Vt + (size_t)(b * 100 + kt) * 512;

    for (int u = tid; u < 512; u += 256) {
        const int r = u >> 3, cu = u & 7;
        const int du = r * 8 + (cu ^ (r & 7));
        {   // Q
            const float* s = g_Q + ((size_t)b * NN + kt * 64 + r) * 64 + cu * 8;
            float v[8];
            *(float4*)v = *(const float4*)s; *(float4*)(v + 4) = *(const float4*)(s + 4);
            uint4 hw; unsigned* hww = (unsigned*)&hw;
#pragma unroll
            for (int i = 0; i < 4; i++) hww[i] = pk2h(v[2*i], v[2*i+1]);
            dQ[du] = hw;
        }
        {   // K: key r -> m = kt*64+r, source row nt(m)
            const int m = kt * 64 + r;
            const int nt = (m % 80) * 80 + m / 80;
            const float* s = g_Q + ((size_t)b * NN + nt) * 64 + cu * 8;
            float v[8];
            *(float4*)v = *(const float4*)s; *(float4*)(v + 4) = *(const float4*)(s + 4);
            uint4 hw; unsigned* hww = (unsigned*)&hw;
#pragma unroll
            for (int i = 0; i < 4; i++) hww[i] = pk2h(v[2*i], v[2*i+1]);
            dK[du] = hw;
        }
        {   // V fp16: row = ch r, keys cu*8..cu*8+7
            const float* s = g_V + ((size_t)b * NN + kt * 64 + cu * 8) * 64 + r;
            float v[8];
#pragma unroll
            for (int j = 0; j < 8; j++) v[j] = s[j * 64];
            uint4 hw; unsigned* hww = (unsigned*)&hw;
#pragma unroll
            for (int i = 0; i < 4; i++) hww[i] = pk2h(v[2*i], v[2*i+1]);
            dV[du] = hw;
        }
    }
}

// ---------------------------------------------------------------------------
// channel attention logits. grid (64 chunks, 4 b), 256 thr (256 CTAs total)
// ---------------------------------------------------------------------------
__global__ __launch_bounds__(256) void chan_logits_kernel() {
    const int b = blockIdx.y, chunk = blockIdx.x, tid = threadIdx.x;
    const int tx = tid & 15, ty = tid >> 4;
    const float* __restrict__ Kc = g_Kc + (size_t)b * NN * CC;
    const float* __restrict__ Qm = g_Q  + (size_t)b * NN * CC;
    float acc[4][4];
#pragma unroll
    for (int i = 0; i < 4; i++)
#pragma unroll
        for (int j = 0; j < 4; j++) acc[i][j] = 0.f;
    const int m0 = chunk * 100;
#pragma unroll 2
    for (int m = m0; m < m0 + 100; m++) {
        float4 kv4 = *(const float4*)(Kc + (size_t)m*64 + ty*4);
        float4 qv4 = *(const float4*)(Qm + (size_t)m*64 + tx*4);
        float kv[4] = {kv4.x, kv4.y, kv4.z, kv4.w};
        float qv[4] = {qv4.x, qv4.y, qv4.z, qv4.w};
#pragma unroll
        for (int i = 0; i < 4; i++)
#pragma unroll
            for (int j = 0; j < 4; j++) acc[i][j] += kv[i] * qv[j];
    }
    float* Lp = g_Lp + ((size_t)b*64 + chunk) * 64 * 64;
#pragma unroll
    for (int i = 0; i < 4; i++)
        *(float4*)(Lp + (size_t)(ty*4 + i)*64 + tx*4) =
            make_float4(acc[i][0], acc[i][1], acc[i][2], acc[i][3]);
}

// ---------------------------------------------------------------------------
// parallel reduce + softmax. grid (64 rows, 4 b), 64 thr (thread = column)
// ---------------------------------------------------------------------------
__global__ void chan_softmax_kernel() {
    __shared__ float red[2], rs[2];
    const int c = blockIdx.x, b = blockIdx.y, j = threadIdx.x;
    float s = 0.f;
#pragma unroll
    for (int ch = 0; ch < 64; ch++)
        s += g_Lp[(((size_t)b * 64 + ch) * 64 + c) * 64 + j];
    float m = s;
#pragma unroll
    for (int o = 16; o; o >>= 1) m = fmaxf(m, __shfl_xor_sync(0xffffffffu, m, o));
    if ((j & 31) == 0) red[j >> 5] = m;
    __syncthreads();
    m = fmaxf(red[0], red[1]);
    const float e = ex2f((s - m) * 1.4426950408889634f);
    float t = e;
#pragma unroll
    for (int o = 16; o; o >>= 1) t += __shfl_xor_sync(0xffffffffu, t, o);
    if ((j & 31) == 0) rs[j >> 5] = t;
    __syncthreads();
    g_ma[((size_t)b * 64 + c) * 64 + j] = e / (rs[0] + rs[1]);
}

// ---------------------------------------------------------------------------
// warp-MMA flash v7: single-pass fp16 QK^T (128 MMA/warp-tile), online softmax.
// grid (50, 4, 4), 128 thr / 4 warps, 128 rows/CTA, 25 key-tiles, 2-stage.
// smem (48KB): Qf16 [0,16K); stage s at 16K + s*16K: K(8K) V(8K)
// ---------------------------------------------------------------------------
__global__ __launch_bounds__(128, 2) void flash_wm7() {
    extern __shared__ char smc[];
    const unsigned sb = smem_u32(smc);
    const int rt = blockIdx.x, quarter = blockIdx.y, b = blockIdx.z;
    const int tid = threadIdx.x, warp = tid >> 5, lane = tid & 31;
    const int g = lane >> 2, t = lane & 3;
    const int kt0 = quarter * 25;
    const float L2E = 1.4426950408889634f;

    // ---- stage-0 prefetch (K 512 + V 512 uint4) ----
    {
        const uint4* sk = g_Kt + (size_t)(b * 100 + kt0) * 512;
        const uint4* sv = g_Vt + (size_t)(b * 100 + kt0) * 512;
        const unsigned base = sb + 16384u;
#pragma unroll
        for (int j = 0; j < 4; j++) { int i = tid + j * 128; cpa16(base + i * 16, sk + i); }
#pragma unroll
        for (int j = 0; j < 4; j++) { int i = tid + j * 128; cpa16(base + 8192u + i * 16, sv + i); }
        CP_COMMIT();
    }
    // ---- Q tiles copy (rt*2, rt*2+1 contiguous -> 1024 uint4) ----
    {
        uint4* dq = (uint4*)smc;
        const uint4* src = g_Qt + (size_t)(b * 100 + rt * 2) * 512;
#pragma unroll
        for (int i = 0; i < 8; i++) { int u = tid + i * 128; dq[u] = src[u]; }
    }

    const int subA = lane >> 3, lrA = lane & 7;
    const int rAb = ((subA & 1) << 3) + lrA;   // row offset within 16-row half
    const int cbA = (subA >> 1) << 4;
    const int rB16 = ((lane >> 4) << 3) + (lane & 7);
    const int bsel = ((lane >> 3) & 1) << 4;

    float O[2][8][4];
#pragma unroll
    for (int h = 0; h < 2; h++)
#pragma unroll
        for (int nb = 0; nb < 8; nb++)
#pragma unroll
            for (int j = 0; j < 4; j++) O[h][nb][j] = 0.f;
    float dd[2][2], mm[2][2];
#pragma unroll
    for (int h = 0; h < 2; h++) { dd[h][0] = dd[h][1] = 0.f; mm[h][0] = mm[h][1] = -INFINITY; }

    for (int it = 0; it < 25; it++) {
        const unsigned koff = 16384u + (unsigned)(it & 1) * 16384u;
        const unsigned voff = koff + 8192u;
        __syncthreads();
        if (it + 1 < 25) {
            const uint4* sk = g_Kt + (size_t)(b * 100 + kt0 + it + 1) * 512;
            const uint4* sv = g_Vt + (size_t)(b * 100 + kt0 + it + 1) * 512;
            const unsigned nbase = sb + 16384u + (unsigned)((it + 1) & 1) * 16384u;
#pragma unroll
            for (int j = 0; j < 4; j++) { int i = tid + j * 128; cpa16(nbase + i * 16, sk + i); }
#pragma unroll
            for (int j = 0; j < 4; j++) { int i = tid + j * 128; cpa16(nbase + 8192u + i * 16, sv + i); }
            CP_COMMIT();
            CP_WAIT1();
        } else {
            CP_WAIT0();
        }
        __syncthreads();

        // ---- S = Q K^T (single fp16 pass, first-touch C=0) ----
        float S[2][8][4];
#pragma unroll
        for (int kc = 0; kc < 4; kc++) {
            unsigned qf[2][4];
#pragma unroll
            for (int h = 0; h < 2; h++) {
                const int rA = warp * 32 + h * 16 + rAb;
                const unsigned aswz = (unsigned)((kc * 32 + cbA) ^ ((rA & 7) << 4));
                ldsm4(qf[h][0], qf[h][1], qf[h][2], qf[h][3], sb + rA * 128 + aswz);
            }
#pragma unroll
            for (int nbp = 0; nbp < 4; nbp++) {
                const int rB = nbp * 16 + rB16;
                const unsigned bswz = (unsigned)((kc * 32 + bsel) ^ ((rB & 7) << 4));
                unsigned k0, k1, k2, k3;
                ldsm4(k0, k1, k2, k3, sb + koff + rB * 128 + bswz);
                if (kc == 0) {
                    mma_h_z(S[0][2*nbp],   qf[0][0], qf[0][1], qf[0][2], qf[0][3], k0, k1);
                    mma_h_z(S[0][2*nbp+1], qf[0][0], qf[0][1], qf[0][2], qf[0][3], k2, k3);
                    mma_h_z(S[1][2*nbp],   qf[1][0], qf[1][1], qf[1][2], qf[1][3], k0, k1);
                    mma_h_z(S[1][2*nbp+1], qf[1][0], qf[1][1], qf[1][2], qf[1][3], k2, k3);
                } else {
                    mma_h(S[0][2*nbp],   qf[0][0], qf[0][1], qf[0][2], qf[0][3], k0, k1);
                    mma_h(S[0][2*nbp+1], qf[0][0], qf[0][1], qf[0][2], qf[0][3], k2, k3);
                    mma_h(S[1][2*nbp],   qf[1][0], qf[1][1], qf[1][2], qf[1][3], k0, k1);
                    mma_h(S[1][2*nbp+1], qf[1][0], qf[1][1], qf[1][2], qf[1][3], k2, k3);
                }
            }
        }

        // ---- online softmax per half ----
        unsigned Ph[2][4][4];
#pragma unroll
        for (int h = 0; h < 2; h++) {
            float tm1 = -INFINITY, tm2 = -INFINITY;
#pragma unroll
            for (int nb = 0; nb < 8; nb++) {
                tm1 = fmaxf(tm1, fmaxf(S[h][nb][0], S[h][nb][1]));
                tm2 = fmaxf(tm2, fmaxf(S[h][nb][2], S[h][nb][3]));
            }
            tm1 = fmaxf(tm1, __shfl_xor_sync(0xffffffffu, tm1, 1));
            tm1 = fmaxf(tm1, __shfl_xor_sync(0xffffffffu, tm1, 2));
            tm2 = fmaxf(tm2, __shfl_xor_sync(0xffffffffu, tm2, 1));
            tm2 = fmaxf(tm2, __shfl_xor_sync(0xffffffffu, tm2, 2));
            const float m1n = fmaxf(mm[h][0], tm1), m2n = fmaxf(mm[h][1], tm2);
            const float sc1 = ex2f((mm[h][0] - m1n) * L2E), sc2 = ex2f((mm[h][1] - m2n) * L2E);
            const float b1 = m1n * L2E, b2 = m2n * L2E;
            mm[h][0] = m1n; mm[h][1] = m2n;

            float ds1 = 0.f, ds2 = 0.f;
#pragma unroll
            for (int nb = 0; nb < 8; nb++) {
                float e0 = ex2f(fmaf(S[h][nb][0], L2E, -b1));
                float e1 = ex2f(fmaf(S[h][nb][1], L2E, -b1));
                float e2 = ex2f(fmaf(S[h][nb][2], L2E, -b2));
                float e3 = ex2f(fmaf(S[h][nb][3], L2E, -b2));
                ds1 += e0 + e1; ds2 += e2 + e3;
                const int kc = nb >> 1, o = (nb & 1) << 1;
                Ph[h][kc][o]     = pk2h(e0, e1);
                Ph[h][kc][o + 1] = pk2h(e2, e3);
            }
            dd[h][0] = dd[h][0] * sc1 + ds1;
            dd[h][1] = dd[h][1] * sc2 + ds2;
#pragma unroll
            for (int nb = 0; nb < 8; nb++) {
                O[h][nb][0] *= sc1; O[h][nb][1] *= sc1;
                O[h][nb][2] *= sc2; O[h][nb][3] *= sc2;
            }
        }

        // ---- O += P V (fp16, V frags shared by both halves) ----
#pragma unroll
        for (int kc = 0; kc < 4; kc++) {
#pragma unroll
            for (int nbp = 0; nbp < 4; nbp++) {
                const int rB = nbp * 16 + rB16;
                const unsigned bswz = (unsigned)((kc * 32 + bsel) ^ ((rB & 7) << 4));
                unsigned v0, v1, v2, v3;
                ldsm4(v0, v1, v2, v3, sb + voff + rB * 128 + bswz);
                mma_h(O[0][2*nbp],   Ph[0][kc][0], Ph[0][kc][1], Ph[0][kc][2], Ph[0][kc][3], v0, v1);
                mma_h(O[0][2*nbp+1], Ph[0][kc][0], Ph[0][kc][1], Ph[0][kc][2], Ph[0][kc][3], v2, v3);
                mma_h(O[1][2*nbp],   Ph[1][kc][0], Ph[1][kc][1], Ph[1][kc][2], Ph[1][kc][3], v0, v1);
                mma_h(O[1][2*nbp+1], Ph[1][kc][0], Ph[1][kc][1], Ph[1][kc][2], Ph[1][kc][3], v2, v3);
            }
        }
    }

    // ---- epilogue per half: reduce denominators, store (m, d, O-fp16) ----
    const int cta = (b * 4 + quarter) * 50 + rt;
    unsigned* Uh = g_Oph + (size_t)cta * 4096;
#pragma unroll
    for (int h = 0; h < 2; h++) {
        float d1 = dd[h][0], d2 = dd[h][1];
        d1 += __shfl_xor_sync(0xffffffffu, d1, 1);
        d1 += __shfl_xor_sync(0xffffffffu, d1, 2);
        d2 += __shfl_xor_sync(0xffffffffu, d2, 1);
        d2 += __shfl_xor_sync(0xffffffffu, d2, 2);
        const int r0 = warp * 32 + h * 16;
        if (t == 0) {
            g_Od[cta * 128 + r0 + g]     = d1;
            g_Od[cta * 128 + r0 + g + 8] = d2;
            g_Om[cta * 128 + r0 + g]     = mm[h][0];
            g_Om[cta * 128 + r0 + g + 8] = mm[h][1];
        }
#pragma unroll
        for (int nb = 0; nb < 8; nb++) {
            Uh[(r0 + g) * 32 + nb * 4 + t]     = pk2h(O[h][nb][0], O[h][nb][1]);
            Uh[(r0 + g + 8) * 32 + nb * 4 + t] = pk2h(O[h][nb][2], O[h][nb][3]);
        }
    }
}

// ---------------------------------------------------------------------------
// fused channel-apply + spatial combine. grid (100, 4), 256 thr.
// ---------------------------------------------------------------------------
__global__ __launch_bounds__(256) void chan_spatial_kernel(float* __restrict__ out) {
    __shared__ float vs[64][64];
    __shared__ float mas[64][65];
    __shared__ float sO[64 * 65];   // [px][ch], spatial normalized
    __shared__ float sden[64];
    __shared__ float sw[4][64];
    const int rt64 = blockIdx.x, b = blockIdx.y, tid = threadIdx.x;
    const int tx = tid & 15, ty = tid >> 4;
    const int n0 = rt64 * 64;
    const int rtb = rt64 >> 1, ro = (rt64 & 1) * 64;
    const float L2E = 1.4426950408889634f;
    int c_q[4];
#pragma unroll
    for (int q = 0; q < 4; q++) c_q[q] = (b * 4 + q) * 50 + rtb;

    if (tid < 64) {
        float mq[4], dq[4], M = -INFINITY;
#pragma unroll
        for (int q = 0; q < 4; q++) {
            mq[q] = g_Om[c_q[q] * 128 + ro + tid];
            dq[q] = g_Od[c_q[q] * 128 + ro + tid];
            M = fmaxf(M, mq[q]);
        }
        float den = 0.f;
#pragma unroll
        for (int q = 0; q < 4; q++) {
            float wq = ex2f((mq[q] - M) * L2E);
            sw[q][tid] = wq;
            den += wq * dq[q];
        }
        sden[tid] = 1.f / den;
    }
    for (int idx = tid; idx < 4096; idx += 256) {
        int c = idx >> 6, cp = idx & 63;
        mas[cp][c] = g_ma[((size_t)b * 64 + c) * 64 + cp];
    }
    {
        int p = tid >> 2, cb = (tid & 3) * 16;
        int n = n0 + p, nt = (n % 80) * 80 + n / 80;
        const float* vp = g_V + ((size_t)b * NN + nt) * 64 + cb;
#pragma unroll
        for (int k = 0; k < 4; k++) {
            float4 v4 = *(const float4*)(vp + 4 * k);
            vs[cb+4*k+0][p] = v4.x; vs[cb+4*k+1][p] = v4.y;
            vs[cb+4*k+2][p] = v4.z; vs[cb+4*k+3][p] = v4.w;
        }
    }
    __syncthreads();

#pragma unroll
    for (int i = 0; i < 8; i++) {
        int u = tid + i * 256;           // 2048 = 64 px * 32 ch-pairs
        int r = u >> 5, cp2 = u & 31;
        float s0 = 0.f, s1 = 0.f;
#pragma unroll
        for (int q = 0; q < 4; q++) {
            unsigned pk = g_Oph[(size_t)c_q[q] * 4096 + (ro + r) * 32 + cp2];
            __half2 h2 = *reinterpret_cast<__half2*>(&pk);
            float2 f = __half22float2(h2);
            s0 += sw[q][r] * f.x;
            s1 += sw[q][r] * f.y;
        }
        sO[r * 65 + cp2 * 2]     = s0 * sden[r];
        sO[r * 65 + cp2 * 2 + 1] = s1 * sden[r];
    }

    float acc[4][4];
#pragma unroll
    for (int i = 0; i < 4; i++)
#pragma unroll
        for (int j = 0; j < 4; j++) acc[i][j] = 0.f;
#pragma unroll 4
    for (int cp = 0; cp < 64; cp++) {
        float mv[4];
#pragma unroll
        for (int i = 0; i < 4; i++) mv[i] = mas[cp][ty * 4 + i];
        float4 v4 = *(const float4*)&vs[cp][tx * 4];
        float vv[4] = {v4.x, v4.y, v4.z, v4.w};
#pragma unroll
        for (int i = 0; i < 4; i++)
#pragma unroll
            for (int j = 0; j < 4; j++) acc[i][j] += mv[i] * vv[j];
    }
    __syncthreads();

#pragma unroll
    for (int i = 0; i < 4; i++) {
        const int ch = ty * 4 + i;
        float4 o4;
        o4.x = acc[i][0] + sO[(tx * 4 + 0) * 65 + ch];
        o4.y = acc[i][1] + sO[(tx * 4 + 1) * 65 + ch];
        o4.z = acc[i][2] + sO[(tx * 4 + 2) * 65 + ch];
        o4.w = acc[i][3] + sO[(tx * 4 + 3) * 65 + ch];
        *(float4*)(out + ((size_t)b * 64 + ch) * NN + n0 + tx * 4) = o4;
    }
}

// ---------------------------------------------------------------------------
extern "C" void kernel_launch(void* const* d_in, const int* in_sizes, int n_in,
                              void* d_out, int out_size)
{
    const float* x    = (const float*)d_in[0];
    const float* w    = (const float*)d_in[1];
    const float* bias = (const float*)d_in[2];
    float* out = (float*)d_out;

    const int fsm = 16384 + 2 * 16384;  // 49152 B
    cudaFuncSetAttribute(flash_wm7, cudaFuncAttributeMaxDynamicSharedMemorySize, fsm);

    qkv_kernel<<<dim3(100, 2, 4), 256>>>(x, w, bias);
    repack_kernel<<<dim3(100, 4), 256>>>();
    chan_logits_kernel<<<dim3(64, 4), 256>>>();
    chan_softmax_kernel<<<dim3(64, 4), 64>>>();
    flash_wm7<<<dim3(50, 4, 4), 128, fsm>>>();
    chan_spatial_kernel<<<dim3(100, 4), 256>>>(out);
}

// round 15
// speedup vs baseline: 9.7556x; 1.0009x over previous
#include <cuda_runtime.h>
#include <cuda_bf16.h>
#include <cuda_fp16.h>
#include <math.h>
#include <stdint.h>

#define BB 4
#define CC 64
#define NN 6400

// ---------------- scratch ----------------
__device__ float g_Q [BB * NN * CC];   // [b][n][c], row n = q(h=n%80, w=n/80)
__device__ float g_V [BB * NN * CC];   // [b][m][c], row m = v(h=m%80, w=m/80)
__device__ float g_Kc[BB * NN * CC];   // [b][m][c], k natural order
__device__ float g_Lp[BB * 64 * CC * CC];
__device__ float g_ma[BB * CC * CC];
// MMA tiles, ldmatrix-swizzled (all fp16)
__device__ uint4 g_Qt[BB * 100 * 512];   // fp16: [row64][ch64]
__device__ uint4 g_Kt[BB * 100 * 512];   // fp16: [key64][ch64]
__device__ uint4 g_Vt[BB * 100 * 512];   // fp16: [ch64][key64]
// split-kv partials: 800 CTAs x 128 rows; O stored fp16x2 (ch pairs)
__device__ unsigned g_Oph[800 * 128 * 32];
__device__ float g_Od[800 * 128];
__device__ float g_Om[800 * 128];

#define ONES_H2 0x3C003C00u

// ---------------- helpers ----------------
__device__ __forceinline__ unsigned smem_u32(const void* p) {
    unsigned a;
    asm("{ .reg .u64 t; cvta.to.shared.u64 t, %1; cvt.u32.u64 %0, t; }" : "=r"(a) : "l"(p));
    return a;
}
__device__ __forceinline__ void ldsm4(unsigned& r0, unsigned& r1, unsigned& r2, unsigned& r3, unsigned a) {
    asm volatile("ldmatrix.sync.aligned.m8n8.x4.shared.b16 {%0,%1,%2,%3}, [%4];"
                 : "=r"(r0), "=r"(r1), "=r"(r2), "=r"(r3) : "r"(a));
}
__device__ __forceinline__ void mma_h(float* c,
                                      unsigned a0, unsigned a1, unsigned a2, unsigned a3,
                                      unsigned b0, unsigned b1) {
    asm volatile("mma.sync.aligned.m16n8k16.row.col.f32.f16.f16.f32 "
                 "{%0,%1,%2,%3}, {%4,%5,%6,%7}, {%8,%9}, {%0,%1,%2,%3};"
                 : "+f"(c[0]), "+f"(c[1]), "+f"(c[2]), "+f"(c[3])
                 : "r"(a0), "r"(a1), "r"(a2), "r"(a3), "r"(b0), "r"(b1));
}
// first-touch variant: D = A*B + 0
__device__ __forceinline__ void mma_h_z(float* c,
                                        unsigned a0, unsigned a1, unsigned a2, unsigned a3,
                                        unsigned b0, unsigned b1) {
    asm volatile("mma.sync.aligned.m16n8k16.row.col.f32.f16.f16.f32 "
                 "{%0,%1,%2,%3}, {%4,%5,%6,%7}, {%8,%9}, {%10,%10,%10,%10};"
                 : "=f"(c[0]), "=f"(c[1]), "=f"(c[2]), "=f"(c[3])
                 : "r"(a0), "r"(a1), "r"(a2), "r"(a3), "r"(b0), "r"(b1), "f"(0.f));
}
__device__ __forceinline__ unsigned pk2h(float lo, float hi) { // f16x2, lower = lo
    unsigned r; asm("cvt.rn.f16x2.f32 %0, %1, %2;" : "=r"(r) : "f"(hi), "f"(lo)); return r;
}
__device__ __forceinline__ unsigned h2exp2(unsigned x) {       // packed 2^x
    unsigned r; asm("ex2.approx.f16x2 %0, %1;" : "=r"(r) : "r"(x)); return r;
}
__device__ __forceinline__ float ex2f(float x) {
    float r; asm("ex2.approx.ftz.f32 %0, %1;" : "=f"(r) : "f"(x)); return r;
}
__device__ __forceinline__ void cpa16(unsigned d, const void* g) {
    asm volatile("cp.async.cg.shared.global [%0], [%1], 16;" :: "r"(d), "l"(g));
}
#define CP_COMMIT() asm volatile("cp.async.commit_group;" ::: "memory")
#define CP_WAIT1()  asm volatile("cp.async.wait_group 1;" ::: "memory")
#define CP_WAIT0()  asm volatile("cp.async.wait_group 0;" ::: "memory")

// ---------------------------------------------------------------------------
// Kernel 1: 1x1 conv qkv. grid (100, 2, 4)
// ---------------------------------------------------------------------------
__global__ __launch_bounds__(256) void qkv_kernel(
    const float* __restrict__ x, const float* __restrict__ w, const float* __restrict__ bias)
{
    __shared__ float ws[64][100];
    __shared__ float xs[64][64];
    const int b = blockIdx.z, half = blockIdx.y, n0 = blockIdx.x * 64;
    const int tid = threadIdx.x, obase = half * 96;

    for (int idx = tid; idx < 96 * 64; idx += 256) {
        int o = idx >> 6, c = idx & 63;
        ws[c][o] = w[(size_t)(obase + o) * 64 + c];
    }
    for (int idx = tid; idx < 64 * 64; idx += 256) {
        int c = idx >> 6, p = idx & 63;
        xs[c][p] = x[((size_t)b * 64 + c) * NN + n0 + p];
    }
    __syncthreads();

    const int p = tid & 63, o0 = (tid >> 6) * 24;
    float acc[24];
#pragma unroll
    for (int j = 0; j < 24; j++) acc[j] = 0.f;
#pragma unroll 4
    for (int c = 0; c < 64; c++) {
        float xv = xs[c][p];
#pragma unroll
        for (int j4 = 0; j4 < 24; j4 += 4) {
            float4 wv = *(const float4*)&ws[c][o0 + j4];
            acc[j4+0] += xv * wv.x; acc[j4+1] += xv * wv.y;
            acc[j4+2] += xv * wv.z; acc[j4+3] += xv * wv.w;
        }
    }
    const int n = n0 + p, h = n / 80, wq = n % 80, nt = wq * 80 + h;
#pragma unroll
    for (int j4 = 0; j4 < 24; j4 += 4) {
        const int o = obase + o0 + j4;
        float4 v4;
        v4.x = acc[j4+0] + bias[o+0]; v4.y = acc[j4+1] + bias[o+1];
        v4.z = acc[j4+2] + bias[o+2]; v4.w = acc[j4+3] + bias[o+3];
        if (o < 64) {
            *(float4*)&g_Q[((size_t)b*NN + nt)*64 + o] = v4;
        } else if (o < 128) {
            *(float4*)&g_Kc[((size_t)b*NN + n)*64 + (o-64)] = v4;
        } else {
            *(float4*)&g_V[((size_t)b*NN + nt)*64 + (o-128)] = v4;
        }
    }
}

// ---------------------------------------------------------------------------
// repack: Q/K/V all single fp16, ldmatrix-swizzled. grid (100, 4)
// ---------------------------------------------------------------------------
__global__ __launch_bounds__(256) void repack_kernel() {
    const int kt = blockIdx.x, b = blockIdx.y, tid = threadIdx.x;
    uint4* dQ = g_Qt + (size_t)(b * 100 + kt) * 512;
    uint4* dK = g_Kt + (size_t)(b * 100 + kt) * 512;
    uint4* dV = g_Vt + (size_t)(b * 100 + kt) * 512;

    for (int u = tid; u < 512; u += 256) {
        const int r = u >> 3, cu = u & 7;
        const int du = r * 8 + (cu ^ (r & 7));
        {   // Q
            const float* s = g_Q + ((size_t)b * NN + kt * 64 + r) * 64 + cu * 8;
            float v[8];
            *(float4*)v = *(const float4*)s; *(float4*)(v + 4) = *(const float4*)(s + 4);
            uint4 hw; unsigned* hww = (unsigned*)&hw;
#pragma unroll
            for (int i = 0; i < 4; i++) hww[i] = pk2h(v[2*i], v[2*i+1]);
            dQ[du] = hw;
        }
        {   // K: key r -> m = kt*64+r, source row nt(m)
            const int m = kt * 64 + r;
            const int nt = (m % 80) * 80 + m / 80;
            const float* s = g_Q + ((size_t)b * NN + nt) * 64 + cu * 8;
            float v[8];
            *(float4*)v = *(const float4*)s; *(float4*)(v + 4) = *(const float4*)(s + 4);
            uint4 hw; unsigned* hww = (unsigned*)&hw;
#pragma unroll
            for (int i = 0; i < 4; i++) hww[i] = pk2h(v[2*i], v[2*i+1]);
            dK[du] = hw;
        }
        {   // V fp16: row = ch r, keys cu*8..cu*8+7
            const float* s = g_V + ((size_t)b * NN + kt * 64 + cu * 8) * 64 + r;
            float v[8];
#pragma unroll
            for (int j = 0; j < 8; j++) v[j] = s[j * 64];
            uint4 hw; unsigned* hww = (unsigned*)&hw;
#pragma unroll
            for (int i = 0; i < 4; i++) hww[i] = pk2h(v[2*i], v[2*i+1]);
            dV[du] = hw;
        }
    }
}

// ---------------------------------------------------------------------------
// channel attention logits. grid (64 chunks, 4 b), 256 thr
// ---------------------------------------------------------------------------
__global__ __launch_bounds__(256) void chan_logits_kernel() {
    const int b = blockIdx.y, chunk = blockIdx.x, tid = threadIdx.x;
    const int tx = tid & 15, ty = tid >> 4;
    const float* __restrict__ Kc = g_Kc + (size_t)b * NN * CC;
    const float* __restrict__ Qm = g_Q  + (size_t)b * NN * CC;
    float acc[4][4];
#pragma unroll
    for (int i = 0; i < 4; i++)
#pragma unroll
        for (int j = 0; j < 4; j++) acc[i][j] = 0.f;
    const int m0 = chunk * 100;
#pragma unroll 2
    for (int m = m0; m < m0 + 100; m++) {
        float4 kv4 = *(const float4*)(Kc + (size_t)m*64 + ty*4);
        float4 qv4 = *(const float4*)(Qm + (size_t)m*64 + tx*4);
        float kv[4] = {kv4.x, kv4.y, kv4.z, kv4.w};
        float qv[4] = {qv4.x, qv4.y, qv4.z, qv4.w};
#pragma unroll
        for (int i = 0; i < 4; i++)
#pragma unroll
            for (int j = 0; j < 4; j++) acc[i][j] += kv[i] * qv[j];
    }
    float* Lp = g_Lp + ((size_t)b*64 + chunk) * 64 * 64;
#pragma unroll
    for (int i = 0; i < 4; i++)
        *(float4*)(Lp + (size_t)(ty*4 + i)*64 + tx*4) =
            make_float4(acc[i][0], acc[i][1], acc[i][2], acc[i][3]);
}

// ---------------------------------------------------------------------------
// parallel reduce + softmax. grid (64 rows, 4 b), 64 thr (thread = column)
// ---------------------------------------------------------------------------
__global__ void chan_softmax_kernel() {
    __shared__ float red[2], rs[2];
    const int c = blockIdx.x, b = blockIdx.y, j = threadIdx.x;
    float s = 0.f;
#pragma unroll
    for (int ch = 0; ch < 64; ch++)
        s += g_Lp[(((size_t)b * 64 + ch) * 64 + c) * 64 + j];
    float m = s;
#pragma unroll
    for (int o = 16; o; o >>= 1) m = fmaxf(m, __shfl_xor_sync(0xffffffffu, m, o));
    if ((j & 31) == 0) red[j >> 5] = m;
    __syncthreads();
    m = fmaxf(red[0], red[1]);
    const float e = ex2f((s - m) * 1.4426950408889634f);
    float t = e;
#pragma unroll
    for (int o = 16; o; o >>= 1) t += __shfl_xor_sync(0xffffffffu, t, o);
    if ((j & 31) == 0) rs[j >> 5] = t;
    __syncthreads();
    g_ma[((size_t)b * 64 + c) * 64 + j] = e / (rs[0] + rs[1]);
}

// ---------------------------------------------------------------------------
// warp-MMA flash v8: 256 thr (warp=16 rows), packed-fp16 exp, ones-MMA denom.
// grid (50, 4, 4), 128 rows/CTA, 25 key-tiles of 64, 2-stage cp.async.
// smem (48KB): Qf16 [0,16K); stage s at 16K + s*16K: K(8K) V(8K)
// ---------------------------------------------------------------------------
__global__ __launch_bounds__(256, 2) void flash_wm8() {
    extern __shared__ char smc[];
    const unsigned sb = smem_u32(smc);
    const int rt = blockIdx.x, quarter = blockIdx.y, b = blockIdx.z;
    const int tid = threadIdx.x, warp = tid >> 5, lane = tid & 31;
    const int g = lane >> 2, t = lane & 3;
    const int kt0 = quarter * 25;
    const float L2E = 1.4426950408889634f;

    // ---- stage-0 prefetch (K 512 + V 512 uint4) ----
    {
        const uint4* sk = g_Kt + (size_t)(b * 100 + kt0) * 512;
        const uint4* sv = g_Vt + (size_t)(b * 100 + kt0) * 512;
        const unsigned base = sb + 16384u;
#pragma unroll
        for (int j = 0; j < 2; j++) { int i = tid + j * 256; cpa16(base + i * 16, sk + i); }
#pragma unroll
        for (int j = 0; j < 2; j++) { int i = tid + j * 256; cpa16(base + 8192u + i * 16, sv + i); }
        CP_COMMIT();
    }
    // ---- Q tiles copy (rt*2, rt*2+1 contiguous -> 1024 uint4) ----
    {
        uint4* dq = (uint4*)smc;
        const uint4* src = g_Qt + (size_t)(b * 100 + rt * 2) * 512;
#pragma unroll
        for (int i = 0; i < 4; i++) { int u = tid + i * 256; dq[u] = src[u]; }
    }

    const int subA = lane >> 3, lrA = lane & 7;
    const int rA = warp * 16 + ((subA & 1) << 3) + lrA;
    const int cbA = (subA >> 1) << 4;
    const int rB16 = ((lane >> 4) << 3) + (lane & 7);
    const int bsel = ((lane >> 3) & 1) << 4;

    float O[8][4];
#pragma unroll
    for (int nb = 0; nb < 8; nb++)
#pragma unroll
        for (int j = 0; j < 4; j++) O[nb][j] = 0.f;
    float d1 = 0.f, d2 = 0.f, m1 = -INFINITY, m2 = -INFINITY;

    for (int it = 0; it < 25; it++) {
        const unsigned koff = 16384u + (unsigned)(it & 1) * 16384u;
        const unsigned voff = koff + 8192u;
        __syncthreads();
        if (it + 1 < 25) {
            const uint4* sk = g_Kt + (size_t)(b * 100 + kt0 + it + 1) * 512;
            const uint4* sv = g_Vt + (size_t)(b * 100 + kt0 + it + 1) * 512;
            const unsigned nbase = sb + 16384u + (unsigned)((it + 1) & 1) * 16384u;
#pragma unroll
            for (int j = 0; j < 2; j++) { int i = tid + j * 256; cpa16(nbase + i * 16, sk + i); }
#pragma unroll
            for (int j = 0; j < 2; j++) { int i = tid + j * 256; cpa16(nbase + 8192u + i * 16, sv + i); }
            CP_COMMIT();
            CP_WAIT1();
        } else {
            CP_WAIT0();
        }
        __syncthreads();

        // ---- S = Q K^T (single fp16 pass, first-touch C=0) ----
        float S[8][4];
#pragma unroll
        for (int kc = 0; kc < 4; kc++) {
            const unsigned aswz = (unsigned)((kc * 32 + cbA) ^ ((rA & 7) << 4));
            unsigned q0, q1, q2, q3;
            ldsm4(q0, q1, q2, q3, sb + rA * 128 + aswz);
#pragma unroll
            for (int nbp = 0; nbp < 4; nbp++) {
                const int rB = nbp * 16 + rB16;
                const unsigned bswz = (unsigned)((kc * 32 + bsel) ^ ((rB & 7) << 4));
                unsigned k0, k1, k2, k3;
                ldsm4(k0, k1, k2, k3, sb + koff + rB * 128 + bswz);
                if (kc == 0) {
                    mma_h_z(S[2*nbp],   q0, q1, q2, q3, k0, k1);
                    mma_h_z(S[2*nbp+1], q0, q1, q2, q3, k2, k3);
                } else {
                    mma_h(S[2*nbp],   q0, q1, q2, q3, k0, k1);
                    mma_h(S[2*nbp+1], q0, q1, q2, q3, k2, k3);
                }
            }
        }

        // ---- online softmax: packed fp16 exp, denominator via ones-MMA ----
        float tm1 = -INFINITY, tm2 = -INFINITY;
#pragma unroll
        for (int nb = 0; nb < 8; nb++) {
            tm1 = fmaxf(tm1, fmaxf(S[nb][0], S[nb][1]));
            tm2 = fmaxf(tm2, fmaxf(S[nb][2], S[nb][3]));
        }
        tm1 = fmaxf(tm1, __shfl_xor_sync(0xffffffffu, tm1, 1));
        tm1 = fmaxf(tm1, __shfl_xor_sync(0xffffffffu, tm1, 2));
        tm2 = fmaxf(tm2, __shfl_xor_sync(0xffffffffu, tm2, 1));
        tm2 = fmaxf(tm2, __shfl_xor_sync(0xffffffffu, tm2, 2));
        const float m1n = fmaxf(m1, tm1), m2n = fmaxf(m2, tm2);
        const float sc1 = ex2f((m1 - m1n) * L2E), sc2 = ex2f((m2 - m2n) * L2E);
        const float b1 = m1n * L2E, b2 = m2n * L2E;
        m1 = m1n; m2 = m2n;

        unsigned Ph[4][4];
#pragma unroll
        for (int nb = 0; nb < 8; nb++) {
            unsigned p01 = pk2h(fmaf(S[nb][0], L2E, -b1), fmaf(S[nb][1], L2E, -b1));
            unsigned p23 = pk2h(fmaf(S[nb][2], L2E, -b2), fmaf(S[nb][3], L2E, -b2));
            const int kc = nb >> 1, o = (nb & 1) << 1;
            Ph[kc][o]     = h2exp2(p01);
            Ph[kc][o + 1] = h2exp2(p23);
        }
        // denominator tile-sums on tensor pipe: D = P @ ones
        float Dacc[4];
#pragma unroll
        for (int kc = 0; kc < 4; kc++) {
            if (kc == 0) mma_h_z(Dacc, Ph[0][0], Ph[0][1], Ph[0][2], Ph[0][3], ONES_H2, ONES_H2);
            else         mma_h (Dacc, Ph[kc][0], Ph[kc][1], Ph[kc][2], Ph[kc][3], ONES_H2, ONES_H2);
        }
        d1 = d1 * sc1 + Dacc[0];
        d2 = d2 * sc2 + Dacc[2];
#pragma unroll
        for (int nb = 0; nb < 8; nb++) {
            O[nb][0] *= sc1; O[nb][1] *= sc1;
            O[nb][2] *= sc2; O[nb][3] *= sc2;
        }

        // ---- O += P V (fp16) ----
#pragma unroll
        for (int kc = 0; kc < 4; kc++) {
#pragma unroll
            for (int nbp = 0; nbp < 4; nbp++) {
                const int rB = nbp * 16 + rB16;
                const unsigned bswz = (unsigned)((kc * 32 + bsel) ^ ((rB & 7) << 4));
                unsigned v0, v1, v2, v3;
                ldsm4(v0, v1, v2, v3, sb + voff + rB * 128 + bswz);
                mma_h(O[2*nbp],   Ph[kc][0], Ph[kc][1], Ph[kc][2], Ph[kc][3], v0, v1);
                mma_h(O[2*nbp+1], Ph[kc][0], Ph[kc][1], Ph[kc][2], Ph[kc][3], v2, v3);
            }
        }
    }

    // ---- epilogue: store (m, d, O-fp16); d already full row sums ----
    const int cta = (b * 4 + quarter) * 50 + rt;
    unsigned* Uh = g_Oph + (size_t)cta * 4096;
    if (t == 0) {
        g_Od[cta * 128 + warp * 16 + g]     = d1;
        g_Od[cta * 128 + warp * 16 + g + 8] = d2;
        g_Om[cta * 128 + warp * 16 + g]     = m1;
        g_Om[cta * 128 + warp * 16 + g + 8] = m2;
    }
#pragma unroll
    for (int nb = 0; nb < 8; nb++) {
        Uh[(warp * 16 + g) * 32 + nb * 4 + t]     = pk2h(O[nb][0], O[nb][1]);
        Uh[(warp * 16 + g + 8) * 32 + nb * 4 + t] = pk2h(O[nb][2], O[nb][3]);
    }
}

// ---------------------------------------------------------------------------
// fused channel-apply + spatial combine. grid (100, 4), 256 thr.
// ---------------------------------------------------------------------------
__global__ __launch_bounds__(256) void chan_spatial_kernel(float* __restrict__ out) {
    __shared__ float vs[64][64];
    __shared__ float mas[64][65];
    __shared__ float sO[64 * 65];
    __shared__ float sden[64];
    __shared__ float sw[4][64];
    const int rt64 = blockIdx.x, b = blockIdx.y, tid = threadIdx.x;
    const int tx = tid & 15, ty = tid >> 4;
    const int n0 = rt64 * 64;
    const int rtb = rt64 >> 1, ro = (rt64 & 1) * 64;
    const float L2E = 1.4426950408889634f;
    int c_q[4];
#pragma unroll
    for (int q = 0; q < 4; q++) c_q[q] = (b * 4 + q) * 50 + rtb;

    if (tid < 64) {
        float mq[4], dq[4], M = -INFINITY;
#pragma unroll
        for (int q = 0; q < 4; q++) {
            mq[q] = g_Om[c_q[q] * 128 + ro + tid];
            dq[q] = g_Od[c_q[q] * 128 + ro + tid];
            M = fmaxf(M, mq[q]);
        }
        float den = 0.f;
#pragma unroll
        for (int q = 0; q < 4; q++) {
            float wq = ex2f((mq[q] - M) * L2E);
            sw[q][tid] = wq;
            den += wq * dq[q];
        }
        sden[tid] = 1.f / den;
    }
    for (int idx = tid; idx < 4096; idx += 256) {
        int c = idx >> 6, cp = idx & 63;
        mas[cp][c] = g_ma[((size_t)b * 64 + c) * 64 + cp];
    }
    {
        int p = tid >> 2, cb = (tid & 3) * 16;
        int n = n0 + p, nt = (n % 80) * 80 + n / 80;
        const float* vp = g_V + ((size_t)b * NN + nt) * 64 + cb;
#pragma unroll
        for (int k = 0; k < 4; k++) {
            float4 v4 = *(const float4*)(vp + 4 * k);
            vs[cb+4*k+0][p] = v4.x; vs[cb+4*k+1][p] = v4.y;
            vs[cb+4*k+2][p] = v4.z; vs[cb+4*k+3][p] = v4.w;
        }
    }
    __syncthreads();

#pragma unroll
    for (int i = 0; i < 8; i++) {
        int u = tid + i * 256;
        int r = u >> 5, cp2 = u & 31;
        float s0 = 0.f, s1 = 0.f;
#pragma unroll
        for (int q = 0; q < 4; q++) {
            unsigned pk = g_Oph[(size_t)c_q[q] * 4096 + (ro + r) * 32 + cp2];
            __half2 h2 = *reinterpret_cast<__half2*>(&pk);
            float2 f = __half22float2(h2);
            s0 += sw[q][r] * f.x;
            s1 += sw[q][r] * f.y;
        }
        sO[r * 65 + cp2 * 2]     = s0 * sden[r];
        sO[r * 65 + cp2 * 2 + 1] = s1 * sden[r];
    }

    float acc[4][4];
#pragma unroll
    for (int i = 0; i < 4; i++)
#pragma unroll
        for (int j = 0; j < 4; j++) acc[i][j] = 0.f;
#pragma unroll 4
    for (int cp = 0; cp < 64; cp++) {
        float mv[4];
#pragma unroll
        for (int i = 0; i < 4; i++) mv[i] = mas[cp][ty * 4 + i];
        float4 v4 = *(const float4*)&vs[cp][tx * 4];
        float vv[4] = {v4.x, v4.y, v4.z, v4.w};
#pragma unroll
        for (int i = 0; i < 4; i++)
#pragma unroll
            for (int j = 0; j < 4; j++) acc[i][j] += mv[i] * vv[j];
    }
    __syncthreads();

#pragma unroll
    for (int i = 0; i < 4; i++) {
        const int ch = ty * 4 + i;
        float4 o4;
        o4.x = acc[i][0] + sO[(tx * 4 + 0) * 65 + ch];
        o4.y = acc[i][1] + sO[(tx * 4 + 1) * 65 + ch];
        o4.z = acc[i][2] + sO[(tx * 4 + 2) * 65 + ch];
        o4.w = acc[i][3] + sO[(tx * 4 + 3) * 65 + ch];
        *(float4*)(out + ((size_t)b * 64 + ch) * NN + n0 + tx * 4) = o4;
    }
}

// ---------------------------------------------------------------------------
extern "C" void kernel_launch(void* const* d_in, const int* in_sizes, int n_in,
                              void* d_out, int out_size)
{
    const float* x    = (const float*)d_in[0];
    const float* w    = (const float*)d_in[1];
    const float* bias = (const float*)d_in[2];
    float* out = (float*)d_out;

    const int fsm = 16384 + 2 * 16384;  // 49152 B
    cudaFuncSetAttribute(flash_wm8, cudaFuncAttributeMaxDynamicSharedMemorySize, fsm);

    qkv_kernel<<<dim3(100, 2, 4), 256>>>(x, w, bias);
    repack_kernel<<<dim3(100, 4), 256>>>();
    chan_logits_kernel<<<dim3(64, 4), 256>>>();
    chan_softmax_kernel<<<dim3(64, 4), 64>>>();
    flash_wm8<<<dim3(50, 4, 4), 256, fsm>>>();
    chan_spatial_kernel<<<dim3(100, 4), 256>>>(out);
}